// round 2
// baseline (speedup 1.0000x reference)
#include <cuda_runtime.h>
#include <math.h>

#define Bb     32
#define Ss     2048
#define Dd     1280
#define Hh     16
#define HDd    96
#define NLl    64
#define DEPTHn 3
#define FFf    5120
#define SKV    (Ss + NLl)      /* 2112 */
#define HHD    (Hh * HDd)      /* 1536 */
#define EPSf   1e-5f

// ---------------- scratch (__device__ globals: no runtime alloc) -----------
__device__ float g_ctx_mean[Bb * Ss];
__device__ float g_ctx_rstd[Bb * Ss];
__device__ float g_lat[Bb * NLl * Dd];
__device__ float g_lat_mean[Bb * NLl];
__device__ float g_lat_rstd[Bb * NLl];
__device__ float g_Q[Bb * NLl * HHD];
__device__ float g_K[(size_t)Bb * SKV * HHD];
__device__ float g_V[(size_t)Bb * SKV * HHD];
__device__ float g_attn[Bb * NLl * HHD];
__device__ float g_mlp[(size_t)Bb * NLl * FFf];

// ---------------- packed f32x2 helpers -------------------------------------
typedef unsigned long long u64;
__device__ __forceinline__ u64 pk2(float lo, float hi) {
    u64 r; asm("mov.b64 %0, {%1, %2};" : "=l"(r) : "f"(lo), "f"(hi)); return r;
}
__device__ __forceinline__ void fma2(u64& d, u64 a, u64 b) {
    asm("fma.rn.f32x2 %0, %1, %2, %0;" : "+l"(d) : "l"(a), "l"(b));
}
__device__ __forceinline__ float2 up2(u64 v) {
    float2 f; asm("mov.b64 {%0, %1}, %2;" : "=f"(f.x), "=f"(f.y) : "l"(v)); return f;
}

// ---------------- per-row mean / rstd ---------------------------------------
__global__ void rowstats_kernel(const float* __restrict__ X,
                                float* __restrict__ mean,
                                float* __restrict__ rstd, int ncols) {
    int row = blockIdx.x;
    const float* x = X + (size_t)row * ncols;
    float s = 0.f, ss = 0.f;
    for (int c = threadIdx.x; c < ncols; c += blockDim.x) {
        float v = x[c]; s += v; ss += v * v;
    }
#pragma unroll
    for (int o = 16; o > 0; o >>= 1) {
        s  += __shfl_xor_sync(0xffffffffu, s, o);
        ss += __shfl_xor_sync(0xffffffffu, ss, o);
    }
    __shared__ float red_s[8], red_q[8];
    int w = threadIdx.x >> 5, nl = threadIdx.x & 31;
    if (nl == 0) { red_s[w] = s; red_q[w] = ss; }
    __syncthreads();
    if (threadIdx.x == 0) {
        float S = 0.f, Q = 0.f;
        int nw = blockDim.x >> 5;
        for (int i = 0; i < nw; i++) { S += red_s[i]; Q += red_q[i]; }
        float m = S / (float)ncols;
        mean[row] = m;
        rstd[row] = rsqrtf(Q / (float)ncols - m * m + EPSf);
    }
}

__global__ void broadcast_lat_kernel(const float* __restrict__ latents) {
    int i = blockIdx.x * blockDim.x + threadIdx.x;
    const int per = NLl * Dd;
    if (i < Bb * per) g_lat[i] = latents[i % per];
}

// ---------------- generic fused GEMM ----------------------------------------
// C[crow(r), n] = LN(A)[r,:] @ B[:,n]  (+resid)(relu)
// LN on A-load: (x-mu[r])*rstd[r]*gamma[k]+beta[k]   (skipped if rmean==null)
// remap: 0 none | 1 latent-KV rows | 2 context-KV rows
__global__ __launch_bounds__(256, 2) void gemm_ln_kernel(
    const float* __restrict__ A, const float* __restrict__ Bm,
    float* __restrict__ C, int M, int N, int K, int ldc,
    const float* __restrict__ rmean, const float* __restrict__ rrstd,
    const float* __restrict__ lnw, const float* __restrict__ lnb,
    const float* __restrict__ resid, int relu, int remap) {
    __shared__ float As[8][132];
    __shared__ float Bs[8][128];

    int tid = threadIdx.x;
    int m0 = blockIdx.y << 7, n0 = blockIdx.x << 7;
    int tx = tid & 15, ty = tid >> 4;

    int am = tid >> 1;                 // 0..127
    int ak = (tid & 1) << 2;           // 0 or 4
    int bk = tid >> 5;                 // 0..7
    int bn = (tid & 31) << 2;

    const float* Aptr = A + (size_t)(m0 + am) * K + ak;
    const float* Bptr = Bm + (size_t)bk * N + n0 + bn;

    float mu = 0.f, rs = 0.f;
    bool doln = (rmean != nullptr);
    if (doln) { mu = rmean[m0 + am]; rs = rrstd[m0 + am]; }

    u64 acc[8][4];
#pragma unroll
    for (int i = 0; i < 8; i++)
#pragma unroll
        for (int j = 0; j < 4; j++) acc[i][j] = 0ull;

    for (int k0 = 0; k0 < K; k0 += 8) {
        float4 av = *(const float4*)(Aptr + k0);
        if (doln) {
            float4 g  = *(const float4*)(lnw + k0 + ak);
            float4 bb = *(const float4*)(lnb + k0 + ak);
            av.x = (av.x - mu) * rs * g.x + bb.x;
            av.y = (av.y - mu) * rs * g.y + bb.y;
            av.z = (av.z - mu) * rs * g.z + bb.z;
            av.w = (av.w - mu) * rs * g.w + bb.w;
        }
        As[ak + 0][am] = av.x;
        As[ak + 1][am] = av.y;
        As[ak + 2][am] = av.z;
        As[ak + 3][am] = av.w;
        *(float4*)&Bs[bk][bn] = *(const float4*)(Bptr + (size_t)k0 * N);
        __syncthreads();

#pragma unroll
        for (int kk = 0; kk < 8; kk++) {
            float4 a0 = *(const float4*)&As[kk][ty << 3];
            float4 a1 = *(const float4*)&As[kk][(ty << 3) + 4];
            ulonglong2 b0 = *(const ulonglong2*)&Bs[kk][tx << 3];
            ulonglong2 b1 = *(const ulonglong2*)&Bs[kk][(tx << 3) + 4];
            float ar[8] = {a0.x, a0.y, a0.z, a0.w, a1.x, a1.y, a1.z, a1.w};
#pragma unroll
            for (int i = 0; i < 8; i++) {
                u64 ad = pk2(ar[i], ar[i]);
                fma2(acc[i][0], ad, b0.x);
                fma2(acc[i][1], ad, b0.y);
                fma2(acc[i][2], ad, b1.x);
                fma2(acc[i][3], ad, b1.y);
            }
        }
        __syncthreads();
    }

#pragma unroll
    for (int i = 0; i < 8; i++) {
        int r = m0 + (ty << 3) + i;
        int crow;
        if (remap == 1)      crow = (r >> 6)  * SKV + Ss + (r & 63);
        else if (remap == 2) crow = (r >> 11) * SKV + (r & 2047);
        else                 crow = r;
        float* cp = C + (size_t)crow * ldc + n0 + (tx << 3);
        float out[8];
#pragma unroll
        for (int j = 0; j < 4; j++) {
            float2 v = up2(acc[i][j]);
            out[2 * j] = v.x; out[2 * j + 1] = v.y;
        }
        if (resid) {
            const float* rp = resid + (size_t)r * N + n0 + (tx << 3);
#pragma unroll
            for (int j = 0; j < 8; j++) out[j] += rp[j];
        }
        if (relu) {
#pragma unroll
            for (int j = 0; j < 8; j++) out[j] = fmaxf(out[j], 0.f);
        }
        *(float4*)cp       = make_float4(out[0], out[1], out[2], out[3]);
        *(float4*)(cp + 4) = make_float4(out[4], out[5], out[6], out[7]);
    }
}

// ---------------- fused attention (one CTA per (b,h)) ------------------------
#define ATT_QS   0
#define ATT_KS   (64 * 100)
#define ATT_VS   (ATT_KS + 32 * 100)
#define ATT_PS   (ATT_VS + 32 * 100)
#define ATT_SMEM ((ATT_PS + 64 * 33) * 4)

__global__ __launch_bounds__(256) void attention_kernel(
    const float* __restrict__ Q, const float* __restrict__ Kb,
    const float* __restrict__ Vb, float* __restrict__ O,
    const float* __restrict__ qw, const float* __restrict__ qb,
    const float* __restrict__ kw, const float* __restrict__ kb) {
    extern __shared__ float sm[];
    float* qs = sm + ATT_QS;   // [64][100]
    float* ks = sm + ATT_KS;   // [32][100]
    float* vs = sm + ATT_VS;   // [32][100]
    float* ps = sm + ATT_PS;   // [64][33]

    int tid = threadIdx.x;
    int bh = blockIdx.x;
    int b = bh >> 4, h = bh & 15;
    const float qscale = rsqrtf((float)HDd);

    int myrow = tid >> 2, mypart = tid & 3;   // softmax / PV mapping
    int qg = tid >> 4, kg = tid & 15;         // score mapping

    // load + per-head LN + scale of Q tile [64 x 96]
    {
        const float* qp = Q + (size_t)(b * NLl + myrow) * HHD + h * HDd + mypart * 24;
        float v[24];
        float s = 0.f, ss = 0.f;
#pragma unroll
        for (int i = 0; i < 24; i += 4) {
            float4 t = *(const float4*)(qp + i);
            v[i] = t.x; v[i+1] = t.y; v[i+2] = t.z; v[i+3] = t.w;
        }
#pragma unroll
        for (int i = 0; i < 24; i++) { s += v[i]; ss += v[i] * v[i]; }
#pragma unroll
        for (int o = 1; o < 4; o <<= 1) {
            s  += __shfl_xor_sync(0xffffffffu, s, o);
            ss += __shfl_xor_sync(0xffffffffu, ss, o);
        }
        float mmu = s * (1.f / 96.f);
        float rsd = rsqrtf(ss * (1.f / 96.f) - mmu * mmu + EPSf);
#pragma unroll
        for (int i = 0; i < 24; i++) {
            int c = mypart * 24 + i;
            qs[myrow * 100 + c] = ((v[i] - mmu) * rsd * qw[c] + qb[c]) * qscale;
        }
    }
    __syncthreads();

    float m_run = -INFINITY, l_run = 0.f;
    float oacc[24];
#pragma unroll
    for (int i = 0; i < 24; i++) oacc[i] = 0.f;

    for (int t = 0; t < SKV / 32; t++) {
        // load K (with head-LN) and V tiles [32 x 96]
        {
            int j = tid >> 3, p8 = tid & 7;
            int kidx = t * 32 + j;
            const float* kp = Kb + ((size_t)b * SKV + kidx) * HHD + h * HDd + p8 * 12;
            const float* vp = Vb + ((size_t)b * SKV + kidx) * HHD + h * HDd + p8 * 12;
            float kv[12];
            float s = 0.f, ss = 0.f;
#pragma unroll
            for (int i = 0; i < 12; i += 4) {
                float4 tt = *(const float4*)(kp + i);
                kv[i] = tt.x; kv[i+1] = tt.y; kv[i+2] = tt.z; kv[i+3] = tt.w;
            }
#pragma unroll
            for (int i = 0; i < 12; i++) { s += kv[i]; ss += kv[i] * kv[i]; }
#pragma unroll
            for (int o = 1; o < 8; o <<= 1) {
                s  += __shfl_xor_sync(0xffffffffu, s, o);
                ss += __shfl_xor_sync(0xffffffffu, ss, o);
            }
            float mmu = s * (1.f / 96.f);
            float rsd = rsqrtf(ss * (1.f / 96.f) - mmu * mmu + EPSf);
#pragma unroll
            for (int i = 0; i < 12; i++) {
                int c = p8 * 12 + i;
                ks[j * 100 + c] = (kv[i] - mmu) * rsd * kw[c] + kb[c];
            }
#pragma unroll
            for (int i = 0; i < 12; i += 4)
                *(float4*)&vs[j * 100 + p8 * 12 + i] = *(const float4*)(vp + i);
        }
        __syncthreads();

        // scores: each thread 4 q-rows x 2 k-cols over d=96
        {
            float sc[4][2];
#pragma unroll
            for (int i = 0; i < 4; i++) { sc[i][0] = 0.f; sc[i][1] = 0.f; }
            int q0 = qg << 2, k0 = kg << 1;
#pragma unroll
            for (int d = 0; d < 96; d += 4) {
                float4 k0v = *(const float4*)&ks[k0 * 100 + d];
                float4 k1v = *(const float4*)&ks[(k0 + 1) * 100 + d];
#pragma unroll
                for (int i = 0; i < 4; i++) {
                    float4 qv = *(const float4*)&qs[(q0 + i) * 100 + d];
                    sc[i][0] += qv.x*k0v.x + qv.y*k0v.y + qv.z*k0v.z + qv.w*k0v.w;
                    sc[i][1] += qv.x*k1v.x + qv.y*k1v.y + qv.z*k1v.z + qv.w*k1v.w;
                }
            }
#pragma unroll
            for (int i = 0; i < 4; i++) {
                ps[(q0 + i) * 33 + k0]     = sc[i][0];
                ps[(q0 + i) * 33 + k0 + 1] = sc[i][1];
            }
        }
        __syncwarp();   // writers and readers of each ps row share a warp

        // online softmax + PV
        {
            float p8v[8];
            float mx = -INFINITY;
#pragma unroll
            for (int i = 0; i < 8; i++) {
                p8v[i] = ps[myrow * 33 + mypart * 8 + i];
                mx = fmaxf(mx, p8v[i]);
            }
#pragma unroll
            for (int o = 1; o < 4; o <<= 1)
                mx = fmaxf(mx, __shfl_xor_sync(0xffffffffu, mx, o));
            float mnew = fmaxf(m_run, mx);
            float corr = __expf(m_run - mnew);
            float psum = 0.f;
#pragma unroll
            for (int i = 0; i < 8; i++) {
                p8v[i] = __expf(p8v[i] - mnew);
                psum += p8v[i];
                ps[myrow * 33 + mypart * 8 + i] = p8v[i];
            }
#pragma unroll
            for (int o = 1; o < 4; o <<= 1)
                psum += __shfl_xor_sync(0xffffffffu, psum, o);
            l_run = l_run * corr + psum;
            m_run = mnew;
#pragma unroll
            for (int i = 0; i < 24; i++) oacc[i] *= corr;
            __syncwarp();
#pragma unroll 4
            for (int j = 0; j < 32; j++) {
                float p = ps[myrow * 33 + j];
                const float4* vr = (const float4*)&vs[j * 100 + mypart * 24];
#pragma unroll
                for (int i4 = 0; i4 < 6; i4++) {
                    float4 v = vr[i4];
                    oacc[i4*4+0] += p * v.x;
                    oacc[i4*4+1] += p * v.y;
                    oacc[i4*4+2] += p * v.z;
                    oacc[i4*4+3] += p * v.w;
                }
            }
        }
        __syncthreads();
    }

    {
        float inv = 1.f / l_run;
        float* op = O + (size_t)(b * NLl + myrow) * HHD + h * HDd + mypart * 24;
#pragma unroll
        for (int i = 0; i < 24; i++) op[i] = oacc[i] * inv;
    }
}

// ---------------- final layer norm -> d_out ---------------------------------
__global__ void final_ln_kernel(float* __restrict__ out,
                                const float* __restrict__ w,
                                const float* __restrict__ bia) {
    int row = blockIdx.x;
    const float* x = g_lat + (size_t)row * Dd;
    float s = 0.f, ss = 0.f;
    for (int c = threadIdx.x; c < Dd; c += blockDim.x) {
        float v = x[c]; s += v; ss += v * v;
    }
#pragma unroll
    for (int o = 16; o > 0; o >>= 1) {
        s  += __shfl_xor_sync(0xffffffffu, s, o);
        ss += __shfl_xor_sync(0xffffffffu, ss, o);
    }
    __shared__ float red_s[8], red_q[8];
    __shared__ float sh_m, sh_r;
    int wrp = threadIdx.x >> 5, nl = threadIdx.x & 31;
    if (nl == 0) { red_s[wrp] = s; red_q[wrp] = ss; }
    __syncthreads();
    if (threadIdx.x == 0) {
        float S = 0.f, Q = 0.f;
        for (int i = 0; i < 8; i++) { S += red_s[i]; Q += red_q[i]; }
        float m = S / (float)Dd;
        sh_m = m;
        sh_r = rsqrtf(Q / (float)Dd - m * m + EPSf);
    }
    __syncthreads();
    float m = sh_m, r = sh_r;
    for (int c = threadIdx.x; c < Dd; c += blockDim.x)
        out[(size_t)row * Dd + c] = (x[c] - m) * r * w[c] + bia[c];
}

// ---------------- launch -----------------------------------------------------
extern "C" void kernel_launch(void* const* d_in, const int* in_sizes, int n_in,
                              void* d_out, int out_size) {
    const float* context  = (const float*)d_in[0];
    const float* latents  = (const float*)d_in[1];
    const float* ctx_ln_w = (const float*)d_in[2];
    const float* ctx_ln_b = (const float*)d_in[3];
    const float* lat_ln_w = (const float*)d_in[4];
    const float* lat_ln_b = (const float*)d_in[5];
    const float* q_ln_w   = (const float*)d_in[6];
    const float* q_ln_b   = (const float*)d_in[7];
    const float* k_ln_w   = (const float*)d_in[8];
    const float* k_ln_b   = (const float*)d_in[9];
    const float* wq       = (const float*)d_in[10];
    const float* wk       = (const float*)d_in[11];
    const float* wv       = (const float*)d_in[12];
    const float* wo       = (const float*)d_in[13];
    const float* mlp_ln_w = (const float*)d_in[14];
    const float* mlp_ln_b = (const float*)d_in[15];
    const float* w_fc     = (const float*)d_in[16];
    const float* w_cproj  = (const float*)d_in[17];
    const float* fin_w    = (const float*)d_in[18];
    const float* fin_b    = (const float*)d_in[19];
    (void)in_sizes; (void)n_in; (void)out_size;

    float *pCm, *pCr, *pLat, *pLm, *pLr, *pQ, *pK, *pV, *pAttn, *pMlp;
    cudaGetSymbolAddress((void**)&pCm,   g_ctx_mean);
    cudaGetSymbolAddress((void**)&pCr,   g_ctx_rstd);
    cudaGetSymbolAddress((void**)&pLat,  g_lat);
    cudaGetSymbolAddress((void**)&pLm,   g_lat_mean);
    cudaGetSymbolAddress((void**)&pLr,   g_lat_rstd);
    cudaGetSymbolAddress((void**)&pQ,    g_Q);
    cudaGetSymbolAddress((void**)&pK,    g_K);
    cudaGetSymbolAddress((void**)&pV,    g_V);
    cudaGetSymbolAddress((void**)&pAttn, g_attn);
    cudaGetSymbolAddress((void**)&pMlp,  g_mlp);

    cudaFuncSetAttribute(attention_kernel,
                         cudaFuncAttributeMaxDynamicSharedMemorySize, ATT_SMEM);

    // context LN stats are layer-invariant: compute once
    rowstats_kernel<<<Bb * Ss, 256>>>(context, pCm, pCr, Dd);
    broadcast_lat_kernel<<<(Bb * NLl * Dd + 255) / 256, 256>>>(latents);

    for (int i = 0; i < DEPTHn; i++) {
        const float* wq_i  = wq      + (size_t)i * Dd * HHD;
        const float* wk_i  = wk      + (size_t)i * Dd * HHD;
        const float* wv_i  = wv      + (size_t)i * Dd * HHD;
        const float* wo_i  = wo      + (size_t)i * HHD * Dd;
        const float* wfc_i = w_fc    + (size_t)i * Dd * FFf;
        const float* wcp_i = w_cproj + (size_t)i * FFf * Dd;
        const float* clw = ctx_ln_w + i * Dd, *clb = ctx_ln_b + i * Dd;
        const float* llw = lat_ln_w + i * Dd, *llb = lat_ln_b + i * Dd;
        const float* mlw = mlp_ln_w + i * Dd, *mlb = mlp_ln_b + i * Dd;
        const float* qlw = q_ln_w + i * HDd, *qlb = q_ln_b + i * HDd;
        const float* klw = k_ln_w + i * HDd, *klb = k_ln_b + i * HDd;

        rowstats_kernel<<<Bb * NLl, 256>>>(pLat, pLm, pLr, Dd);

        dim3 gl(HHD / 128, (Bb * NLl) / 128);
        gemm_ln_kernel<<<gl, 256>>>(pLat, wq_i, pQ, Bb * NLl, HHD, Dd, HHD,
                                    pLm, pLr, llw, llb, nullptr, 0, 0);
        gemm_ln_kernel<<<gl, 256>>>(pLat, wk_i, pK, Bb * NLl, HHD, Dd, HHD,
                                    pLm, pLr, llw, llb, nullptr, 0, 1);
        gemm_ln_kernel<<<gl, 256>>>(pLat, wv_i, pV, Bb * NLl, HHD, Dd, HHD,
                                    pLm, pLr, llw, llb, nullptr, 0, 1);

        dim3 gc(HHD / 128, (Bb * Ss) / 128);
        gemm_ln_kernel<<<gc, 256>>>(context, wk_i, pK, Bb * Ss, HHD, Dd, HHD,
                                    pCm, pCr, clw, clb, nullptr, 0, 2);
        gemm_ln_kernel<<<gc, 256>>>(context, wv_i, pV, Bb * Ss, HHD, Dd, HHD,
                                    pCm, pCr, clw, clb, nullptr, 0, 2);

        attention_kernel<<<Bb * Hh, 256, ATT_SMEM>>>(pQ, pK, pV, pAttn,
                                                     qlw, qlb, klw, klb);

        dim3 go(Dd / 128, (Bb * NLl) / 128);
        gemm_ln_kernel<<<go, 256>>>(pAttn, wo_i, pLat, Bb * NLl, Dd, HHD, Dd,
                                    nullptr, nullptr, nullptr, nullptr,
                                    pLat, 0, 0);

        rowstats_kernel<<<Bb * NLl, 256>>>(pLat, pLm, pLr, Dd);

        dim3 gf(FFf / 128, (Bb * NLl) / 128);
        gemm_ln_kernel<<<gf, 256>>>(pLat, wfc_i, pMlp, Bb * NLl, FFf, Dd, FFf,
                                    pLm, pLr, mlw, mlb, nullptr, 1, 0);

        dim3 gp(Dd / 128, (Bb * NLl) / 128);
        gemm_ln_kernel<<<gp, 256>>>(pMlp, wcp_i, pLat, Bb * NLl, Dd, FFf, Dd,
                                    nullptr, nullptr, nullptr, nullptr,
                                    pLat, 0, 0);
    }

    final_ln_kernel<<<Bb * NLl, 256>>>((float*)d_out, fin_w, fin_b);
}

// round 4
// speedup vs baseline: 2.1288x; 2.1288x over previous
#include <cuda_runtime.h>
#include <cuda_bf16.h>
#include <cstdint>
#include <math.h>

#define Bb     32
#define Ss     2048
#define Dd     1280
#define Hh     16
#define HDd    96
#define NLl    64
#define DEPTHn 3
#define FFf    5120
#define SKV    (Ss + NLl)      /* 2112 */
#define HHD    (Hh * HDd)      /* 1536 */
#define EPSf   1e-5f

// ======================= scratch (device globals) ===========================
__device__ float g_ctx_mean[Bb * Ss];
__device__ float g_ctx_rstd[Bb * Ss];
__device__ float g_lat[Bb * NLl * Dd];
__device__ float g_lat_mean[Bb * NLl];
__device__ float g_lat_rstd[Bb * NLl];
__device__ float g_Q[Bb * NLl * HHD];
__device__ float g_K[(size_t)Bb * SKV * HHD];
__device__ float g_V[(size_t)Bb * SKV * HHD];
__device__ float g_attn[Bb * NLl * HHD];
__device__ float g_mlp[(size_t)Bb * NLl * FFf];

// packed (hi,lo) bf16 pairs, one u32 per source fp32 value
#define WT_QKV   (HHD * Dd)          /* 1966080 */
#define WT_FC    ((size_t)Dd * FFf)  /* 6553600 */
#define WT_LAYER (4u * WT_QKV + 2u * WT_FC)
__device__ unsigned g_Wt[(size_t)3 * WT_LAYER];
__device__ unsigned g_Apack[(size_t)Bb * Ss * Dd];

// ======================= small prep kernels =================================
__global__ void rowstats_kernel(const float* __restrict__ X,
                                float* __restrict__ mean,
                                float* __restrict__ rstd, int ncols) {
    int row = blockIdx.x;
    const float* x = X + (size_t)row * ncols;
    float s = 0.f, ss = 0.f;
    for (int c = threadIdx.x; c < ncols; c += blockDim.x) {
        float v = x[c]; s += v; ss += v * v;
    }
#pragma unroll
    for (int o = 16; o > 0; o >>= 1) {
        s  += __shfl_xor_sync(0xffffffffu, s, o);
        ss += __shfl_xor_sync(0xffffffffu, ss, o);
    }
    __shared__ float red_s[8], red_q[8];
    int w = threadIdx.x >> 5, nl = threadIdx.x & 31;
    if (nl == 0) { red_s[w] = s; red_q[w] = ss; }
    __syncthreads();
    if (threadIdx.x == 0) {
        float S = 0.f, Q = 0.f;
        int nw = blockDim.x >> 5;
        for (int i = 0; i < nw; i++) { S += red_s[i]; Q += red_q[i]; }
        float m = S / (float)ncols;
        mean[row] = m;
        rstd[row] = rsqrtf(Q / (float)ncols - m * m + EPSf);
    }
}

__global__ void broadcast_lat_kernel(const float* __restrict__ latents) {
    int i = blockIdx.x * blockDim.x + threadIdx.x;
    const int per = NLl * Dd;
    if (i < Bb * per) g_lat[i] = latents[i % per];
}

// transpose + hi/lo bf16 split:  W[K,N] fp32  ->  out[N,K] packed u32
__global__ void wt_pack_kernel(const float* __restrict__ W,
                               unsigned* __restrict__ out, int K, int N) {
    __shared__ float tile[32][33];
    int n0 = blockIdx.x << 5, k0 = blockIdx.y << 5;
    for (int i = threadIdx.y; i < 32; i += 8)
        tile[i][threadIdx.x] = W[(size_t)(k0 + i) * N + n0 + threadIdx.x];
    __syncthreads();
    for (int i = threadIdx.y; i < 32; i += 8) {
        float v = tile[threadIdx.x][i];
        __nv_bfloat16 h = __float2bfloat16(v);
        __nv_bfloat16 l = __float2bfloat16(v - __bfloat162float(h));
        out[(size_t)(n0 + i) * K + k0 + threadIdx.x] =
            ((unsigned)__bfloat16_as_ushort(l) << 16) | __bfloat16_as_ushort(h);
    }
}

// LN (optional) + hi/lo bf16 split pack:  X[M,K] fp32 -> out[M,K] packed u32
__global__ void pack_ln_kernel(const float* __restrict__ X,
                               const float* __restrict__ mean,
                               const float* __restrict__ rstd,
                               const float* __restrict__ lnw,
                               const float* __restrict__ lnb,
                               unsigned* __restrict__ out, int ncols) {
    int row = blockIdx.x;
    const float* x = X + (size_t)row * ncols;
    unsigned* o = out + (size_t)row * ncols;
    bool doln = (mean != nullptr);
    float mu = 0.f, rs = 1.f;
    if (doln) { mu = mean[row]; rs = rstd[row]; }
    for (int c = threadIdx.x; c < ncols; c += blockDim.x) {
        float v = x[c];
        if (doln) v = (v - mu) * rs * lnw[c] + lnb[c];
        __nv_bfloat16 h = __float2bfloat16(v);
        __nv_bfloat16 l = __float2bfloat16(v - __bfloat162float(h));
        o[c] = ((unsigned)__bfloat16_as_ushort(l) << 16) | __bfloat16_as_ushort(h);
    }
}

// ======================= HMMA (mma.sync) GEMM ===============================
// C[crow(r), n] = A[r,:] @ Wt[n,:]   bf16x3: Ah.Bh + Ah.Bl + Al.Bh, fp32 acc
// CTA tile 128x128, K chunk 64, 8 warps (2x4), warp tile 64x32.
// smem stage: Ah/Al/Bh/Bl planes, each [128 rows][64 bf16 = 128B], SW128 swizzle.
#define ST_BYTES   65536
#define GM_SMEM    (2 * ST_BYTES)
#define PL_AH      0
#define PL_AL      16384
#define PL_BH      32768
#define PL_BL      49152

#define LDSM4(r0, r1, r2, r3, addr)                                          \
    asm volatile("ldmatrix.sync.aligned.m8n8.x4.shared.b16 {%0,%1,%2,%3}, [%4];" \
        : "=r"(r0), "=r"(r1), "=r"(r2), "=r"(r3) : "r"(addr))

#define MMA16816(d, a, b0, b1)                                               \
    asm volatile("mma.sync.aligned.m16n8k16.row.col.f32.bf16.bf16.f32 "      \
        "{%0,%1,%2,%3}, {%4,%5,%6,%7}, {%8,%9}, {%0,%1,%2,%3};"              \
        : "+f"((d)[0]), "+f"((d)[1]), "+f"((d)[2]), "+f"((d)[3])             \
        : "r"((a)[0]), "r"((a)[1]), "r"((a)[2]), "r"((a)[3]),                \
          "r"(b0), "r"(b1))

__device__ __forceinline__ uint32_t smem_u32(const void* p) {
    uint32_t a;
    asm("{ .reg .u64 t; cvta.to.shared.u64 t, %1; cvt.u32.u64 %0, t; }"
        : "=r"(a) : "l"(p));
    return a;
}
__device__ __forceinline__ uint32_t swz_addr(uint32_t base, int row, int chunk16) {
    uint32_t off = (uint32_t)(row * 128 + chunk16 * 16);
    return base + (off ^ ((off >> 3) & 0x70));
}
__device__ __forceinline__ void sts_split(char* hi, char* lo, int row, int col8,
                                          uint4 p) {
    unsigned hi01 = (p.x & 0xFFFFu) | (p.y << 16);
    unsigned hi23 = (p.z & 0xFFFFu) | (p.w << 16);
    unsigned lo01 = (p.x >> 16) | (p.y & 0xFFFF0000u);
    unsigned lo23 = (p.z >> 16) | (p.w & 0xFFFF0000u);
    unsigned off = (unsigned)(row * 128 + col8 * 8);
    off ^= (off >> 3) & 0x70;
    *(uint2*)(hi + off) = make_uint2(hi01, hi23);
    *(uint2*)(lo + off) = make_uint2(lo01, lo23);
}

__global__ __launch_bounds__(256, 1) void gemm_mma_kernel(
    const unsigned* __restrict__ Apack, const unsigned* __restrict__ Wt,
    float* __restrict__ C, int M, int N, int K, int ldc,
    const float* __restrict__ resid, int relu, int remap) {
    extern __shared__ char sm[];
    uint32_t smb = smem_u32(sm);
    int tid = threadIdx.x, wid = tid >> 5, lane = tid & 31;
    int warp_m = wid >> 2, warp_n = wid & 3;

    int m0 = blockIdx.y << 7, n0 = blockIdx.x << 7;
    const uint4* Ap = (const uint4*)(Apack + (size_t)m0 * K);
    const uint4* Bp = (const uint4*)(Wt + (size_t)n0 * K);
    int K4 = K >> 2;
    int NC = K >> 6;

    int ldrow = tid >> 4;          // 0..15 (two per warp)
    int ldcol = tid & 15;          // uint4 within 64-u32 row chunk

    float acc[4][4][4];
#pragma unroll
    for (int i = 0; i < 4; i++)
#pragma unroll
        for (int j = 0; j < 4; j++)
#pragma unroll
            for (int k = 0; k < 4; k++) acc[i][j][k] = 0.f;

    uint4 bufA[8], bufB[8];
    // prologue: load chunk 0
#pragma unroll
    for (int i = 0; i < 8; i++) {
        int row = i * 16 + ldrow;
        bufA[i] = Ap[(size_t)row * K4 + ldcol];
        bufB[i] = Bp[(size_t)row * K4 + ldcol];
    }
#pragma unroll
    for (int i = 0; i < 8; i++) {
        int row = i * 16 + ldrow;
        sts_split(sm + PL_AH, sm + PL_AL, row, ldcol, bufA[i]);
        sts_split(sm + PL_BH, sm + PL_BL, row, ldcol, bufB[i]);
    }
    __syncthreads();

    int lrow = lane & 15, lhalf = lane >> 4;
    for (int c = 0; c < NC; c++) {
        if (c + 1 < NC) {
#pragma unroll
            for (int i = 0; i < 8; i++) {
                int row = i * 16 + ldrow;
                bufA[i] = Ap[(size_t)row * K4 + (c + 1) * 16 + ldcol];
                bufB[i] = Bp[(size_t)row * K4 + (c + 1) * 16 + ldcol];
            }
        }
        uint32_t st = smb + (uint32_t)((c & 1) * ST_BYTES);
#pragma unroll
        for (int kq = 0; kq < 4; kq++) {
            uint32_t ah[4][4], al[4][4];
#pragma unroll
            for (int mt = 0; mt < 4; mt++) {
                int row = warp_m * 64 + mt * 16 + lrow;
                int ch = kq * 2 + lhalf;
                LDSM4(ah[mt][0], ah[mt][1], ah[mt][2], ah[mt][3],
                      swz_addr(st + PL_AH, row, ch));
                LDSM4(al[mt][0], al[mt][1], al[mt][2], al[mt][3],
                      swz_addr(st + PL_AL, row, ch));
            }
            uint32_t bh0[4], bh1[4], bl0[4], bl1[4];
#pragma unroll
            for (int nt2 = 0; nt2 < 2; nt2++) {
                int row = warp_n * 32 + nt2 * 16 + lrow;
                int ch = kq * 2 + lhalf;
                uint32_t r0, r1, r2, r3;
                LDSM4(r0, r1, r2, r3, swz_addr(st + PL_BH, row, ch));
                bh0[nt2 * 2] = r0; bh1[nt2 * 2] = r2;
                bh0[nt2 * 2 + 1] = r1; bh1[nt2 * 2 + 1] = r3;
                LDSM4(r0, r1, r2, r3, swz_addr(st + PL_BL, row, ch));
                bl0[nt2 * 2] = r0; bl1[nt2 * 2] = r2;
                bl0[nt2 * 2 + 1] = r1; bl1[nt2 * 2 + 1] = r3;
            }
#pragma unroll
            for (int mt = 0; mt < 4; mt++)
#pragma unroll
                for (int nt = 0; nt < 4; nt++) {
                    MMA16816(acc[mt][nt], ah[mt], bh0[nt], bh1[nt]);
                    MMA16816(acc[mt][nt], ah[mt], bl0[nt], bl1[nt]);
                    MMA16816(acc[mt][nt], al[mt], bh0[nt], bh1[nt]);
                }
        }
        if (c + 1 < NC) {
            char* stn = sm + ((c + 1) & 1) * ST_BYTES;
#pragma unroll
            for (int i = 0; i < 8; i++) {
                int row = i * 16 + ldrow;
                sts_split(stn + PL_AH, stn + PL_AL, row, ldcol, bufA[i]);
                sts_split(stn + PL_BH, stn + PL_BL, row, ldcol, bufB[i]);
            }
        }
        __syncthreads();
    }

    // epilogue
    int qrow = lane >> 2, qcol = (lane & 3) * 2;
#pragma unroll
    for (int mt = 0; mt < 4; mt++) {
#pragma unroll
        for (int half = 0; half < 2; half++) {
            int r = m0 + warp_m * 64 + mt * 16 + half * 8 + qrow;
            int crow;
            if (remap == 1)      crow = (r >> 6)  * SKV + Ss + (r & 63);
            else if (remap == 2) crow = (r >> 11) * SKV + (r & 2047);
            else                 crow = r;
            float* cp = C + (size_t)crow * ldc + n0 + warp_n * 32;
            const float* rp =
                resid ? resid + (size_t)r * N + n0 + warp_n * 32 : nullptr;
#pragma unroll
            for (int nt = 0; nt < 4; nt++) {
                float v0 = acc[mt][nt][half * 2];
                float v1 = acc[mt][nt][half * 2 + 1];
                int col = nt * 8 + qcol;
                if (rp) { v0 += rp[col]; v1 += rp[col + 1]; }
                if (relu) { v0 = fmaxf(v0, 0.f); v1 = fmaxf(v1, 0.f); }
                *(float2*)(cp + col) = make_float2(v0, v1);
            }
        }
    }
}

// ======================= fused attention ====================================
#define ATT_QS   0
#define ATT_KS   (64 * 100)
#define ATT_VS   (ATT_KS + 32 * 100)
#define ATT_PS   (ATT_VS + 32 * 100)
#define ATT_SMEM ((ATT_PS + 64 * 33) * 4)

__global__ __launch_bounds__(256) void attention_kernel(
    const float* __restrict__ Q, const float* __restrict__ Kb,
    const float* __restrict__ Vb, float* __restrict__ O,
    const float* __restrict__ qw, const float* __restrict__ qb,
    const float* __restrict__ kw, const float* __restrict__ kb) {
    extern __shared__ float smf[];
    float* qs = smf + ATT_QS;
    float* ks = smf + ATT_KS;
    float* vs = smf + ATT_VS;
    float* ps = smf + ATT_PS;

    int tid = threadIdx.x;
    int bh = blockIdx.x;
    int b = bh >> 4, h = bh & 15;
    const float qscale = rsqrtf((float)HDd);

    int myrow = tid >> 2, mypart = tid & 3;
    int qg = tid >> 4, kg = tid & 15;

    {
        const float* qp = Q + (size_t)(b * NLl + myrow) * HHD + h * HDd + mypart * 24;
        float v[24];
        float s = 0.f, ss = 0.f;
#pragma unroll
        for (int i = 0; i < 24; i += 4) {
            float4 t = *(const float4*)(qp + i);
            v[i] = t.x; v[i+1] = t.y; v[i+2] = t.z; v[i+3] = t.w;
        }
#pragma unroll
        for (int i = 0; i < 24; i++) { s += v[i]; ss += v[i] * v[i]; }
#pragma unroll
        for (int o = 1; o < 4; o <<= 1) {
            s  += __shfl_xor_sync(0xffffffffu, s, o);
            ss += __shfl_xor_sync(0xffffffffu, ss, o);
        }
        float mmu = s * (1.f / 96.f);
        float rsd = rsqrtf(ss * (1.f / 96.f) - mmu * mmu + EPSf);
#pragma unroll
        for (int i = 0; i < 24; i++) {
            int c = mypart * 24 + i;
            qs[myrow * 100 + c] = ((v[i] - mmu) * rsd * qw[c] + qb[c]) * qscale;
        }
    }
    __syncthreads();

    float m_run = -INFINITY, l_run = 0.f;
    float oacc[24];
#pragma unroll
    for (int i = 0; i < 24; i++) oacc[i] = 0.f;

    for (int t = 0; t < SKV / 32; t++) {
        {
            int j = tid >> 3, p8 = tid & 7;
            int kidx = t * 32 + j;
            const float* kp = Kb + ((size_t)b * SKV + kidx) * HHD + h * HDd + p8 * 12;
            const float* vp = Vb + ((size_t)b * SKV + kidx) * HHD + h * HDd + p8 * 12;
            float kv[12];
            float s = 0.f, ss = 0.f;
#pragma unroll
            for (int i = 0; i < 12; i += 4) {
                float4 tt = *(const float4*)(kp + i);
                kv[i] = tt.x; kv[i+1] = tt.y; kv[i+2] = tt.z; kv[i+3] = tt.w;
            }
#pragma unroll
            for (int i = 0; i < 12; i++) { s += kv[i]; ss += kv[i] * kv[i]; }
#pragma unroll
            for (int o = 1; o < 8; o <<= 1) {
                s  += __shfl_xor_sync(0xffffffffu, s, o);
                ss += __shfl_xor_sync(0xffffffffu, ss, o);
            }
            float mmu = s * (1.f / 96.f);
            float rsd = rsqrtf(ss * (1.f / 96.f) - mmu * mmu + EPSf);
#pragma unroll
            for (int i = 0; i < 12; i++) {
                int c = p8 * 12 + i;
                ks[j * 100 + c] = (kv[i] - mmu) * rsd * kw[c] + kb[c];
            }
#pragma unroll
            for (int i = 0; i < 12; i += 4)
                *(float4*)&vs[j * 100 + p8 * 12 + i] = *(const float4*)(vp + i);
        }
        __syncthreads();

        {
            float sc[4][2];
#pragma unroll
            for (int i = 0; i < 4; i++) { sc[i][0] = 0.f; sc[i][1] = 0.f; }
            int q0 = qg << 2, k0 = kg << 1;
#pragma unroll
            for (int d = 0; d < 96; d += 4) {
                float4 k0v = *(const float4*)&ks[k0 * 100 + d];
                float4 k1v = *(const float4*)&ks[(k0 + 1) * 100 + d];
#pragma unroll
                for (int i = 0; i < 4; i++) {
                    float4 qv = *(const float4*)&qs[(q0 + i) * 100 + d];
                    sc[i][0] += qv.x*k0v.x + qv.y*k0v.y + qv.z*k0v.z + qv.w*k0v.w;
                    sc[i][1] += qv.x*k1v.x + qv.y*k1v.y + qv.z*k1v.z + qv.w*k1v.w;
                }
            }
#pragma unroll
            for (int i = 0; i < 4; i++) {
                ps[(q0 + i) * 33 + k0]     = sc[i][0];
                ps[(q0 + i) * 33 + k0 + 1] = sc[i][1];
            }
        }
        __syncwarp();

        {
            float p8v[8];
            float mx = -INFINITY;
#pragma unroll
            for (int i = 0; i < 8; i++) {
                p8v[i] = ps[myrow * 33 + mypart * 8 + i];
                mx = fmaxf(mx, p8v[i]);
            }
#pragma unroll
            for (int o = 1; o < 4; o <<= 1)
                mx = fmaxf(mx, __shfl_xor_sync(0xffffffffu, mx, o));
            float mnew = fmaxf(m_run, mx);
            float corr = __expf(m_run - mnew);
            float psum = 0.f;
#pragma unroll
            for (int i = 0; i < 8; i++) {
                p8v[i] = __expf(p8v[i] - mnew);
                psum += p8v[i];
                ps[myrow * 33 + mypart * 8 + i] = p8v[i];
            }
#pragma unroll
            for (int o = 1; o < 4; o <<= 1)
                psum += __shfl_xor_sync(0xffffffffu, psum, o);
            l_run = l_run * corr + psum;
            m_run = mnew;
#pragma unroll
            for (int i = 0; i < 24; i++) oacc[i] *= corr;
            __syncwarp();
#pragma unroll 4
            for (int j = 0; j < 32; j++) {
                float p = ps[myrow * 33 + j];
                const float4* vr = (const float4*)&vs[j * 100 + mypart * 24];
#pragma unroll
                for (int i4 = 0; i4 < 6; i4++) {
                    float4 v = vr[i4];
                    oacc[i4*4+0] += p * v.x;
                    oacc[i4*4+1] += p * v.y;
                    oacc[i4*4+2] += p * v.z;
                    oacc[i4*4+3] += p * v.w;
                }
            }
        }
        __syncthreads();
    }

    {
        float inv = 1.f / l_run;
        float* op = O + (size_t)(b * NLl + myrow) * HHD + h * HDd + mypart * 24;
#pragma unroll
        for (int i = 0; i < 24; i++) op[i] = oacc[i] * inv;
    }
}

// ======================= final layer norm -> d_out ==========================
__global__ void final_ln_kernel(float* __restrict__ out,
                                const float* __restrict__ w,
                                const float* __restrict__ bia) {
    int row = blockIdx.x;
    const float* x = g_lat + (size_t)row * Dd;
    float s = 0.f, ss = 0.f;
    for (int c = threadIdx.x; c < Dd; c += blockDim.x) {
        float v = x[c]; s += v; ss += v * v;
    }
#pragma unroll
    for (int o = 16; o > 0; o >>= 1) {
        s  += __shfl_xor_sync(0xffffffffu, s, o);
        ss += __shfl_xor_sync(0xffffffffu, ss, o);
    }
    __shared__ float red_s[8], red_q[8];
    __shared__ float sh_m, sh_r;
    int wrp = threadIdx.x >> 5, nl = threadIdx.x & 31;
    if (nl == 0) { red_s[wrp] = s; red_q[wrp] = ss; }
    __syncthreads();
    if (threadIdx.x == 0) {
        float S = 0.f, Q = 0.f;
        for (int i = 0; i < 8; i++) { S += red_s[i]; Q += red_q[i]; }
        float m = S / (float)Dd;
        sh_m = m;
        sh_r = rsqrtf(Q / (float)Dd - m * m + EPSf);
    }
    __syncthreads();
    float m = sh_m, r = sh_r;
    for (int c = threadIdx.x; c < Dd; c += blockDim.x)
        out[(size_t)row * Dd + c] = (x[c] - m) * r * w[c] + bia[c];
}

// ======================= launch =============================================
extern "C" void kernel_launch(void* const* d_in, const int* in_sizes, int n_in,
                              void* d_out, int out_size) {
    const float* context  = (const float*)d_in[0];
    const float* latents  = (const float*)d_in[1];
    const float* ctx_ln_w = (const float*)d_in[2];
    const float* ctx_ln_b = (const float*)d_in[3];
    const float* lat_ln_w = (const float*)d_in[4];
    const float* lat_ln_b = (const float*)d_in[5];
    const float* q_ln_w   = (const float*)d_in[6];
    const float* q_ln_b   = (const float*)d_in[7];
    const float* k_ln_w   = (const float*)d_in[8];
    const float* k_ln_b   = (const float*)d_in[9];
    const float* wq       = (const float*)d_in[10];
    const float* wk       = (const float*)d_in[11];
    const float* wv       = (const float*)d_in[12];
    const float* wo       = (const float*)d_in[13];
    const float* mlp_ln_w = (const float*)d_in[14];
    const float* mlp_ln_b = (const float*)d_in[15];
    const float* w_fc     = (const float*)d_in[16];
    const float* w_cproj  = (const float*)d_in[17];
    const float* fin_w    = (const float*)d_in[18];
    const float* fin_b    = (const float*)d_in[19];
    (void)in_sizes; (void)n_in; (void)out_size;

    float *pCm, *pCr, *pLat, *pLm, *pLr, *pQ, *pK, *pV, *pAttn, *pMlp;
    unsigned *pWt, *pAp;
    cudaGetSymbolAddress((void**)&pCm,   g_ctx_mean);
    cudaGetSymbolAddress((void**)&pCr,   g_ctx_rstd);
    cudaGetSymbolAddress((void**)&pLat,  g_lat);
    cudaGetSymbolAddress((void**)&pLm,   g_lat_mean);
    cudaGetSymbolAddress((void**)&pLr,   g_lat_rstd);
    cudaGetSymbolAddress((void**)&pQ,    g_Q);
    cudaGetSymbolAddress((void**)&pK,    g_K);
    cudaGetSymbolAddress((void**)&pV,    g_V);
    cudaGetSymbolAddress((void**)&pAttn, g_attn);
    cudaGetSymbolAddress((void**)&pMlp,  g_mlp);
    cudaGetSymbolAddress((void**)&pWt,   g_Wt);
    cudaGetSymbolAddress((void**)&pAp,   g_Apack);

    cudaFuncSetAttribute(attention_kernel,
                         cudaFuncAttributeMaxDynamicSharedMemorySize, ATT_SMEM);
    cudaFuncSetAttribute(gemm_mma_kernel,
                         cudaFuncAttributeMaxDynamicSharedMemorySize, GM_SMEM);

    // ---- one-time weight transpose + bf16 hi/lo split ----
    dim3 tb(32, 8);
    for (int i = 0; i < DEPTHn; i++) {
        size_t base = (size_t)i * WT_LAYER;
        wt_pack_kernel<<<dim3(HHD / 32, Dd / 32), tb>>>(
            wq + (size_t)i * Dd * HHD, pWt + base, Dd, HHD);
        wt_pack_kernel<<<dim3(HHD / 32, Dd / 32), tb>>>(
            wk + (size_t)i * Dd * HHD, pWt + base + WT_QKV, Dd, HHD);
        wt_pack_kernel<<<dim3(HHD / 32, Dd / 32), tb>>>(
            wv + (size_t)i * Dd * HHD, pWt + base + 2u * WT_QKV, Dd, HHD);
        wt_pack_kernel<<<dim3(Dd / 32, HHD / 32), tb>>>(
            wo + (size_t)i * HHD * Dd, pWt + base + 3u * WT_QKV, HHD, Dd);
        wt_pack_kernel<<<dim3(FFf / 32, Dd / 32), tb>>>(
            w_fc + (size_t)i * Dd * FFf, pWt + base + 4u * WT_QKV, Dd, FFf);
        wt_pack_kernel<<<dim3(Dd / 32, FFf / 32), tb>>>(
            w_cproj + (size_t)i * FFf * Dd, pWt + base + 4u * WT_QKV + WT_FC,
            FFf, Dd);
    }

    rowstats_kernel<<<Bb * Ss, 256>>>(context, pCm, pCr, Dd);
    broadcast_lat_kernel<<<(Bb * NLl * Dd + 255) / 256, 256>>>(latents);

    const int ML = Bb * NLl;   // 2048
    const int MC = Bb * Ss;    // 65536

    for (int i = 0; i < DEPTHn; i++) {
        size_t base = (size_t)i * WT_LAYER;
        const unsigned* wq_t = pWt + base;
        const unsigned* wk_t = pWt + base + WT_QKV;
        const unsigned* wv_t = pWt + base + 2u * WT_QKV;
        const unsigned* wo_t = pWt + base + 3u * WT_QKV;
        const unsigned* wfc_t = pWt + base + 4u * WT_QKV;
        const unsigned* wcp_t = pWt + base + 4u * WT_QKV + WT_FC;
        const float* clw = ctx_ln_w + i * Dd, *clb = ctx_ln_b + i * Dd;
        const float* llw = lat_ln_w + i * Dd, *llb = lat_ln_b + i * Dd;
        const float* mlw = mlp_ln_w + i * Dd, *mlb = mlp_ln_b + i * Dd;
        const float* qlw = q_ln_w + i * HDd, *qlb = q_ln_b + i * HDd;
        const float* klw = k_ln_w + i * HDd, *klb = k_ln_b + i * HDd;

        // latent QKV
        rowstats_kernel<<<ML, 256>>>(pLat, pLm, pLr, Dd);
        pack_ln_kernel<<<ML, 256>>>(pLat, pLm, pLr, llw, llb, pAp, Dd);
        gemm_mma_kernel<<<dim3(HHD / 128, ML / 128), 256, GM_SMEM>>>(
            pAp, wq_t, pQ, ML, HHD, Dd, HHD, nullptr, 0, 0);
        gemm_mma_kernel<<<dim3(HHD / 128, ML / 128), 256, GM_SMEM>>>(
            pAp, wk_t, pK, ML, HHD, Dd, HHD, nullptr, 0, 1);
        gemm_mma_kernel<<<dim3(HHD / 128, ML / 128), 256, GM_SMEM>>>(
            pAp, wv_t, pV, ML, HHD, Dd, HHD, nullptr, 0, 1);

        // context KV
        pack_ln_kernel<<<MC, 256>>>(context, pCm, pCr, clw, clb, pAp, Dd);
        gemm_mma_kernel<<<dim3(HHD / 128, MC / 128), 256, GM_SMEM>>>(
            pAp, wk_t, pK, MC, HHD, Dd, HHD, nullptr, 0, 2);
        gemm_mma_kernel<<<dim3(HHD / 128, MC / 128), 256, GM_SMEM>>>(
            pAp, wv_t, pV, MC, HHD, Dd, HHD, nullptr, 0, 2);

        attention_kernel<<<Bb * Hh, 256, ATT_SMEM>>>(pQ, pK, pV, pAttn,
                                                     qlw, qlb, klw, klb);

        // wo projection + residual
        pack_ln_kernel<<<ML, 256>>>(pAttn, nullptr, nullptr, nullptr, nullptr,
                                    pAp, HHD);
        gemm_mma_kernel<<<dim3(Dd / 128, ML / 128), 256, GM_SMEM>>>(
            pAp, wo_t, pLat, ML, Dd, HHD, Dd, pLat, 0, 0);

        // MLP
        rowstats_kernel<<<ML, 256>>>(pLat, pLm, pLr, Dd);
        pack_ln_kernel<<<ML, 256>>>(pLat, pLm, pLr, mlw, mlb, pAp, Dd);
        gemm_mma_kernel<<<dim3(FFf / 128, ML / 128), 256, GM_SMEM>>>(
            pAp, wfc_t, pMlp, ML, FFf, Dd, FFf, nullptr, 1, 0);
        pack_ln_kernel<<<ML, 256>>>(pMlp, nullptr, nullptr, nullptr, nullptr,
                                    pAp, FFf);
        gemm_mma_kernel<<<dim3(Dd / 128, ML / 128), 256, GM_SMEM>>>(
            pAp, wcp_t, pLat, ML, Dd, FFf, Dd, pLat, 0, 0);
    }

    final_ln_kernel<<<Bb * NLl, 256>>>((float*)d_out, fin_w, fin_b);
}

// round 5
// speedup vs baseline: 2.2520x; 1.0579x over previous
#include <cuda_runtime.h>
#include <cuda_bf16.h>
#include <cstdint>
#include <math.h>

#define Bb     32
#define Ss     2048
#define Dd     1280
#define Hh     16
#define HDd    96
#define NLl    64
#define DEPTHn 3
#define FFf    5120
#define SKV    (Ss + NLl)      /* 2112 */
#define HHD    (Hh * HDd)      /* 1536 */
#define EPSf   1e-5f

typedef __nv_bfloat16 bf16;

// ======================= scratch (device globals) ===========================
__device__ float g_ctx_mean[Bb * Ss];
__device__ float g_ctx_rstd[Bb * Ss];
__device__ float g_lat[Bb * NLl * Dd];
__device__ float g_lat_mean[Bb * NLl];
__device__ float g_lat_rstd[Bb * NLl];
__device__ float g_Q[Bb * NLl * HHD];
__device__ float g_K[(size_t)Bb * SKV * HHD];
__device__ float g_V[(size_t)Bb * SKV * HHD];
__device__ float g_attn[Bb * NLl * HHD];
__device__ float g_mlp[(size_t)Bb * NLl * FFf];
__device__ float g_bias[DEPTHn * 2 * HHD];

// weight planes: [N][K] bf16, hi and lo of the fp32 value
#define SZ1      1966080u                 /* 1536*1280 (= 1280*1536) */
#define SZFC     6553600u                 /* 5120*1280 */
#define OFF_WQ   0u
#define OFF_WK   (SZ1)
#define OFF_WV   (2u * SZ1)
#define OFF_WKF  (3u * SZ1)               /* gamma-folded, ctx */
#define OFF_WVF  (4u * SZ1)
#define OFF_WO   (5u * SZ1)
#define OFF_WFC  (6u * SZ1)
#define OFF_WCP  (6u * SZ1 + SZFC)
#define LAYER_W  (6u * SZ1 + 2u * SZFC)   /* 24903680 */
__device__ bf16 g_Whi[(size_t)DEPTHn * LAYER_W];
__device__ bf16 g_Wlo[(size_t)DEPTHn * LAYER_W];

// activation planes
__device__ bf16 g_Ahi[(size_t)Bb * Ss * Dd];   // ctx, packed ONCE
__device__ bf16 g_Alo[(size_t)Bb * Ss * Dd];
__device__ bf16 g_Lhi[(size_t)Bb * NLl * FFf]; // latent-side scratch
__device__ bf16 g_Llo[(size_t)Bb * NLl * FFf];

// ======================= small prep kernels =================================
__global__ void rowstats_kernel(const float* __restrict__ X,
                                float* __restrict__ mean,
                                float* __restrict__ rstd, int ncols) {
    int row = blockIdx.x;
    const float* x = X + (size_t)row * ncols;
    float s = 0.f, ss = 0.f;
    for (int c = threadIdx.x; c < ncols; c += blockDim.x) {
        float v = x[c]; s += v; ss += v * v;
    }
#pragma unroll
    for (int o = 16; o > 0; o >>= 1) {
        s  += __shfl_xor_sync(0xffffffffu, s, o);
        ss += __shfl_xor_sync(0xffffffffu, ss, o);
    }
    __shared__ float red_s[8], red_q[8];
    int w = threadIdx.x >> 5, nl = threadIdx.x & 31;
    if (nl == 0) { red_s[w] = s; red_q[w] = ss; }
    __syncthreads();
    if (threadIdx.x == 0) {
        float S = 0.f, Q = 0.f;
        int nw = blockDim.x >> 5;
        for (int i = 0; i < nw; i++) { S += red_s[i]; Q += red_q[i]; }
        float m = S / (float)ncols;
        mean[row] = m;
        rstd[row] = rsqrtf(Q / (float)ncols - m * m + EPSf);
    }
}

__global__ void broadcast_lat_kernel(const float* __restrict__ latents) {
    int i = blockIdx.x * blockDim.x + threadIdx.x;
    const int per = NLl * Dd;
    if (i < Bb * per) g_lat[i] = latents[i % per];
}

// (optional stats)(optional affine) + hi/lo split -> two bf16 planes
__global__ void pack2_kernel(const float* __restrict__ X,
                             const float* __restrict__ mean,
                             const float* __restrict__ rstd,
                             const float* __restrict__ lnw,
                             const float* __restrict__ lnb,
                             bf16* __restrict__ hi, bf16* __restrict__ lo,
                             int ncols) {
    int row = blockIdx.x;
    const float* x = X + (size_t)row * ncols;
    bf16* oh = hi + (size_t)row * ncols;
    bf16* ol = lo + (size_t)row * ncols;
    float mu = 0.f, rs = 1.f;
    if (mean) { mu = mean[row]; rs = rstd[row]; }
    for (int c = threadIdx.x; c < ncols; c += blockDim.x) {
        float v = x[c];
        if (mean) v = (v - mu) * rs;
        if (lnw)  v = v * lnw[c] + lnb[c];
        bf16 h = __float2bfloat16(v);
        bf16 l = __float2bfloat16(v - __bfloat162float(h));
        oh[c] = h; ol[c] = l;
    }
}

// transpose + optional gamma fold + hi/lo split: W[K,N] -> planes[N,K]
__global__ void wt_pack2_kernel(const float* __restrict__ W,
                                const float* __restrict__ gamma,
                                bf16* __restrict__ hi, bf16* __restrict__ lo,
                                int K, int N) {
    __shared__ float tile[32][33];
    int n0 = blockIdx.x << 5, k0 = blockIdx.y << 5;
    for (int i = threadIdx.y; i < 32; i += 8)
        tile[i][threadIdx.x] = W[(size_t)(k0 + i) * N + n0 + threadIdx.x];
    __syncthreads();
    float g = gamma ? gamma[k0 + threadIdx.x] : 1.f;
    for (int i = threadIdx.y; i < 32; i += 8) {
        float v = tile[threadIdx.x][i] * g;   // W[k0+tx][n0+i]
        bf16 h = __float2bfloat16(v);
        bf16 l = __float2bfloat16(v - __bfloat162float(h));
        size_t idx = (size_t)(n0 + i) * K + k0 + threadIdx.x;
        hi[idx] = h; lo[idx] = l;
    }
}

// bias[n] = sum_k beta[k] * W[k*N + n]
__global__ void bias_kernel(const float* __restrict__ beta,
                            const float* __restrict__ W,
                            float* __restrict__ out, int K, int N) {
    int n = blockIdx.x * blockDim.x + threadIdx.x;
    if (n >= N) return;
    float s = 0.f;
    for (int k = 0; k < K; k++) s += beta[k] * W[(size_t)k * N + n];
    out[n] = s;
}

// ======================= HMMA GEMM with cp.async pipeline ===================
// C[crow(r), n] = A[r,:] @ Wt[n,:]  bf16x3 (Ah.Bh + Ah.Bl + Al.Bh), fp32 acc
// CTA tile 128x256, 8 warps (2m x 4n), warp tile 64x64, K chunk 64, 2 stages.
#define PL_AH    0
#define PL_AL    16384
#define PL_BH    32768
#define PL_BL    65536
#define ST_BYTES 98304
#define GM_SMEM  (2 * ST_BYTES)

#define CP_ASYNC16(dst, src) \
    asm volatile("cp.async.cg.shared.global [%0], [%1], 16;" \
                 :: "r"(dst), "l"(src))
#define CP_COMMIT() asm volatile("cp.async.commit_group;" ::: "memory")
#define CP_WAIT0()  asm volatile("cp.async.wait_group 0;" ::: "memory")
#define CP_WAIT1()  asm volatile("cp.async.wait_group 1;" ::: "memory")

#define LDSM4(r0, r1, r2, r3, addr)                                          \
    asm volatile("ldmatrix.sync.aligned.m8n8.x4.shared.b16 {%0,%1,%2,%3}, [%4];" \
        : "=r"(r0), "=r"(r1), "=r"(r2), "=r"(r3) : "r"(addr))

#define MMA16816(d, a, b0, b1)                                               \
    asm volatile("mma.sync.aligned.m16n8k16.row.col.f32.bf16.bf16.f32 "      \
        "{%0,%1,%2,%3}, {%4,%5,%6,%7}, {%8,%9}, {%0,%1,%2,%3};"              \
        : "+f"((d)[0]), "+f"((d)[1]), "+f"((d)[2]), "+f"((d)[3])             \
        : "r"((a)[0]), "r"((a)[1]), "r"((a)[2]), "r"((a)[3]),                \
          "r"(b0), "r"(b1))

__device__ __forceinline__ uint32_t smem_u32(const void* p) {
    uint32_t a;
    asm("{ .reg .u64 t; cvta.to.shared.u64 t, %1; cvt.u32.u64 %0, t; }"
        : "=r"(a) : "l"(p));
    return a;
}
__device__ __forceinline__ uint32_t swz(uint32_t off) {
    return off ^ ((off >> 3) & 0x70);
}

__device__ __forceinline__ void issue_chunk(
    uint32_t st, const bf16* __restrict__ Ahi, const bf16* __restrict__ Alo,
    const bf16* __restrict__ Bhi, const bf16* __restrict__ Blo,
    int K, int c, int tid) {
    // A planes: 128 rows x 8 x16B each -> 4 copies/thread/plane
#pragma unroll
    for (int i = 0; i < 4; i++) {
        int flat = i * 256 + tid;
        int row = flat >> 3, col16 = flat & 7;
        uint32_t off = swz((uint32_t)(row * 128 + col16 * 16));
        size_t gsrc = (size_t)row * K + (size_t)c * 64 + col16 * 8;
        CP_ASYNC16(st + PL_AH + off, Ahi + gsrc);
        CP_ASYNC16(st + PL_AL + off, Alo + gsrc);
    }
    // B planes: 256 rows x 8 -> 8 copies/thread/plane
#pragma unroll
    for (int i = 0; i < 8; i++) {
        int flat = i * 256 + tid;
        int row = flat >> 3, col16 = flat & 7;
        uint32_t off = swz((uint32_t)(row * 128 + col16 * 16));
        size_t gsrc = (size_t)row * K + (size_t)c * 64 + col16 * 8;
        CP_ASYNC16(st + PL_BH + off, Bhi + gsrc);
        CP_ASYNC16(st + PL_BL + off, Blo + gsrc);
    }
}

__global__ __launch_bounds__(256, 1) void gemm_cp_kernel(
    const bf16* __restrict__ Ahi, const bf16* __restrict__ Alo,
    const bf16* __restrict__ Whi, const bf16* __restrict__ Wlo,
    float* __restrict__ C, int K, int N, int ldc,
    const float* __restrict__ bias, const float* __restrict__ resid,
    int relu, int remap) {
    extern __shared__ char sm[];
    uint32_t smb = smem_u32(sm);
    int tid = threadIdx.x, wid = tid >> 5, lane = tid & 31;
    int warp_m = wid >> 2, warp_n = wid & 3;

    int m0 = blockIdx.y << 7, n0 = blockIdx.x << 8;
    const bf16* Ah = Ahi + (size_t)m0 * K;
    const bf16* Al = Alo + (size_t)m0 * K;
    const bf16* Bh = Whi + (size_t)n0 * K;
    const bf16* Bl = Wlo + (size_t)n0 * K;
    int NC = K >> 6;

    float acc[4][8][4];
#pragma unroll
    for (int i = 0; i < 4; i++)
#pragma unroll
        for (int j = 0; j < 8; j++)
#pragma unroll
            for (int k = 0; k < 4; k++) acc[i][j][k] = 0.f;

    issue_chunk(smb, Ah, Al, Bh, Bl, K, 0, tid);
    CP_COMMIT();
    issue_chunk(smb + ST_BYTES, Ah, Al, Bh, Bl, K, 1, tid);
    CP_COMMIT();

    int lrow = lane & 15, lhalf = lane >> 4;
    for (int c = 0; c < NC; c++) {
        if (c + 1 < NC) { CP_WAIT1(); } else { CP_WAIT0(); }
        __syncthreads();
        uint32_t st = smb + (uint32_t)((c & 1) * ST_BYTES);
#pragma unroll
        for (int kq = 0; kq < 4; kq++) {
            int ch = kq * 2 + lhalf;
            uint32_t ah[4][4], al[4][4];
#pragma unroll
            for (int mt = 0; mt < 4; mt++) {
                uint32_t ro = swz((uint32_t)((warp_m * 64 + mt * 16 + lrow) * 128 + ch * 16));
                LDSM4(ah[mt][0], ah[mt][1], ah[mt][2], ah[mt][3], st + PL_AH + ro);
                LDSM4(al[mt][0], al[mt][1], al[mt][2], al[mt][3], st + PL_AL + ro);
            }
            uint32_t bh0[8], bh1[8], bl0[8], bl1[8];
#pragma unroll
            for (int nt2 = 0; nt2 < 4; nt2++) {
                uint32_t ro = swz((uint32_t)((warp_n * 64 + nt2 * 16 + lrow) * 128 + ch * 16));
                uint32_t r0, r1, r2, r3;
                LDSM4(r0, r1, r2, r3, st + PL_BH + ro);
                bh0[nt2 * 2] = r0; bh1[nt2 * 2] = r2;
                bh0[nt2 * 2 + 1] = r1; bh1[nt2 * 2 + 1] = r3;
                LDSM4(r0, r1, r2, r3, st + PL_BL + ro);
                bl0[nt2 * 2] = r0; bl1[nt2 * 2] = r2;
                bl0[nt2 * 2 + 1] = r1; bl1[nt2 * 2 + 1] = r3;
            }
#pragma unroll
            for (int mt = 0; mt < 4; mt++)
#pragma unroll
                for (int nt = 0; nt < 8; nt++) {
                    MMA16816(acc[mt][nt], ah[mt], bh0[nt], bh1[nt]);
                    MMA16816(acc[mt][nt], ah[mt], bl0[nt], bl1[nt]);
                    MMA16816(acc[mt][nt], al[mt], bh0[nt], bh1[nt]);
                }
        }
        __syncthreads();
        if (c + 2 < NC) {
            issue_chunk(smb + (uint32_t)((c & 1) * ST_BYTES), Ah, Al, Bh, Bl,
                        K, c + 2, tid);
            CP_COMMIT();
        }
    }

    // epilogue
    int qrow = lane >> 2, qcol = (lane & 3) * 2;
#pragma unroll
    for (int mt = 0; mt < 4; mt++) {
#pragma unroll
        for (int half = 0; half < 2; half++) {
            int r = m0 + warp_m * 64 + mt * 16 + half * 8 + qrow;
            int crow;
            if (remap == 1)      crow = (r >> 6)  * SKV + Ss + (r & 63);
            else if (remap == 2) crow = (r >> 11) * SKV + (r & 2047);
            else                 crow = r;
            int cb = n0 + warp_n * 64;
            float* cp = C + (size_t)crow * ldc + cb;
            const float* rp = resid ? resid + (size_t)r * N + cb : nullptr;
            const float* bp = bias ? bias + cb : nullptr;
#pragma unroll
            for (int nt = 0; nt < 8; nt++) {
                float v0 = acc[mt][nt][half * 2];
                float v1 = acc[mt][nt][half * 2 + 1];
                int col = nt * 8 + qcol;
                if (bp) { v0 += bp[col]; v1 += bp[col + 1]; }
                if (rp) { v0 += rp[col]; v1 += rp[col + 1]; }
                if (relu) { v0 = fmaxf(v0, 0.f); v1 = fmaxf(v1, 0.f); }
                *(float2*)(cp + col) = make_float2(v0, v1);
            }
        }
    }
}

// ======================= fused attention ====================================
#define ATT_QS   0
#define ATT_KS   (64 * 100)
#define ATT_VS   (ATT_KS + 32 * 100)
#define ATT_PS   (ATT_VS + 32 * 100)
#define ATT_SMEM ((ATT_PS + 64 * 33) * 4)

__global__ __launch_bounds__(256) void attention_kernel(
    const float* __restrict__ Q, const float* __restrict__ Kb,
    const float* __restrict__ Vb, float* __restrict__ O,
    const float* __restrict__ qw, const float* __restrict__ qb,
    const float* __restrict__ kw, const float* __restrict__ kb) {
    extern __shared__ float smf[];
    float* qs = smf + ATT_QS;
    float* ks = smf + ATT_KS;
    float* vs = smf + ATT_VS;
    float* ps = smf + ATT_PS;

    int tid = threadIdx.x;
    int bh = blockIdx.x;
    int b = bh >> 4, h = bh & 15;
    const float qscale = rsqrtf((float)HDd);

    int myrow = tid >> 2, mypart = tid & 3;
    int qg = tid >> 4, kg = tid & 15;

    {
        const float* qp = Q + (size_t)(b * NLl + myrow) * HHD + h * HDd + mypart * 24;
        float v[24];
        float s = 0.f, ss = 0.f;
#pragma unroll
        for (int i = 0; i < 24; i += 4) {
            float4 t = *(const float4*)(qp + i);
            v[i] = t.x; v[i+1] = t.y; v[i+2] = t.z; v[i+3] = t.w;
        }
#pragma unroll
        for (int i = 0; i < 24; i++) { s += v[i]; ss += v[i] * v[i]; }
#pragma unroll
        for (int o = 1; o < 4; o <<= 1) {
            s  += __shfl_xor_sync(0xffffffffu, s, o);
            ss += __shfl_xor_sync(0xffffffffu, ss, o);
        }
        float mmu = s * (1.f / 96.f);
        float rsd = rsqrtf(ss * (1.f / 96.f) - mmu * mmu + EPSf);
#pragma unroll
        for (int i = 0; i < 24; i++) {
            int c = mypart * 24 + i;
            qs[myrow * 100 + c] = ((v[i] - mmu) * rsd * qw[c] + qb[c]) * qscale;
        }
    }
    __syncthreads();

    float m_run = -INFINITY, l_run = 0.f;
    float oacc[24];
#pragma unroll
    for (int i = 0; i < 24; i++) oacc[i] = 0.f;

    for (int t = 0; t < SKV / 32; t++) {
        {
            int j = tid >> 3, p8 = tid & 7;
            int kidx = t * 32 + j;
            const float* kp = Kb + ((size_t)b * SKV + kidx) * HHD + h * HDd + p8 * 12;
            const float* vp = Vb + ((size_t)b * SKV + kidx) * HHD + h * HDd + p8 * 12;
            float kv[12];
            float s = 0.f, ss = 0.f;
#pragma unroll
            for (int i = 0; i < 12; i += 4) {
                float4 tt = *(const float4*)(kp + i);
                kv[i] = tt.x; kv[i+1] = tt.y; kv[i+2] = tt.z; kv[i+3] = tt.w;
            }
#pragma unroll
            for (int i = 0; i < 12; i++) { s += kv[i]; ss += kv[i] * kv[i]; }
#pragma unroll
            for (int o = 1; o < 8; o <<= 1) {
                s  += __shfl_xor_sync(0xffffffffu, s, o);
                ss += __shfl_xor_sync(0xffffffffu, ss, o);
            }
            float mmu = s * (1.f / 96.f);
            float rsd = rsqrtf(ss * (1.f / 96.f) - mmu * mmu + EPSf);
#pragma unroll
            for (int i = 0; i < 12; i++) {
                int c = p8 * 12 + i;
                ks[j * 100 + c] = (kv[i] - mmu) * rsd * kw[c] + kb[c];
            }
#pragma unroll
            for (int i = 0; i < 12; i += 4)
                *(float4*)&vs[j * 100 + p8 * 12 + i] = *(const float4*)(vp + i);
        }
        __syncthreads();

        {
            float sc[4][2];
#pragma unroll
            for (int i = 0; i < 4; i++) { sc[i][0] = 0.f; sc[i][1] = 0.f; }
            int q0 = qg << 2, k0 = kg << 1;
#pragma unroll
            for (int d = 0; d < 96; d += 4) {
                float4 k0v = *(const float4*)&ks[k0 * 100 + d];
                float4 k1v = *(const float4*)&ks[(k0 + 1) * 100 + d];
#pragma unroll
                for (int i = 0; i < 4; i++) {
                    float4 qv = *(const float4*)&qs[(q0 + i) * 100 + d];
                    sc[i][0] += qv.x*k0v.x + qv.y*k0v.y + qv.z*k0v.z + qv.w*k0v.w;
                    sc[i][1] += qv.x*k1v.x + qv.y*k1v.y + qv.z*k1v.z + qv.w*k1v.w;
                }
            }
#pragma unroll
            for (int i = 0; i < 4; i++) {
                ps[(q0 + i) * 33 + k0]     = sc[i][0];
                ps[(q0 + i) * 33 + k0 + 1] = sc[i][1];
            }
        }
        __syncwarp();

        {
            float p8v[8];
            float mx = -INFINITY;
#pragma unroll
            for (int i = 0; i < 8; i++) {
                p8v[i] = ps[myrow * 33 + mypart * 8 + i];
                mx = fmaxf(mx, p8v[i]);
            }
#pragma unroll
            for (int o = 1; o < 4; o <<= 1)
                mx = fmaxf(mx, __shfl_xor_sync(0xffffffffu, mx, o));
            float mnew = fmaxf(m_run, mx);
            float corr = __expf(m_run - mnew);
            float psum = 0.f;
#pragma unroll
            for (int i = 0; i < 8; i++) {
                p8v[i] = __expf(p8v[i] - mnew);
                psum += p8v[i];
                ps[myrow * 33 + mypart * 8 + i] = p8v[i];
            }
#pragma unroll
            for (int o = 1; o < 4; o <<= 1)
                psum += __shfl_xor_sync(0xffffffffu, psum, o);
            l_run = l_run * corr + psum;
            m_run = mnew;
#pragma unroll
            for (int i = 0; i < 24; i++) oacc[i] *= corr;
            __syncwarp();
#pragma unroll 4
            for (int j = 0; j < 32; j++) {
                float p = ps[myrow * 33 + j];
                const float4* vr = (const float4*)&vs[j * 100 + mypart * 24];
#pragma unroll
                for (int i4 = 0; i4 < 6; i4++) {
                    float4 v = vr[i4];
                    oacc[i4*4+0] += p * v.x;
                    oacc[i4*4+1] += p * v.y;
                    oacc[i4*4+2] += p * v.z;
                    oacc[i4*4+3] += p * v.w;
                }
            }
        }
        __syncthreads();
    }

    {
        float inv = 1.f / l_run;
        float* op = O + (size_t)(b * NLl + myrow) * HHD + h * HDd + mypart * 24;
#pragma unroll
        for (int i = 0; i < 24; i++) op[i] = oacc[i] * inv;
    }
}

// ======================= final layer norm -> d_out ==========================
__global__ void final_ln_kernel(float* __restrict__ out,
                                const float* __restrict__ w,
                                const float* __restrict__ bia) {
    int row = blockIdx.x;
    const float* x = g_lat + (size_t)row * Dd;
    float s = 0.f, ss = 0.f;
    for (int c = threadIdx.x; c < Dd; c += blockDim.x) {
        float v = x[c]; s += v; ss += v * v;
    }
#pragma unroll
    for (int o = 16; o > 0; o >>= 1) {
        s  += __shfl_xor_sync(0xffffffffu, s, o);
        ss += __shfl_xor_sync(0xffffffffu, ss, o);
    }
    __shared__ float red_s[8], red_q[8];
    __shared__ float sh_m, sh_r;
    int wrp = threadIdx.x >> 5, nl = threadIdx.x & 31;
    if (nl == 0) { red_s[wrp] = s; red_q[wrp] = ss; }
    __syncthreads();
    if (threadIdx.x == 0) {
        float S = 0.f, Q = 0.f;
        for (int i = 0; i < 8; i++) { S += red_s[i]; Q += red_q[i]; }
        float m = S / (float)Dd;
        sh_m = m;
        sh_r = rsqrtf(Q / (float)Dd - m * m + EPSf);
    }
    __syncthreads();
    float m = sh_m, r = sh_r;
    for (int c = threadIdx.x; c < Dd; c += blockDim.x)
        out[(size_t)row * Dd + c] = (x[c] - m) * r * w[c] + bia[c];
}

// ======================= launch =============================================
extern "C" void kernel_launch(void* const* d_in, const int* in_sizes, int n_in,
                              void* d_out, int out_size) {
    const float* context  = (const float*)d_in[0];
    const float* latents  = (const float*)d_in[1];
    const float* ctx_ln_w = (const float*)d_in[2];
    const float* ctx_ln_b = (const float*)d_in[3];
    const float* lat_ln_w = (const float*)d_in[4];
    const float* lat_ln_b = (const float*)d_in[5];
    const float* q_ln_w   = (const float*)d_in[6];
    const float* q_ln_b   = (const float*)d_in[7];
    const float* k_ln_w   = (const float*)d_in[8];
    const float* k_ln_b   = (const float*)d_in[9];
    const float* wq       = (const float*)d_in[10];
    const float* wk       = (const float*)d_in[11];
    const float* wv       = (const float*)d_in[12];
    const float* wo       = (const float*)d_in[13];
    const float* mlp_ln_w = (const float*)d_in[14];
    const float* mlp_ln_b = (const float*)d_in[15];
    const float* w_fc     = (const float*)d_in[16];
    const float* w_cproj  = (const float*)d_in[17];
    const float* fin_w    = (const float*)d_in[18];
    const float* fin_b    = (const float*)d_in[19];
    (void)in_sizes; (void)n_in; (void)out_size;

    float *pCm, *pCr, *pLat, *pLm, *pLr, *pQ, *pK, *pV, *pAttn, *pMlp, *pBias;
    bf16 *pWhi, *pWlo, *pAhi, *pAlo, *pLhi, *pLlo;
    cudaGetSymbolAddress((void**)&pCm,   g_ctx_mean);
    cudaGetSymbolAddress((void**)&pCr,   g_ctx_rstd);
    cudaGetSymbolAddress((void**)&pLat,  g_lat);
    cudaGetSymbolAddress((void**)&pLm,   g_lat_mean);
    cudaGetSymbolAddress((void**)&pLr,   g_lat_rstd);
    cudaGetSymbolAddress((void**)&pQ,    g_Q);
    cudaGetSymbolAddress((void**)&pK,    g_K);
    cudaGetSymbolAddress((void**)&pV,    g_V);
    cudaGetSymbolAddress((void**)&pAttn, g_attn);
    cudaGetSymbolAddress((void**)&pMlp,  g_mlp);
    cudaGetSymbolAddress((void**)&pBias, g_bias);
    cudaGetSymbolAddress((void**)&pWhi,  g_Whi);
    cudaGetSymbolAddress((void**)&pWlo,  g_Wlo);
    cudaGetSymbolAddress((void**)&pAhi,  g_Ahi);
    cudaGetSymbolAddress((void**)&pAlo,  g_Alo);
    cudaGetSymbolAddress((void**)&pLhi,  g_Lhi);
    cudaGetSymbolAddress((void**)&pLlo,  g_Llo);

    cudaFuncSetAttribute(attention_kernel,
                         cudaFuncAttributeMaxDynamicSharedMemorySize, ATT_SMEM);
    cudaFuncSetAttribute(gemm_cp_kernel,
                         cudaFuncAttributeMaxDynamicSharedMemorySize, GM_SMEM);

    // ---- one-time packing: weights (transpose + split, ctx-gamma fold) ----
    dim3 tb(32, 8);
    for (int i = 0; i < DEPTHn; i++) {
        size_t wb = (size_t)i * LAYER_W;
        const float* gci = ctx_ln_w + i * Dd;
        const float* bci = ctx_ln_b + i * Dd;
        wt_pack2_kernel<<<dim3(HHD / 32, Dd / 32), tb>>>(
            wq + (size_t)i * Dd * HHD, nullptr, pWhi + wb + OFF_WQ,
            pWlo + wb + OFF_WQ, Dd, HHD);
        wt_pack2_kernel<<<dim3(HHD / 32, Dd / 32), tb>>>(
            wk + (size_t)i * Dd * HHD, nullptr, pWhi + wb + OFF_WK,
            pWlo + wb + OFF_WK, Dd, HHD);
        wt_pack2_kernel<<<dim3(HHD / 32, Dd / 32), tb>>>(
            wv + (size_t)i * Dd * HHD, nullptr, pWhi + wb + OFF_WV,
            pWlo + wb + OFF_WV, Dd, HHD);
        wt_pack2_kernel<<<dim3(HHD / 32, Dd / 32), tb>>>(
            wk + (size_t)i * Dd * HHD, gci, pWhi + wb + OFF_WKF,
            pWlo + wb + OFF_WKF, Dd, HHD);
        wt_pack2_kernel<<<dim3(HHD / 32, Dd / 32), tb>>>(
            wv + (size_t)i * Dd * HHD, gci, pWhi + wb + OFF_WVF,
            pWlo + wb + OFF_WVF, Dd, HHD);
        wt_pack2_kernel<<<dim3(Dd / 32, HHD / 32), tb>>>(
            wo + (size_t)i * HHD * Dd, nullptr, pWhi + wb + OFF_WO,
            pWlo + wb + OFF_WO, HHD, Dd);
        wt_pack2_kernel<<<dim3(FFf / 32, Dd / 32), tb>>>(
            w_fc + (size_t)i * Dd * FFf, nullptr, pWhi + wb + OFF_WFC,
            pWlo + wb + OFF_WFC, Dd, FFf);
        wt_pack2_kernel<<<dim3(Dd / 32, FFf / 32), tb>>>(
            w_cproj + (size_t)i * FFf * Dd, nullptr, pWhi + wb + OFF_WCP,
            pWlo + wb + OFF_WCP, FFf, Dd);
        bias_kernel<<<HHD / 256, 256>>>(bci, wk + (size_t)i * Dd * HHD,
                                        pBias + (i * 2 + 0) * HHD, Dd, HHD);
        bias_kernel<<<HHD / 256, 256>>>(bci, wv + (size_t)i * Dd * HHD,
                                        pBias + (i * 2 + 1) * HHD, Dd, HHD);
    }

    // ---- context: stats + normalize + pack ONCE ----
    rowstats_kernel<<<Bb * Ss, 256>>>(context, pCm, pCr, Dd);
    pack2_kernel<<<Bb * Ss, 256>>>(context, pCm, pCr, nullptr, nullptr,
                                   pAhi, pAlo, Dd);
    broadcast_lat_kernel<<<(Bb * NLl * Dd + 255) / 256, 256>>>(latents);

    const int ML = Bb * NLl;   // 2048
    const int MC = Bb * Ss;    // 65536

    for (int i = 0; i < DEPTHn; i++) {
        size_t wb = (size_t)i * LAYER_W;
        const float* llw = lat_ln_w + i * Dd, *llb = lat_ln_b + i * Dd;
        const float* mlw = mlp_ln_w + i * Dd, *mlb = mlp_ln_b + i * Dd;
        const float* qlw = q_ln_w + i * HDd, *qlb = q_ln_b + i * HDd;
        const float* klw = k_ln_w + i * HDd, *klb = k_ln_b + i * HDd;

        // latent QKV
        rowstats_kernel<<<ML, 256>>>(pLat, pLm, pLr, Dd);
        pack2_kernel<<<ML, 256>>>(pLat, pLm, pLr, llw, llb, pLhi, pLlo, Dd);
        gemm_cp_kernel<<<dim3(HHD / 256, ML / 128), 256, GM_SMEM>>>(
            pLhi, pLlo, pWhi + wb + OFF_WQ, pWlo + wb + OFF_WQ,
            pQ, Dd, HHD, HHD, nullptr, nullptr, 0, 0);
        gemm_cp_kernel<<<dim3(HHD / 256, ML / 128), 256, GM_SMEM>>>(
            pLhi, pLlo, pWhi + wb + OFF_WK, pWlo + wb + OFF_WK,
            pK, Dd, HHD, HHD, nullptr, nullptr, 0, 1);
        gemm_cp_kernel<<<dim3(HHD / 256, ML / 128), 256, GM_SMEM>>>(
            pLhi, pLlo, pWhi + wb + OFF_WV, pWlo + wb + OFF_WV,
            pV, Dd, HHD, HHD, nullptr, nullptr, 0, 1);

        // context KV (folded weights + bias; ctx packed once outside loop)
        gemm_cp_kernel<<<dim3(HHD / 256, MC / 128), 256, GM_SMEM>>>(
            pAhi, pAlo, pWhi + wb + OFF_WKF, pWlo + wb + OFF_WKF,
            pK, Dd, HHD, HHD, pBias + (i * 2 + 0) * HHD, nullptr, 0, 2);
        gemm_cp_kernel<<<dim3(HHD / 256, MC / 128), 256, GM_SMEM>>>(
            pAhi, pAlo, pWhi + wb + OFF_WVF, pWlo + wb + OFF_WVF,
            pV, Dd, HHD, HHD, pBias + (i * 2 + 1) * HHD, nullptr, 0, 2);

        attention_kernel<<<Bb * Hh, 256, ATT_SMEM>>>(pQ, pK, pV, pAttn,
                                                     qlw, qlb, klw, klb);

        // wo projection + residual
        pack2_kernel<<<ML, 256>>>(pAttn, nullptr, nullptr, nullptr, nullptr,
                                  pLhi, pLlo, HHD);
        gemm_cp_kernel<<<dim3(Dd / 256, ML / 128), 256, GM_SMEM>>>(
            pLhi, pLlo, pWhi + wb + OFF_WO, pWlo + wb + OFF_WO,
            pLat, HHD, Dd, Dd, nullptr, pLat, 0, 0);

        // MLP
        rowstats_kernel<<<ML, 256>>>(pLat, pLm, pLr, Dd);
        pack2_kernel<<<ML, 256>>>(pLat, pLm, pLr, mlw, mlb, pLhi, pLlo, Dd);
        gemm_cp_kernel<<<dim3(FFf / 256, ML / 128), 256, GM_SMEM>>>(
            pLhi, pLlo, pWhi + wb + OFF_WFC, pWlo + wb + OFF_WFC,
            pMlp, Dd, FFf, FFf, nullptr, nullptr, 1, 0);
        pack2_kernel<<<ML, 256>>>(pMlp, nullptr, nullptr, nullptr, nullptr,
                                  pLhi, pLlo, FFf);
        gemm_cp_kernel<<<dim3(Dd / 256, ML / 128), 256, GM_SMEM>>>(
            pLhi, pLlo, pWhi + wb + OFF_WCP, pWlo + wb + OFF_WCP,
            pLat, FFf, Dd, Dd, nullptr, pLat, 0, 0);
    }

    final_ln_kernel<<<Bb * NLl, 256>>>((float*)d_out, fin_w, fin_b);
}

// round 6
// speedup vs baseline: 4.2988x; 1.9089x over previous
#include <cuda_runtime.h>
#include <cuda_fp16.h>
#include <cstdint>
#include <math.h>

#define Bb     32
#define Ss     2048
#define Dd     1280
#define Hh     16
#define HDd    96
#define NLl    64
#define DEPTHn 3
#define FFf    5120
#define SKV    (Ss + NLl)      /* 2112 */
#define HHD    (Hh * HDd)      /* 1536 */
#define EPSf   1e-5f

// ======================= scratch (device globals) ===========================
__device__ float g_ctx_mean[Bb * Ss];
__device__ float g_ctx_rstd[Bb * Ss];
__device__ float g_lat[Bb * NLl * Dd];
__device__ float g_lat_mean[Bb * NLl];
__device__ float g_lat_rstd[Bb * NLl];
__device__ float g_Q[Bb * NLl * HHD];
__device__ float g_K[(size_t)Bb * SKV * HHD];
__device__ float g_V[(size_t)Bb * SKV * HHD];
__device__ float g_attn[Bb * NLl * HHD];
__device__ float g_mlp[(size_t)Bb * NLl * FFf];
__device__ float g_bias[DEPTHn * 2 * HHD];

// fp16 weight planes: [N][K]
#define SZ1      1966080u                 /* 1536*1280 */
#define SZFC     6553600u                 /* 5120*1280 */
#define OFF_WQ   0u
#define OFF_WK   (SZ1)
#define OFF_WV   (2u * SZ1)
#define OFF_WKF  (3u * SZ1)               /* gamma-folded, ctx */
#define OFF_WVF  (4u * SZ1)
#define OFF_WO   (5u * SZ1)
#define OFF_WFC  (6u * SZ1)
#define OFF_WCP  (6u * SZ1 + SZFC)
#define LAYER_W  (6u * SZ1 + 2u * SZFC)
__device__ __half g_W[(size_t)DEPTHn * LAYER_W];
__device__ __half g_Actx[(size_t)Bb * Ss * Dd];   // ctx, packed ONCE
__device__ __half g_Alat[(size_t)Bb * NLl * FFf]; // latent-side scratch

// ======================= small prep kernels =================================
__global__ void rowstats_kernel(const float* __restrict__ X,
                                float* __restrict__ mean,
                                float* __restrict__ rstd, int ncols) {
    int row = blockIdx.x;
    const float* x = X + (size_t)row * ncols;
    float s = 0.f, ss = 0.f;
    for (int c = threadIdx.x; c < ncols; c += blockDim.x) {
        float v = x[c]; s += v; ss += v * v;
    }
#pragma unroll
    for (int o = 16; o > 0; o >>= 1) {
        s  += __shfl_xor_sync(0xffffffffu, s, o);
        ss += __shfl_xor_sync(0xffffffffu, ss, o);
    }
    __shared__ float red_s[8], red_q[8];
    int w = threadIdx.x >> 5, nl = threadIdx.x & 31;
    if (nl == 0) { red_s[w] = s; red_q[w] = ss; }
    __syncthreads();
    if (threadIdx.x == 0) {
        float S = 0.f, Q = 0.f;
        int nw = blockDim.x >> 5;
        for (int i = 0; i < nw; i++) { S += red_s[i]; Q += red_q[i]; }
        float m = S / (float)ncols;
        mean[row] = m;
        rstd[row] = rsqrtf(Q / (float)ncols - m * m + EPSf);
    }
}

__global__ void broadcast_lat_kernel(const float* __restrict__ latents) {
    int i = blockIdx.x * blockDim.x + threadIdx.x;
    const int per = NLl * Dd;
    if (i < Bb * per) g_lat[i] = latents[i % per];
}

// (optional stats)(optional affine) -> fp16 plane
__global__ void packh_kernel(const float* __restrict__ X,
                             const float* __restrict__ mean,
                             const float* __restrict__ rstd,
                             const float* __restrict__ lnw,
                             const float* __restrict__ lnb,
                             __half* __restrict__ out, int ncols) {
    int row = blockIdx.x;
    const float* x = X + (size_t)row * ncols;
    __half* o = out + (size_t)row * ncols;
    float mu = 0.f, rs = 1.f;
    if (mean) { mu = mean[row]; rs = rstd[row]; }
    for (int c = threadIdx.x; c < ncols; c += blockDim.x) {
        float v = x[c];
        if (mean) v = (v - mu) * rs;
        if (lnw)  v = v * lnw[c] + lnb[c];
        o[c] = __float2half_rn(v);
    }
}

// transpose + optional gamma fold: W[K,N] fp32 -> out[N,K] fp16
__global__ void wt_packh_kernel(const float* __restrict__ W,
                                const float* __restrict__ gamma,
                                __half* __restrict__ out, int K, int N) {
    __shared__ float tile[32][33];
    int n0 = blockIdx.x << 5, k0 = blockIdx.y << 5;
    for (int i = threadIdx.y; i < 32; i += 8)
        tile[i][threadIdx.x] = W[(size_t)(k0 + i) * N + n0 + threadIdx.x];
    __syncthreads();
    float g = gamma ? gamma[k0 + threadIdx.x] : 1.f;
    for (int i = threadIdx.y; i < 32; i += 8)
        out[(size_t)(n0 + i) * K + k0 + threadIdx.x] =
            __float2half_rn(tile[threadIdx.x][i] * g);
}

// bias[n] = sum_k beta[k] * W[k*N + n]   (parallel over k-groups)
__global__ void bias_kernel(const float* __restrict__ beta,
                            const float* __restrict__ W,
                            float* __restrict__ out, int K, int N) {
    __shared__ float red[16][17];
    int n = blockIdx.x * 16 + (threadIdx.x & 15);
    int kg = threadIdx.x >> 4;           // 16 k-groups
    float s = 0.f;
    for (int k = kg; k < K; k += 16) s += beta[k] * W[(size_t)k * N + n];
    red[kg][threadIdx.x & 15] = s;
    __syncthreads();
    if (kg == 0) {
        float t = 0.f;
#pragma unroll
        for (int i = 0; i < 16; i++) t += red[i][threadIdx.x & 15];
        out[n] = t;
    }
}

// ======================= fp16 HMMA GEMM with cp.async =======================
// C[crow(r), n] = A[r,:] @ Wt[n,:]   single-term fp16, fp32 accum
// CTA tile 128x256, 8 warps (2m x 4n), warp tile 64x64, K chunk 64, 2 stages.
#define PL_A     0
#define PL_B     16384
#define ST_BYTES 49152
#define GM_SMEM  (2 * ST_BYTES)

#define CP_ASYNC16(dst, src) \
    asm volatile("cp.async.cg.shared.global [%0], [%1], 16;" \
                 :: "r"(dst), "l"(src))
#define CP_COMMIT() asm volatile("cp.async.commit_group;" ::: "memory")
#define CP_WAIT0()  asm volatile("cp.async.wait_group 0;" ::: "memory")
#define CP_WAIT1()  asm volatile("cp.async.wait_group 1;" ::: "memory")

#define LDSM4(r0, r1, r2, r3, addr)                                          \
    asm volatile("ldmatrix.sync.aligned.m8n8.x4.shared.b16 {%0,%1,%2,%3}, [%4];" \
        : "=r"(r0), "=r"(r1), "=r"(r2), "=r"(r3) : "r"(addr))

#define MMAH(d, a, b0, b1)                                                   \
    asm volatile("mma.sync.aligned.m16n8k16.row.col.f32.f16.f16.f32 "        \
        "{%0,%1,%2,%3}, {%4,%5,%6,%7}, {%8,%9}, {%0,%1,%2,%3};"              \
        : "+f"((d)[0]), "+f"((d)[1]), "+f"((d)[2]), "+f"((d)[3])             \
        : "r"((a)[0]), "r"((a)[1]), "r"((a)[2]), "r"((a)[3]),                \
          "r"(b0), "r"(b1))

__device__ __forceinline__ uint32_t smem_u32(const void* p) {
    uint32_t a;
    asm("{ .reg .u64 t; cvta.to.shared.u64 t, %1; cvt.u32.u64 %0, t; }"
        : "=r"(a) : "l"(p));
    return a;
}
__device__ __forceinline__ uint32_t swz(uint32_t off) {
    return off ^ ((off >> 3) & 0x70);
}

__device__ __forceinline__ void issue_chunk(
    uint32_t st, const __half* __restrict__ A, const __half* __restrict__ B,
    int K, int c, int tid) {
    // A: 128 rows x 128B (64 fp16), 1024 x16B total -> 4 per thread
#pragma unroll
    for (int i = 0; i < 4; i++) {
        int flat = i * 256 + tid;
        int row = flat >> 3, col16 = flat & 7;
        uint32_t off = swz((uint32_t)(row * 128 + col16 * 16));
        CP_ASYNC16(st + PL_A + off, A + (size_t)row * K + (size_t)c * 64 + col16 * 8);
    }
    // B: 256 rows -> 8 per thread
#pragma unroll
    for (int i = 0; i < 8; i++) {
        int flat = i * 256 + tid;
        int row = flat >> 3, col16 = flat & 7;
        uint32_t off = swz((uint32_t)(row * 128 + col16 * 16));
        CP_ASYNC16(st + PL_B + off, B + (size_t)row * K + (size_t)c * 64 + col16 * 8);
    }
}

__global__ __launch_bounds__(256, 1) void gemm_h_kernel(
    const __half* __restrict__ Ain, const __half* __restrict__ Win,
    float* __restrict__ C, int K, int N, int ldc,
    const float* __restrict__ bias, const float* __restrict__ resid,
    int relu, int remap) {
    extern __shared__ char sm[];
    uint32_t smb = smem_u32(sm);
    int tid = threadIdx.x, wid = tid >> 5, lane = tid & 31;
    int warp_m = wid >> 2, warp_n = wid & 3;

    int m0 = blockIdx.y << 7, n0 = blockIdx.x << 8;
    const __half* A = Ain + (size_t)m0 * K;
    const __half* B = Win + (size_t)n0 * K;
    int NC = K >> 6;

    float acc[4][8][4];
#pragma unroll
    for (int i = 0; i < 4; i++)
#pragma unroll
        for (int j = 0; j < 8; j++)
#pragma unroll
            for (int k = 0; k < 4; k++) acc[i][j][k] = 0.f;

    issue_chunk(smb, A, B, K, 0, tid);
    CP_COMMIT();
    issue_chunk(smb + ST_BYTES, A, B, K, 1, tid);
    CP_COMMIT();

    int lrow = lane & 15, lhalf = lane >> 4;
    for (int c = 0; c < NC; c++) {
        if (c + 1 < NC) { CP_WAIT1(); } else { CP_WAIT0(); }
        __syncthreads();
        uint32_t st = smb + (uint32_t)((c & 1) * ST_BYTES);
#pragma unroll
        for (int kq = 0; kq < 4; kq++) {
            int ch = kq * 2 + lhalf;
            uint32_t ah[4][4];
#pragma unroll
            for (int mt = 0; mt < 4; mt++) {
                uint32_t ro = swz((uint32_t)((warp_m * 64 + mt * 16 + lrow) * 128 + ch * 16));
                LDSM4(ah[mt][0], ah[mt][1], ah[mt][2], ah[mt][3], st + PL_A + ro);
            }
#pragma unroll
            for (int nt2 = 0; nt2 < 4; nt2++) {
                uint32_t ro = swz((uint32_t)((warp_n * 64 + nt2 * 16 + lrow) * 128 + ch * 16));
                uint32_t r0, r1, r2, r3;
                LDSM4(r0, r1, r2, r3, st + PL_B + ro);
#pragma unroll
                for (int mt = 0; mt < 4; mt++) {
                    MMAH(acc[mt][nt2 * 2],     ah[mt], r0, r2);
                    MMAH(acc[mt][nt2 * 2 + 1], ah[mt], r1, r3);
                }
            }
        }
        __syncthreads();
        if (c + 2 < NC) {
            issue_chunk(smb + (uint32_t)((c & 1) * ST_BYTES), A, B, K, c + 2, tid);
            CP_COMMIT();
        }
    }

    // epilogue
    int qrow = lane >> 2, qcol = (lane & 3) * 2;
#pragma unroll
    for (int mt = 0; mt < 4; mt++) {
#pragma unroll
        for (int half = 0; half < 2; half++) {
            int r = m0 + warp_m * 64 + mt * 16 + half * 8 + qrow;
            int crow;
            if (remap == 1)      crow = (r >> 6)  * SKV + Ss + (r & 63);
            else if (remap == 2) crow = (r >> 11) * SKV + (r & 2047);
            else                 crow = r;
            int cb = n0 + warp_n * 64;
            float* cp = C + (size_t)crow * ldc + cb;
            const float* rp = resid ? resid + (size_t)r * N + cb : nullptr;
            const float* bp = bias ? bias + cb : nullptr;
#pragma unroll
            for (int nt = 0; nt < 8; nt++) {
                float v0 = acc[mt][nt][half * 2];
                float v1 = acc[mt][nt][half * 2 + 1];
                int col = nt * 8 + qcol;
                if (bp) { v0 += bp[col]; v1 += bp[col + 1]; }
                if (rp) { v0 += rp[col]; v1 += rp[col + 1]; }
                if (relu) { v0 = fmaxf(v0, 0.f); v1 = fmaxf(v1, 0.f); }
                *(float2*)(cp + col) = make_float2(v0, v1);
            }
        }
    }
}

// ======================= fused attention ====================================
#define ATT_QS   0
#define ATT_KS   (64 * 100)
#define ATT_VS   (ATT_KS + 32 * 100)
#define ATT_PS   (ATT_VS + 32 * 100)
#define ATT_SMEM ((ATT_PS + 64 * 33) * 4)

__global__ __launch_bounds__(256) void attention_kernel(
    const float* __restrict__ Q, const float* __restrict__ Kb,
    const float* __restrict__ Vb, float* __restrict__ O,
    const float* __restrict__ qw, const float* __restrict__ qb,
    const float* __restrict__ kw, const float* __restrict__ kb) {
    extern __shared__ float smf[];
    float* qs = smf + ATT_QS;
    float* ks = smf + ATT_KS;
    float* vs = smf + ATT_VS;
    float* ps = smf + ATT_PS;

    int tid = threadIdx.x;
    int bh = blockIdx.x;
    int b = bh >> 4, h = bh & 15;
    const float qscale = rsqrtf((float)HDd);

    int myrow = tid >> 2, mypart = tid & 3;
    int qg = tid >> 4, kg = tid & 15;

    {
        const float* qp = Q + (size_t)(b * NLl + myrow) * HHD + h * HDd + mypart * 24;
        float v[24];
        float s = 0.f, ss = 0.f;
#pragma unroll
        for (int i = 0; i < 24; i += 4) {
            float4 t = *(const float4*)(qp + i);
            v[i] = t.x; v[i+1] = t.y; v[i+2] = t.z; v[i+3] = t.w;
        }
#pragma unroll
        for (int i = 0; i < 24; i++) { s += v[i]; ss += v[i] * v[i]; }
#pragma unroll
        for (int o = 1; o < 4; o <<= 1) {
            s  += __shfl_xor_sync(0xffffffffu, s, o);
            ss += __shfl_xor_sync(0xffffffffu, ss, o);
        }
        float mmu = s * (1.f / 96.f);
        float rsd = rsqrtf(ss * (1.f / 96.f) - mmu * mmu + EPSf);
#pragma unroll
        for (int i = 0; i < 24; i++) {
            int c = mypart * 24 + i;
            qs[myrow * 100 + c] = ((v[i] - mmu) * rsd * qw[c] + qb[c]) * qscale;
        }
    }
    __syncthreads();

    float m_run = -INFINITY, l_run = 0.f;
    float oacc[24];
#pragma unroll
    for (int i = 0; i < 24; i++) oacc[i] = 0.f;

    for (int t = 0; t < SKV / 32; t++) {
        {
            int j = tid >> 3, p8 = tid & 7;
            int kidx = t * 32 + j;
            const float* kp = Kb + ((size_t)b * SKV + kidx) * HHD + h * HDd + p8 * 12;
            const float* vp = Vb + ((size_t)b * SKV + kidx) * HHD + h * HDd + p8 * 12;
            float kv[12];
            float s = 0.f, ss = 0.f;
#pragma unroll
            for (int i = 0; i < 12; i += 4) {
                float4 tt = *(const float4*)(kp + i);
                kv[i] = tt.x; kv[i+1] = tt.y; kv[i+2] = tt.z; kv[i+3] = tt.w;
            }
#pragma unroll
            for (int i = 0; i < 12; i++) { s += kv[i]; ss += kv[i] * kv[i]; }
#pragma unroll
            for (int o = 1; o < 8; o <<= 1) {
                s  += __shfl_xor_sync(0xffffffffu, s, o);
                ss += __shfl_xor_sync(0xffffffffu, ss, o);
            }
            float mmu = s * (1.f / 96.f);
            float rsd = rsqrtf(ss * (1.f / 96.f) - mmu * mmu + EPSf);
#pragma unroll
            for (int i = 0; i < 12; i++) {
                int c = p8 * 12 + i;
                ks[j * 100 + c] = (kv[i] - mmu) * rsd * kw[c] + kb[c];
            }
#pragma unroll
            for (int i = 0; i < 12; i += 4)
                *(float4*)&vs[j * 100 + p8 * 12 + i] = *(const float4*)(vp + i);
        }
        __syncthreads();

        {
            float sc[4][2];
#pragma unroll
            for (int i = 0; i < 4; i++) { sc[i][0] = 0.f; sc[i][1] = 0.f; }
            int q0 = qg << 2, k0 = kg << 1;
#pragma unroll
            for (int d = 0; d < 96; d += 4) {
                float4 k0v = *(const float4*)&ks[k0 * 100 + d];
                float4 k1v = *(const float4*)&ks[(k0 + 1) * 100 + d];
#pragma unroll
                for (int i = 0; i < 4; i++) {
                    float4 qv = *(const float4*)&qs[(q0 + i) * 100 + d];
                    sc[i][0] += qv.x*k0v.x + qv.y*k0v.y + qv.z*k0v.z + qv.w*k0v.w;
                    sc[i][1] += qv.x*k1v.x + qv.y*k1v.y + qv.z*k1v.z + qv.w*k1v.w;
                }
            }
#pragma unroll
            for (int i = 0; i < 4; i++) {
                ps[(q0 + i) * 33 + k0]     = sc[i][0];
                ps[(q0 + i) * 33 + k0 + 1] = sc[i][1];
            }
        }
        __syncwarp();

        {
            float p8v[8];
            float mx = -INFINITY;
#pragma unroll
            for (int i = 0; i < 8; i++) {
                p8v[i] = ps[myrow * 33 + mypart * 8 + i];
                mx = fmaxf(mx, p8v[i]);
            }
#pragma unroll
            for (int o = 1; o < 4; o <<= 1)
                mx = fmaxf(mx, __shfl_xor_sync(0xffffffffu, mx, o));
            float mnew = fmaxf(m_run, mx);
            float corr = __expf(m_run - mnew);
            float psum = 0.f;
#pragma unroll
            for (int i = 0; i < 8; i++) {
                p8v[i] = __expf(p8v[i] - mnew);
                psum += p8v[i];
                ps[myrow * 33 + mypart * 8 + i] = p8v[i];
            }
#pragma unroll
            for (int o = 1; o < 4; o <<= 1)
                psum += __shfl_xor_sync(0xffffffffu, psum, o);
            l_run = l_run * corr + psum;
            m_run = mnew;
#pragma unroll
            for (int i = 0; i < 24; i++) oacc[i] *= corr;
            __syncwarp();
#pragma unroll 4
            for (int j = 0; j < 32; j++) {
                float p = ps[myrow * 33 + j];
                const float4* vr = (const float4*)&vs[j * 100 + mypart * 24];
#pragma unroll
                for (int i4 = 0; i4 < 6; i4++) {
                    float4 v = vr[i4];
                    oacc[i4*4+0] += p * v.x;
                    oacc[i4*4+1] += p * v.y;
                    oacc[i4*4+2] += p * v.z;
                    oacc[i4*4+3] += p * v.w;
                }
            }
        }
        __syncthreads();
    }

    {
        float inv = 1.f / l_run;
        float* op = O + (size_t)(b * NLl + myrow) * HHD + h * HDd + mypart * 24;
#pragma unroll
        for (int i = 0; i < 24; i++) op[i] = oacc[i] * inv;
    }
}

// ======================= final layer norm -> d_out ==========================
__global__ void final_ln_kernel(float* __restrict__ out,
                                const float* __restrict__ w,
                                const float* __restrict__ bia) {
    int row = blockIdx.x;
    const float* x = g_lat + (size_t)row * Dd;
    float s = 0.f, ss = 0.f;
    for (int c = threadIdx.x; c < Dd; c += blockDim.x) {
        float v = x[c]; s += v; ss += v * v;
    }
#pragma unroll
    for (int o = 16; o > 0; o >>= 1) {
        s  += __shfl_xor_sync(0xffffffffu, s, o);
        ss += __shfl_xor_sync(0xffffffffu, ss, o);
    }
    __shared__ float red_s[8], red_q[8];
    __shared__ float sh_m, sh_r;
    int wrp = threadIdx.x >> 5, nl = threadIdx.x & 31;
    if (nl == 0) { red_s[wrp] = s; red_q[wrp] = ss; }
    __syncthreads();
    if (threadIdx.x == 0) {
        float S = 0.f, Q = 0.f;
        for (int i = 0; i < 8; i++) { S += red_s[i]; Q += red_q[i]; }
        float m = S / (float)Dd;
        sh_m = m;
        sh_r = rsqrtf(Q / (float)Dd - m * m + EPSf);
    }
    __syncthreads();
    float m = sh_m, r = sh_r;
    for (int c = threadIdx.x; c < Dd; c += blockDim.x)
        out[(size_t)row * Dd + c] = (x[c] - m) * r * w[c] + bia[c];
}

// ======================= launch =============================================
extern "C" void kernel_launch(void* const* d_in, const int* in_sizes, int n_in,
                              void* d_out, int out_size) {
    const float* context  = (const float*)d_in[0];
    const float* latents  = (const float*)d_in[1];
    const float* ctx_ln_w = (const float*)d_in[2];
    const float* ctx_ln_b = (const float*)d_in[3];
    const float* lat_ln_w = (const float*)d_in[4];
    const float* lat_ln_b = (const float*)d_in[5];
    const float* q_ln_w   = (const float*)d_in[6];
    const float* q_ln_b   = (const float*)d_in[7];
    const float* k_ln_w   = (const float*)d_in[8];
    const float* k_ln_b   = (const float*)d_in[9];
    const float* wq       = (const float*)d_in[10];
    const float* wk       = (const float*)d_in[11];
    const float* wv       = (const float*)d_in[12];
    const float* wo       = (const float*)d_in[13];
    const float* mlp_ln_w = (const float*)d_in[14];
    const float* mlp_ln_b = (const float*)d_in[15];
    const float* w_fc     = (const float*)d_in[16];
    const float* w_cproj  = (const float*)d_in[17];
    const float* fin_w    = (const float*)d_in[18];
    const float* fin_b    = (const float*)d_in[19];
    (void)in_sizes; (void)n_in; (void)out_size;

    float *pCm, *pCr, *pLat, *pLm, *pLr, *pQ, *pK, *pV, *pAttn, *pMlp, *pBias;
    __half *pW, *pActx, *pAlat;
    cudaGetSymbolAddress((void**)&pCm,   g_ctx_mean);
    cudaGetSymbolAddress((void**)&pCr,   g_ctx_rstd);
    cudaGetSymbolAddress((void**)&pLat,  g_lat);
    cudaGetSymbolAddress((void**)&pLm,   g_lat_mean);
    cudaGetSymbolAddress((void**)&pLr,   g_lat_rstd);
    cudaGetSymbolAddress((void**)&pQ,    g_Q);
    cudaGetSymbolAddress((void**)&pK,    g_K);
    cudaGetSymbolAddress((void**)&pV,    g_V);
    cudaGetSymbolAddress((void**)&pAttn, g_attn);
    cudaGetSymbolAddress((void**)&pMlp,  g_mlp);
    cudaGetSymbolAddress((void**)&pBias, g_bias);
    cudaGetSymbolAddress((void**)&pW,    g_W);
    cudaGetSymbolAddress((void**)&pActx, g_Actx);
    cudaGetSymbolAddress((void**)&pAlat, g_Alat);

    cudaFuncSetAttribute(attention_kernel,
                         cudaFuncAttributeMaxDynamicSharedMemorySize, ATT_SMEM);
    cudaFuncSetAttribute(gemm_h_kernel,
                         cudaFuncAttributeMaxDynamicSharedMemorySize, GM_SMEM);

    const int ML = Bb * NLl;   // 2048
    const int MC = Bb * Ss;    // 65536
    dim3 tb(32, 8);

    // ---- prologue ordered so ncu (-s 5 -c 1) captures the ctx K GEMM ----
    rowstats_kernel<<<Bb * Ss, 256>>>(context, pCm, pCr, Dd);          // #0
    packh_kernel<<<Bb * Ss, 256>>>(context, pCm, pCr, nullptr, nullptr,
                                   pActx, Dd);                         // #1
    wt_packh_kernel<<<dim3(HHD / 32, Dd / 32), tb>>>(
        wk, ctx_ln_w, pW + OFF_WKF, Dd, HHD);                          // #2
    bias_kernel<<<HHD / 16, 256>>>(ctx_ln_b, wk, pBias + 0, Dd, HHD);  // #3
    wt_packh_kernel<<<dim3(HHD / 32, Dd / 32), tb>>>(
        wv, ctx_ln_w, pW + OFF_WVF, Dd, HHD);                          // #4
    gemm_h_kernel<<<dim3(HHD / 256, MC / 128), 256, GM_SMEM>>>(        // #5 <- ncu
        pActx, pW + OFF_WKF, pK, Dd, HHD, HHD, pBias + 0, nullptr, 0, 2);
    bias_kernel<<<HHD / 16, 256>>>(ctx_ln_b, wv, pBias + HHD, Dd, HHD);
    gemm_h_kernel<<<dim3(HHD / 256, MC / 128), 256, GM_SMEM>>>(
        pActx, pW + OFF_WVF, pV, Dd, HHD, HHD, pBias + HHD, nullptr, 0, 2);

    // ---- remaining one-time weight packing ----
    for (int i = 0; i < DEPTHn; i++) {
        size_t wb = (size_t)i * LAYER_W;
        const float* gci = ctx_ln_w + i * Dd;
        const float* bci = ctx_ln_b + i * Dd;
        wt_packh_kernel<<<dim3(HHD / 32, Dd / 32), tb>>>(
            wq + (size_t)i * Dd * HHD, nullptr, pW + wb + OFF_WQ, Dd, HHD);
        wt_packh_kernel<<<dim3(HHD / 32, Dd / 32), tb>>>(
            wk + (size_t)i * Dd * HHD, nullptr, pW + wb + OFF_WK, Dd, HHD);
        wt_packh_kernel<<<dim3(HHD / 32, Dd / 32), tb>>>(
            wv + (size_t)i * Dd * HHD, nullptr, pW + wb + OFF_WV, Dd, HHD);
        if (i > 0) {
            wt_packh_kernel<<<dim3(HHD / 32, Dd / 32), tb>>>(
                wk + (size_t)i * Dd * HHD, gci, pW + wb + OFF_WKF, Dd, HHD);
            wt_packh_kernel<<<dim3(HHD / 32, Dd / 32), tb>>>(
                wv + (size_t)i * Dd * HHD, gci, pW + wb + OFF_WVF, Dd, HHD);
            bias_kernel<<<HHD / 16, 256>>>(bci, wk + (size_t)i * Dd * HHD,
                                           pBias + (i * 2 + 0) * HHD, Dd, HHD);
            bias_kernel<<<HHD / 16, 256>>>(bci, wv + (size_t)i * Dd * HHD,
                                           pBias + (i * 2 + 1) * HHD, Dd, HHD);
        }
        wt_packh_kernel<<<dim3(Dd / 32, HHD / 32), tb>>>(
            wo + (size_t)i * HHD * Dd, nullptr, pW + wb + OFF_WO, HHD, Dd);
        wt_packh_kernel<<<dim3(FFf / 32, Dd / 32), tb>>>(
            w_fc + (size_t)i * Dd * FFf, nullptr, pW + wb + OFF_WFC, Dd, FFf);
        wt_packh_kernel<<<dim3(Dd / 32, FFf / 32), tb>>>(
            w_cproj + (size_t)i * FFf * Dd, nullptr, pW + wb + OFF_WCP, FFf, Dd);
    }

    broadcast_lat_kernel<<<(Bb * NLl * Dd + 255) / 256, 256>>>(latents);

    for (int i = 0; i < DEPTHn; i++) {
        size_t wb = (size_t)i * LAYER_W;
        const float* llw = lat_ln_w + i * Dd, *llb = lat_ln_b + i * Dd;
        const float* mlw = mlp_ln_w + i * Dd, *mlb = mlp_ln_b + i * Dd;
        const float* qlw = q_ln_w + i * HDd, *qlb = q_ln_b + i * HDd;
        const float* klw = k_ln_w + i * HDd, *klb = k_ln_b + i * HDd;

        // latent QKV
        rowstats_kernel<<<ML, 256>>>(pLat, pLm, pLr, Dd);
        packh_kernel<<<ML, 256>>>(pLat, pLm, pLr, llw, llb, pAlat, Dd);
        gemm_h_kernel<<<dim3(HHD / 256, ML / 128), 256, GM_SMEM>>>(
            pAlat, pW + wb + OFF_WQ, pQ, Dd, HHD, HHD, nullptr, nullptr, 0, 0);
        gemm_h_kernel<<<dim3(HHD / 256, ML / 128), 256, GM_SMEM>>>(
            pAlat, pW + wb + OFF_WK, pK, Dd, HHD, HHD, nullptr, nullptr, 0, 1);
        gemm_h_kernel<<<dim3(HHD / 256, ML / 128), 256, GM_SMEM>>>(
            pAlat, pW + wb + OFF_WV, pV, Dd, HHD, HHD, nullptr, nullptr, 0, 1);

        // context KV (layer 0 done in prologue)
        if (i > 0) {
            gemm_h_kernel<<<dim3(HHD / 256, MC / 128), 256, GM_SMEM>>>(
                pActx, pW + wb + OFF_WKF, pK, Dd, HHD, HHD,
                pBias + (i * 2 + 0) * HHD, nullptr, 0, 2);
            gemm_h_kernel<<<dim3(HHD / 256, MC / 128), 256, GM_SMEM>>>(
                pActx, pW + wb + OFF_WVF, pV, Dd, HHD, HHD,
                pBias + (i * 2 + 1) * HHD, nullptr, 0, 2);
        }

        attention_kernel<<<Bb * Hh, 256, ATT_SMEM>>>(pQ, pK, pV, pAttn,
                                                     qlw, qlb, klw, klb);

        // wo projection + residual
        packh_kernel<<<ML, 256>>>(pAttn, nullptr, nullptr, nullptr, nullptr,
                                  pAlat, HHD);
        gemm_h_kernel<<<dim3(Dd / 256, ML / 128), 256, GM_SMEM>>>(
            pAlat, pW + wb + OFF_WO, pLat, HHD, Dd, Dd, nullptr, pLat, 0, 0);

        // MLP
        rowstats_kernel<<<ML, 256>>>(pLat, pLm, pLr, Dd);
        packh_kernel<<<ML, 256>>>(pLat, pLm, pLr, mlw, mlb, pAlat, Dd);
        gemm_h_kernel<<<dim3(FFf / 256, ML / 128), 256, GM_SMEM>>>(
            pAlat, pW + wb + OFF_WFC, pMlp, Dd, FFf, FFf, nullptr, nullptr, 1, 0);
        packh_kernel<<<ML, 256>>>(pMlp, nullptr, nullptr, nullptr, nullptr,
                                  pAlat, FFf);
        gemm_h_kernel<<<dim3(Dd / 256, ML / 128), 256, GM_SMEM>>>(
            pAlat, pW + wb + OFF_WCP, pLat, FFf, Dd, Dd, nullptr, pLat, 0, 0);
    }

    final_ln_kernel<<<Bb * NLl, 256>>>((float*)d_out, fin_w, fin_b);
}

// round 7
// speedup vs baseline: 4.3407x; 1.0097x over previous
#include <cuda_runtime.h>
#include <cuda_fp16.h>
#include <cstdint>
#include <math.h>

#define Bb     32
#define Ss     2048
#define Dd     1280
#define Hh     16
#define HDd    96
#define NLl    64
#define DEPTHn 3
#define FFf    5120
#define SKV    (Ss + NLl)      /* 2112 */
#define HHD    (Hh * HDd)      /* 1536 */
#define EPSf   1e-5f

// ======================= scratch (device globals) ===========================
__device__ float g_lat[Bb * NLl * Dd];
__device__ float g_bias[DEPTHn * 2 * HHD];
__device__ __half g_Qh[Bb * NLl * HHD];
__device__ __half g_K[(size_t)Bb * SKV * HHD];
__device__ __half g_V[(size_t)Bb * SKV * HHD];
__device__ __half g_attnH[Bb * NLl * HHD];
__device__ __half g_Amlp[(size_t)Bb * NLl * FFf];

#define SZ1      1966080u                 /* 1536*1280 */
#define SZFC     6553600u                 /* 5120*1280 */
#define OFF_WQ   0u
#define OFF_WK   (SZ1)
#define OFF_WV   (2u * SZ1)
#define OFF_WKF  (3u * SZ1)               /* gamma-folded, ctx */
#define OFF_WVF  (4u * SZ1)
#define OFF_WO   (5u * SZ1)
#define OFF_WFC  (6u * SZ1)
#define OFF_WCP  (6u * SZ1 + SZFC)
#define LAYER_W  (6u * SZ1 + 2u * SZFC)
__device__ __half g_W[(size_t)DEPTHn * LAYER_W];
__device__ __half g_Actx[(size_t)Bb * Ss * Dd];   // ctx, packed ONCE
__device__ __half g_Alat[Bb * NLl * Dd];          // latent LN pack

// ======================= prep kernels ========================================
// fused: per-row stats + normalize + optional affine -> fp16
__global__ void packln_kernel(const float* __restrict__ X,
                              const float* __restrict__ lnw,
                              const float* __restrict__ lnb,
                              __half* __restrict__ out, int ncols) {
    int row = blockIdx.x;
    const float* x = X + (size_t)row * ncols;
    __half* o = out + (size_t)row * ncols;
    float v[8];
    int nv = 0;
    float s = 0.f, ss = 0.f;
    for (int c = threadIdx.x; c < ncols; c += blockDim.x) {
        float t = x[c];
        v[nv++] = t;
        s += t; ss += t * t;
    }
#pragma unroll
    for (int o2 = 16; o2 > 0; o2 >>= 1) {
        s  += __shfl_xor_sync(0xffffffffu, s, o2);
        ss += __shfl_xor_sync(0xffffffffu, ss, o2);
    }
    __shared__ float red_s[8], red_q[8];
    __shared__ float sh_m, sh_r;
    int w = threadIdx.x >> 5, nl = threadIdx.x & 31;
    if (nl == 0) { red_s[w] = s; red_q[w] = ss; }
    __syncthreads();
    if (threadIdx.x == 0) {
        float S = 0.f, Q = 0.f;
        int nw = blockDim.x >> 5;
        for (int i = 0; i < nw; i++) { S += red_s[i]; Q += red_q[i]; }
        float m = S / (float)ncols;
        sh_m = m;
        sh_r = rsqrtf(Q / (float)ncols - m * m + EPSf);
    }
    __syncthreads();
    float mu = sh_m, rs = sh_r;
    nv = 0;
    for (int c = threadIdx.x; c < ncols; c += blockDim.x) {
        float t = (v[nv++] - mu) * rs;
        if (lnw) t = t * lnw[c] + lnb[c];
        o[c] = __float2half_rn(t);
    }
}

__global__ void broadcast_lat_kernel(const float* __restrict__ latents) {
    int i = blockIdx.x * blockDim.x + threadIdx.x;
    const int per = NLl * Dd;
    if (i < Bb * per) g_lat[i] = latents[i % per];
}

// transpose + optional gamma fold: W[K,N] fp32 -> out[N,K] fp16
__global__ void wt_packh_kernel(const float* __restrict__ W,
                                const float* __restrict__ gamma,
                                __half* __restrict__ out, int K, int N) {
    __shared__ float tile[32][33];
    int n0 = blockIdx.x << 5, k0 = blockIdx.y << 5;
    for (int i = threadIdx.y; i < 32; i += 8)
        tile[i][threadIdx.x] = W[(size_t)(k0 + i) * N + n0 + threadIdx.x];
    __syncthreads();
    float g = gamma ? gamma[k0 + threadIdx.x] : 1.f;
    for (int i = threadIdx.y; i < 32; i += 8)
        out[(size_t)(n0 + i) * K + k0 + threadIdx.x] =
            __float2half_rn(tile[threadIdx.x][i] * g);
}

// bias[n] = sum_k beta[k] * W[k*N + n]
__global__ void bias_kernel(const float* __restrict__ beta,
                            const float* __restrict__ W,
                            float* __restrict__ out, int K, int N) {
    __shared__ float red[16][17];
    int n = blockIdx.x * 16 + (threadIdx.x & 15);
    int kg = threadIdx.x >> 4;
    float s = 0.f;
    for (int k = kg; k < K; k += 16) s += beta[k] * W[(size_t)k * N + n];
    red[kg][threadIdx.x & 15] = s;
    __syncthreads();
    if (kg == 0) {
        float t = 0.f;
#pragma unroll
        for (int i = 0; i < 16; i++) t += red[i][threadIdx.x & 15];
        out[n] = t;
    }
}

// ======================= fp16 HMMA GEMM, 3-stage cp.async ===================
#define CP_ASYNC16(dst, src) \
    asm volatile("cp.async.cg.shared.global [%0], [%1], 16;" \
                 :: "r"(dst), "l"(src))
#define CP_COMMIT() asm volatile("cp.async.commit_group;" ::: "memory")
#define CP_WAITG(n) asm volatile("cp.async.wait_group %0;" :: "n"(n) : "memory")

#define LDSM4(r0, r1, r2, r3, addr)                                          \
    asm volatile("ldmatrix.sync.aligned.m8n8.x4.shared.b16 {%0,%1,%2,%3}, [%4];" \
        : "=r"(r0), "=r"(r1), "=r"(r2), "=r"(r3) : "r"(addr))

#define MMAH(d, a, b0, b1)                                                   \
    asm volatile("mma.sync.aligned.m16n8k16.row.col.f32.f16.f16.f32 "        \
        "{%0,%1,%2,%3}, {%4,%5,%6,%7}, {%8,%9}, {%0,%1,%2,%3};"              \
        : "+f"((d)[0]), "+f"((d)[1]), "+f"((d)[2]), "+f"((d)[3])             \
        : "r"((a)[0]), "r"((a)[1]), "r"((a)[2]), "r"((a)[3]),                \
          "r"(b0), "r"(b1))

__device__ __forceinline__ uint32_t smem_u32(const void* p) {
    uint32_t a;
    asm("{ .reg .u64 t; cvta.to.shared.u64 t, %1; cvt.u32.u64 %0, t; }"
        : "=r"(a) : "l"(p));
    return a;
}
__device__ __forceinline__ uint32_t swz(uint32_t off) {
    return off ^ ((off >> 3) & 0x70);
}
__device__ __forceinline__ void store2(float* p, float a, float b) {
    *(float2*)p = make_float2(a, b);
}
__device__ __forceinline__ void store2(__half* p, float a, float b) {
    *(__half2*)p = __floats2half2_rn(a, b);
}

template <int BN>
__device__ __forceinline__ void issue_chunk(
    uint32_t st, const __half* __restrict__ A, const __half* __restrict__ B,
    int K, int c, int tid) {
#pragma unroll
    for (int i = 0; i < 4; i++) {           // A: 128 rows x 8 x16B
        int flat = i * 256 + tid;
        int row = flat >> 3, col16 = flat & 7;
        uint32_t off = swz((uint32_t)(row * 128 + col16 * 16));
        CP_ASYNC16(st + off, A + (size_t)row * K + (size_t)c * 64 + col16 * 8);
    }
#pragma unroll
    for (int i = 0; i < BN / 32; i++) {     // B: BN rows x 8 x16B
        int flat = i * 256 + tid;
        int row = flat >> 3, col16 = flat & 7;
        uint32_t off = swz((uint32_t)(row * 128 + col16 * 16));
        CP_ASYNC16(st + 16384 + off, B + (size_t)row * K + (size_t)c * 64 + col16 * 8);
    }
}

// CTA tile 128 x BN, warp tile 64 x (BN/4), K chunk 64, 3 stages, 1 sync/chunk
template <int BN, typename OutT>
__global__ __launch_bounds__(256, 1) void gemm_h_kernel(
    const __half* __restrict__ Ain, const __half* __restrict__ Win,
    OutT* __restrict__ C, int K, int N, int ldc,
    const float* __restrict__ bias, const float* __restrict__ resid,
    int relu, int remap) {
    constexpr int WN = BN / 4;
    constexpr int NT = WN / 8;
    constexpr int ST = 16384 + BN * 128;
    extern __shared__ char sm[];
    uint32_t smb = smem_u32(sm);
    int tid = threadIdx.x, wid = tid >> 5, lane = tid & 31;
    int warp_m = wid >> 2, warp_n = wid & 3;

    int m0 = blockIdx.y << 7, n0 = blockIdx.x * BN;
    const __half* A = Ain + (size_t)m0 * K;
    const __half* B = Win + (size_t)n0 * K;
    int NC = K >> 6;

    float acc[4][NT][4];
#pragma unroll
    for (int i = 0; i < 4; i++)
#pragma unroll
        for (int j = 0; j < NT; j++)
#pragma unroll
            for (int k = 0; k < 4; k++) acc[i][j][k] = 0.f;

    issue_chunk<BN>(smb, A, B, K, 0, tid);
    CP_COMMIT();
    issue_chunk<BN>(smb + ST, A, B, K, 1, tid);
    CP_COMMIT();

    int lrow = lane & 15, lhalf = lane >> 4;
    for (int c = 0; c < NC; c++) {
        CP_WAITG(1);
        __syncthreads();
        uint32_t st = smb + (uint32_t)((c % 3) * ST);
#pragma unroll
        for (int kq = 0; kq < 4; kq++) {
            int ch = kq * 2 + lhalf;
            uint32_t ah[4][4];
#pragma unroll
            for (int mt = 0; mt < 4; mt++) {
                uint32_t ro = swz((uint32_t)((warp_m * 64 + mt * 16 + lrow) * 128 + ch * 16));
                LDSM4(ah[mt][0], ah[mt][1], ah[mt][2], ah[mt][3], st + ro);
            }
#pragma unroll
            for (int nt2 = 0; nt2 < WN / 16; nt2++) {
                uint32_t ro = swz((uint32_t)((warp_n * WN + nt2 * 16 + lrow) * 128 + ch * 16));
                uint32_t r0, r1, r2, r3;
                LDSM4(r0, r1, r2, r3, st + 16384 + ro);
#pragma unroll
                for (int mt = 0; mt < 4; mt++) {
                    MMAH(acc[mt][nt2 * 2],     ah[mt], r0, r2);
                    MMAH(acc[mt][nt2 * 2 + 1], ah[mt], r1, r3);
                }
            }
        }
        if (c + 2 < NC) {
            // stage (c+2)%3 == (c-1)%3: consumed at iter c-1, safe after this
            // iteration's syncthreads (all warps completed compute c-1).
            issue_chunk<BN>(smb + (uint32_t)(((c + 2) % 3) * ST), A, B, K, c + 2, tid);
            CP_COMMIT();
        }
    }

    // epilogue
    int qrow = lane >> 2, qcol = (lane & 3) * 2;
#pragma unroll
    for (int mt = 0; mt < 4; mt++) {
#pragma unroll
        for (int half = 0; half < 2; half++) {
            int r = m0 + warp_m * 64 + mt * 16 + half * 8 + qrow;
            int crow;
            if (remap == 1)      crow = (r >> 6)  * SKV + Ss + (r & 63);
            else if (remap == 2) crow = (r >> 11) * SKV + (r & 2047);
            else                 crow = r;
            int cb = n0 + warp_n * WN;
            OutT* cp = C + (size_t)crow * ldc + cb;
            const float* rp = resid ? resid + (size_t)r * N + cb : nullptr;
            const float* bp = bias ? bias + cb : nullptr;
#pragma unroll
            for (int nt = 0; nt < NT; nt++) {
                float v0 = acc[mt][nt][half * 2];
                float v1 = acc[mt][nt][half * 2 + 1];
                int col = nt * 8 + qcol;
                if (bp) { v0 += bp[col]; v1 += bp[col + 1]; }
                if (rp) { v0 += rp[col]; v1 += rp[col + 1]; }
                if (relu) { v0 = fmaxf(v0, 0.f); v1 = fmaxf(v1, 0.f); }
                store2(cp + col, v0, v1);
            }
        }
    }
}

// ======================= fused attention (fp16 I/O) =========================
#define ATT_QS   0
#define ATT_KS   (64 * 100)
#define ATT_VS   (ATT_KS + 32 * 100)
#define ATT_PS   (ATT_VS + 32 * 100)
#define ATT_SMEM ((ATT_PS + 64 * 33) * 4)

__global__ __launch_bounds__(256) void attention_kernel(
    const __half* __restrict__ Q, const __half* __restrict__ Kb,
    const __half* __restrict__ Vb, __half* __restrict__ O,
    const float* __restrict__ qw, const float* __restrict__ qb,
    const float* __restrict__ kw, const float* __restrict__ kb) {
    extern __shared__ float smf[];
    float* qs = smf + ATT_QS;
    float* ks = smf + ATT_KS;
    float* vs = smf + ATT_VS;
    float* ps = smf + ATT_PS;

    int tid = threadIdx.x;
    int bh = blockIdx.x;
    int b = bh >> 4, h = bh & 15;
    const float qscale = rsqrtf((float)HDd);

    int myrow = tid >> 2, mypart = tid & 3;
    int qg = tid >> 4, kg = tid & 15;

    {
        const __half* qp = Q + (size_t)(b * NLl + myrow) * HHD + h * HDd + mypart * 24;
        float v[24];
        float s = 0.f, ss = 0.f;
#pragma unroll
        for (int i = 0; i < 24; i += 8) {
            uint4 t = *(const uint4*)(qp + i);
            __half2* hp = (__half2*)&t;
#pragma unroll
            for (int j = 0; j < 4; j++) {
                float2 f = __half22float2(hp[j]);
                v[i + 2 * j] = f.x; v[i + 2 * j + 1] = f.y;
            }
        }
#pragma unroll
        for (int i = 0; i < 24; i++) { s += v[i]; ss += v[i] * v[i]; }
#pragma unroll
        for (int o = 1; o < 4; o <<= 1) {
            s  += __shfl_xor_sync(0xffffffffu, s, o);
            ss += __shfl_xor_sync(0xffffffffu, ss, o);
        }
        float mmu = s * (1.f / 96.f);
        float rsd = rsqrtf(ss * (1.f / 96.f) - mmu * mmu + EPSf);
#pragma unroll
        for (int i = 0; i < 24; i++) {
            int c = mypart * 24 + i;
            qs[myrow * 100 + c] = ((v[i] - mmu) * rsd * qw[c] + qb[c]) * qscale;
        }
    }
    __syncthreads();

    float m_run = -INFINITY, l_run = 0.f;
    float oacc[24];
#pragma unroll
    for (int i = 0; i < 24; i++) oacc[i] = 0.f;

    for (int t = 0; t < SKV / 32; t++) {
        {
            int j = tid >> 3, p8 = tid & 7;
            int kidx = t * 32 + j;
            const __half* kp = Kb + ((size_t)b * SKV + kidx) * HHD + h * HDd + p8 * 12;
            const __half* vp = Vb + ((size_t)b * SKV + kidx) * HHD + h * HDd + p8 * 12;
            float kv[12], vv[12];
            float s = 0.f, ss = 0.f;
#pragma unroll
            for (int i = 0; i < 12; i += 4) {
                uint2 tk = *(const uint2*)(kp + i);
                uint2 tv = *(const uint2*)(vp + i);
                __half2* hk = (__half2*)&tk;
                __half2* hv = (__half2*)&tv;
                float2 f0 = __half22float2(hk[0]), f1 = __half22float2(hk[1]);
                kv[i] = f0.x; kv[i+1] = f0.y; kv[i+2] = f1.x; kv[i+3] = f1.y;
                f0 = __half22float2(hv[0]); f1 = __half22float2(hv[1]);
                vv[i] = f0.x; vv[i+1] = f0.y; vv[i+2] = f1.x; vv[i+3] = f1.y;
            }
#pragma unroll
            for (int i = 0; i < 12; i++) { s += kv[i]; ss += kv[i] * kv[i]; }
#pragma unroll
            for (int o = 1; o < 8; o <<= 1) {
                s  += __shfl_xor_sync(0xffffffffu, s, o);
                ss += __shfl_xor_sync(0xffffffffu, ss, o);
            }
            float mmu = s * (1.f / 96.f);
            float rsd = rsqrtf(ss * (1.f / 96.f) - mmu * mmu + EPSf);
#pragma unroll
            for (int i = 0; i < 12; i++) {
                int c = p8 * 12 + i;
                ks[j * 100 + c] = (kv[i] - mmu) * rsd * kw[c] + kb[c];
            }
#pragma unroll
            for (int i = 0; i < 12; i += 4)
                *(float4*)&vs[j * 100 + p8 * 12 + i] =
                    make_float4(vv[i], vv[i+1], vv[i+2], vv[i+3]);
        }
        __syncthreads();

        {
            float sc[4][2];
#pragma unroll
            for (int i = 0; i < 4; i++) { sc[i][0] = 0.f; sc[i][1] = 0.f; }
            int q0 = qg << 2, k0 = kg << 1;
#pragma unroll
            for (int d = 0; d < 96; d += 4) {
                float4 k0v = *(const float4*)&ks[k0 * 100 + d];
                float4 k1v = *(const float4*)&ks[(k0 + 1) * 100 + d];
#pragma unroll
                for (int i = 0; i < 4; i++) {
                    float4 qv = *(const float4*)&qs[(q0 + i) * 100 + d];
                    sc[i][0] += qv.x*k0v.x + qv.y*k0v.y + qv.z*k0v.z + qv.w*k0v.w;
                    sc[i][1] += qv.x*k1v.x + qv.y*k1v.y + qv.z*k1v.z + qv.w*k1v.w;
                }
            }
#pragma unroll
            for (int i = 0; i < 4; i++) {
                ps[(q0 + i) * 33 + k0]     = sc[i][0];
                ps[(q0 + i) * 33 + k0 + 1] = sc[i][1];
            }
        }
        __syncwarp();

        {
            float p8v[8];
            float mx = -INFINITY;
#pragma unroll
            for (int i = 0; i < 8; i++) {
                p8v[i] = ps[myrow * 33 + mypart * 8 + i];
                mx = fmaxf(mx, p8v[i]);
            }
#pragma unroll
            for (int o = 1; o < 4; o <<= 1)
                mx = fmaxf(mx, __shfl_xor_sync(0xffffffffu, mx, o));
            float mnew = fmaxf(m_run, mx);
            float corr = __expf(m_run - mnew);
            float psum = 0.f;
#pragma unroll
            for (int i = 0; i < 8; i++) {
                p8v[i] = __expf(p8v[i] - mnew);
                psum += p8v[i];
                ps[myrow * 33 + mypart * 8 + i] = p8v[i];
            }
#pragma unroll
            for (int o = 1; o < 4; o <<= 1)
                psum += __shfl_xor_sync(0xffffffffu, psum, o);
            l_run = l_run * corr + psum;
            m_run = mnew;
#pragma unroll
            for (int i = 0; i < 24; i++) oacc[i] *= corr;
            __syncwarp();
#pragma unroll 4
            for (int j = 0; j < 32; j++) {
                float p = ps[myrow * 33 + j];
                const float4* vr = (const float4*)&vs[j * 100 + mypart * 24];
#pragma unroll
                for (int i4 = 0; i4 < 6; i4++) {
                    float4 v = vr[i4];
                    oacc[i4*4+0] += p * v.x;
                    oacc[i4*4+1] += p * v.y;
                    oacc[i4*4+2] += p * v.z;
                    oacc[i4*4+3] += p * v.w;
                }
            }
        }
        __syncthreads();
    }

    {
        float inv = 1.f / l_run;
        __half* op = O + (size_t)(b * NLl + myrow) * HHD + h * HDd + mypart * 24;
#pragma unroll
        for (int i = 0; i < 24; i += 2)
            *(__half2*)(op + i) = __floats2half2_rn(oacc[i] * inv, oacc[i+1] * inv);
    }
}

// ======================= final layer norm -> d_out ==========================
__global__ void final_ln_kernel(float* __restrict__ out,
                                const float* __restrict__ w,
                                const float* __restrict__ bia) {
    int row = blockIdx.x;
    const float* x = g_lat + (size_t)row * Dd;
    float s = 0.f, ss = 0.f;
    for (int c = threadIdx.x; c < Dd; c += blockDim.x) {
        float v = x[c]; s += v; ss += v * v;
    }
#pragma unroll
    for (int o = 16; o > 0; o >>= 1) {
        s  += __shfl_xor_sync(0xffffffffu, s, o);
        ss += __shfl_xor_sync(0xffffffffu, ss, o);
    }
    __shared__ float red_s[8], red_q[8];
    __shared__ float sh_m, sh_r;
    int wrp = threadIdx.x >> 5, nl = threadIdx.x & 31;
    if (nl == 0) { red_s[wrp] = s; red_q[wrp] = ss; }
    __syncthreads();
    if (threadIdx.x == 0) {
        float S = 0.f, Q = 0.f;
        for (int i = 0; i < 8; i++) { S += red_s[i]; Q += red_q[i]; }
        float m = S / (float)Dd;
        sh_m = m;
        sh_r = rsqrtf(Q / (float)Dd - m * m + EPSf);
    }
    __syncthreads();
    float m = sh_m, r = sh_r;
    for (int c = threadIdx.x; c < Dd; c += blockDim.x)
        out[(size_t)row * Dd + c] = (x[c] - m) * r * w[c] + bia[c];
}

// ======================= launch =============================================
extern "C" void kernel_launch(void* const* d_in, const int* in_sizes, int n_in,
                              void* d_out, int out_size) {
    const float* context  = (const float*)d_in[0];
    const float* latents  = (const float*)d_in[1];
    const float* ctx_ln_w = (const float*)d_in[2];
    const float* ctx_ln_b = (const float*)d_in[3];
    const float* lat_ln_w = (const float*)d_in[4];
    const float* lat_ln_b = (const float*)d_in[5];
    const float* q_ln_w   = (const float*)d_in[6];
    const float* q_ln_b   = (const float*)d_in[7];
    const float* k_ln_w   = (const float*)d_in[8];
    const float* k_ln_b   = (const float*)d_in[9];
    const float* wq       = (const float*)d_in[10];
    const float* wk       = (const float*)d_in[11];
    const float* wv       = (const float*)d_in[12];
    const float* wo       = (const float*)d_in[13];
    const float* mlp_ln_w = (const float*)d_in[14];
    const float* mlp_ln_b = (const float*)d_in[15];
    const float* w_fc     = (const float*)d_in[16];
    const float* w_cproj  = (const float*)d_in[17];
    const float* fin_w    = (const float*)d_in[18];
    const float* fin_b    = (const float*)d_in[19];
    (void)in_sizes; (void)n_in; (void)out_size;

    float *pLat, *pBias;
    __half *pW, *pActx, *pAlat, *pAmlp, *pQh, *pK, *pV, *pAttnH;
    cudaGetSymbolAddress((void**)&pLat,   g_lat);
    cudaGetSymbolAddress((void**)&pBias,  g_bias);
    cudaGetSymbolAddress((void**)&pW,     g_W);
    cudaGetSymbolAddress((void**)&pActx,  g_Actx);
    cudaGetSymbolAddress((void**)&pAlat,  g_Alat);
    cudaGetSymbolAddress((void**)&pAmlp,  g_Amlp);
    cudaGetSymbolAddress((void**)&pQh,    g_Qh);
    cudaGetSymbolAddress((void**)&pK,     g_K);
    cudaGetSymbolAddress((void**)&pV,     g_V);
    cudaGetSymbolAddress((void**)&pAttnH, g_attnH);

    constexpr int SM256 = 3 * (16384 + 256 * 128);  // 147456
    constexpr int SM128 = 3 * (16384 + 128 * 128);  // 98304
    cudaFuncSetAttribute(attention_kernel,
                         cudaFuncAttributeMaxDynamicSharedMemorySize, ATT_SMEM);
    cudaFuncSetAttribute(gemm_h_kernel<256, __half>,
                         cudaFuncAttributeMaxDynamicSharedMemorySize, SM256);
    cudaFuncSetAttribute(gemm_h_kernel<128, __half>,
                         cudaFuncAttributeMaxDynamicSharedMemorySize, SM128);
    cudaFuncSetAttribute(gemm_h_kernel<128, float>,
                         cudaFuncAttributeMaxDynamicSharedMemorySize, SM128);

    const int ML = Bb * NLl;   // 2048
    const int MC = Bb * Ss;    // 65536
    dim3 tb(32, 8);

    // ---- prologue ordered so ncu (captures launch index 3) hits ctx K GEMM
    packln_kernel<<<MC, 256>>>(context, nullptr, nullptr, pActx, Dd);   // #0
    wt_packh_kernel<<<dim3(HHD / 32, Dd / 32), tb>>>(
        wk, ctx_ln_w, pW + OFF_WKF, Dd, HHD);                           // #1
    bias_kernel<<<HHD / 16, 256>>>(ctx_ln_b, wk, pBias + 0, Dd, HHD);   // #2
    gemm_h_kernel<256, __half><<<dim3(HHD / 256, MC / 128), 256, SM256>>>( // #3
        pActx, pW + OFF_WKF, pK, Dd, HHD, HHD, pBias + 0, nullptr, 0, 2);
    wt_packh_kernel<<<dim3(HHD / 32, Dd / 32), tb>>>(
        wv, ctx_ln_w, pW + OFF_WVF, Dd, HHD);
    bias_kernel<<<HHD / 16, 256>>>(ctx_ln_b, wv, pBias + HHD, Dd, HHD);
    gemm_h_kernel<256, __half><<<dim3(HHD / 256, MC / 128), 256, SM256>>>(
        pActx, pW + OFF_WVF, pV, Dd, HHD, HHD, pBias + HHD, nullptr, 0, 2);

    // ---- remaining one-time weight packing ----
    for (int i = 0; i < DEPTHn; i++) {
        size_t wb = (size_t)i * LAYER_W;
        const float* gci = ctx_ln_w + i * Dd;
        const float* bci = ctx_ln_b + i * Dd;
        wt_packh_kernel<<<dim3(HHD / 32, Dd / 32), tb>>>(
            wq + (size_t)i * Dd * HHD, nullptr, pW + wb + OFF_WQ, Dd, HHD);
        wt_packh_kernel<<<dim3(HHD / 32, Dd / 32), tb>>>(
            wk + (size_t)i * Dd * HHD, nullptr, pW + wb + OFF_WK, Dd, HHD);
        wt_packh_kernel<<<dim3(HHD / 32, Dd / 32), tb>>>(
            wv + (size_t)i * Dd * HHD, nullptr, pW + wb + OFF_WV, Dd, HHD);
        if (i > 0) {
            wt_packh_kernel<<<dim3(HHD / 32, Dd / 32), tb>>>(
                wk + (size_t)i * Dd * HHD, gci, pW + wb + OFF_WKF, Dd, HHD);
            wt_packh_kernel<<<dim3(HHD / 32, Dd / 32), tb>>>(
                wv + (size_t)i * Dd * HHD, gci, pW + wb + OFF_WVF, Dd, HHD);
            bias_kernel<<<HHD / 16, 256>>>(bci, wk + (size_t)i * Dd * HHD,
                                           pBias + (i * 2 + 0) * HHD, Dd, HHD);
            bias_kernel<<<HHD / 16, 256>>>(bci, wv + (size_t)i * Dd * HHD,
                                           pBias + (i * 2 + 1) * HHD, Dd, HHD);
        }
        wt_packh_kernel<<<dim3(Dd / 32, HHD / 32), tb>>>(
            wo + (size_t)i * HHD * Dd, nullptr, pW + wb + OFF_WO, HHD, Dd);
        wt_packh_kernel<<<dim3(FFf / 32, Dd / 32), tb>>>(
            w_fc + (size_t)i * Dd * FFf, nullptr, pW + wb + OFF_WFC, Dd, FFf);
        wt_packh_kernel<<<dim3(Dd / 32, FFf / 32), tb>>>(
            w_cproj + (size_t)i * FFf * Dd, nullptr, pW + wb + OFF_WCP, FFf, Dd);
    }

    broadcast_lat_kernel<<<(Bb * NLl * Dd + 255) / 256, 256>>>(latents);

    for (int i = 0; i < DEPTHn; i++) {
        size_t wb = (size_t)i * LAYER_W;
        const float* llw = lat_ln_w + i * Dd, *llb = lat_ln_b + i * Dd;
        const float* mlw = mlp_ln_w + i * Dd, *mlb = mlp_ln_b + i * Dd;
        const float* qlw = q_ln_w + i * HDd, *qlb = q_ln_b + i * HDd;
        const float* klw = k_ln_w + i * HDd, *klb = k_ln_b + i * HDd;

        // latent QKV (BN=128 tiles)
        packln_kernel<<<ML, 256>>>(pLat, llw, llb, pAlat, Dd);
        gemm_h_kernel<128, __half><<<dim3(HHD / 128, ML / 128), 256, SM128>>>(
            pAlat, pW + wb + OFF_WQ, pQh, Dd, HHD, HHD, nullptr, nullptr, 0, 0);
        gemm_h_kernel<128, __half><<<dim3(HHD / 128, ML / 128), 256, SM128>>>(
            pAlat, pW + wb + OFF_WK, pK, Dd, HHD, HHD, nullptr, nullptr, 0, 1);
        gemm_h_kernel<128, __half><<<dim3(HHD / 128, ML / 128), 256, SM128>>>(
            pAlat, pW + wb + OFF_WV, pV, Dd, HHD, HHD, nullptr, nullptr, 0, 1);

        // context KV (layer 0 done in prologue)
        if (i > 0) {
            gemm_h_kernel<256, __half><<<dim3(HHD / 256, MC / 128), 256, SM256>>>(
                pActx, pW + wb + OFF_WKF, pK, Dd, HHD, HHD,
                pBias + (i * 2 + 0) * HHD, nullptr, 0, 2);
            gemm_h_kernel<256, __half><<<dim3(HHD / 256, MC / 128), 256, SM256>>>(
                pActx, pW + wb + OFF_WVF, pV, Dd, HHD, HHD,
                pBias + (i * 2 + 1) * HHD, nullptr, 0, 2);
        }

        attention_kernel<<<Bb * Hh, 256, ATT_SMEM>>>(pQh, pK, pV, pAttnH,
                                                     qlw, qlb, klw, klb);

        // wo projection + residual (reads fp16 attn directly)
        gemm_h_kernel<128, float><<<dim3(Dd / 128, ML / 128), 256, SM128>>>(
            pAttnH, pW + wb + OFF_WO, pLat, HHD, Dd, Dd, nullptr, pLat, 0, 0);

        // MLP
        packln_kernel<<<ML, 256>>>(pLat, mlw, mlb, pAlat, Dd);
        gemm_h_kernel<128, __half><<<dim3(FFf / 128, ML / 128), 256, SM128>>>(
            pAlat, pW + wb + OFF_WFC, pAmlp, Dd, FFf, FFf, nullptr, nullptr, 1, 0);
        gemm_h_kernel<128, float><<<dim3(Dd / 128, ML / 128), 256, SM128>>>(
            pAmlp, pW + wb + OFF_WCP, pLat, FFf, Dd, Dd, nullptr, pLat, 0, 0);
    }

    final_ln_kernel<<<Bb * NLl, 256>>>((float*)d_out, fin_w, fin_b);
}

// round 8
// speedup vs baseline: 4.7683x; 1.0985x over previous
#include <cuda_runtime.h>
#include <cuda_fp16.h>
#include <cstdint>
#include <math.h>

#define Bb     32
#define Ss     2048
#define Dd     1280
#define Hh     16
#define HDd    96
#define NLl    64
#define DEPTHn 3
#define FFf    5120
#define SKV    (Ss + NLl)      /* 2112 */
#define HHD    (Hh * HDd)      /* 1536 */
#define EPSf   1e-5f

// ======================= scratch (device globals) ===========================
__device__ float g_lat[Bb * NLl * Dd];
__device__ float g_bias[DEPTHn * 2 * HHD];
__device__ __half g_Qh[Bb * NLl * HHD];
__device__ __half g_K[(size_t)Bb * SKV * HHD];
__device__ __half g_V[(size_t)Bb * SKV * HHD];
__device__ __half g_attnH[Bb * NLl * HHD];
__device__ __half g_Amlp[(size_t)Bb * NLl * FFf];

#define SZ1      1966080u                 /* 1536*1280 */
#define SZFC     6553600u                 /* 5120*1280 */
#define OFF_WQ   0u
#define OFF_WK   (SZ1)
#define OFF_WV   (2u * SZ1)
#define OFF_WKF  (3u * SZ1)               /* gamma-folded, ctx */
#define OFF_WVF  (4u * SZ1)
#define OFF_WO   (5u * SZ1)
#define OFF_WFC  (6u * SZ1)
#define OFF_WCP  (6u * SZ1 + SZFC)
#define LAYER_W  (6u * SZ1 + 2u * SZFC)
__device__ __half g_W[(size_t)DEPTHn * LAYER_W];
__device__ __half g_Actx[(size_t)Bb * Ss * Dd];   // ctx, packed ONCE
__device__ __half g_Alat[Bb * NLl * Dd];          // latent LN pack

// ======================= prep kernels ========================================
__global__ void packln_kernel(const float* __restrict__ X,
                              const float* __restrict__ lnw,
                              const float* __restrict__ lnb,
                              __half* __restrict__ out, int ncols) {
    int row = blockIdx.x;
    const float* x = X + (size_t)row * ncols;
    __half* o = out + (size_t)row * ncols;
    float v[8];
    int nv = 0;
    float s = 0.f, ss = 0.f;
    for (int c = threadIdx.x; c < ncols; c += blockDim.x) {
        float t = x[c];
        v[nv++] = t;
        s += t; ss += t * t;
    }
#pragma unroll
    for (int o2 = 16; o2 > 0; o2 >>= 1) {
        s  += __shfl_xor_sync(0xffffffffu, s, o2);
        ss += __shfl_xor_sync(0xffffffffu, ss, o2);
    }
    __shared__ float red_s[8], red_q[8];
    __shared__ float sh_m, sh_r;
    int w = threadIdx.x >> 5, nl = threadIdx.x & 31;
    if (nl == 0) { red_s[w] = s; red_q[w] = ss; }
    __syncthreads();
    if (threadIdx.x == 0) {
        float S = 0.f, Q = 0.f;
        int nw = blockDim.x >> 5;
        for (int i = 0; i < nw; i++) { S += red_s[i]; Q += red_q[i]; }
        float m = S / (float)ncols;
        sh_m = m;
        sh_r = rsqrtf(Q / (float)ncols - m * m + EPSf);
    }
    __syncthreads();
    float mu = sh_m, rs = sh_r;
    nv = 0;
    for (int c = threadIdx.x; c < ncols; c += blockDim.x) {
        float t = (v[nv++] - mu) * rs;
        if (lnw) t = t * lnw[c] + lnb[c];
        o[c] = __float2half_rn(t);
    }
}

__global__ void broadcast_lat_kernel(const float* __restrict__ latents) {
    int i = blockIdx.x * blockDim.x + threadIdx.x;
    const int per = NLl * Dd;
    if (i < Bb * per) g_lat[i] = latents[i % per];
}

__global__ void wt_packh_kernel(const float* __restrict__ W,
                                const float* __restrict__ gamma,
                                __half* __restrict__ out, int K, int N) {
    __shared__ float tile[32][33];
    int n0 = blockIdx.x << 5, k0 = blockIdx.y << 5;
    for (int i = threadIdx.y; i < 32; i += 8)
        tile[i][threadIdx.x] = W[(size_t)(k0 + i) * N + n0 + threadIdx.x];
    __syncthreads();
    float g = gamma ? gamma[k0 + threadIdx.x] : 1.f;
    for (int i = threadIdx.y; i < 32; i += 8)
        out[(size_t)(n0 + i) * K + k0 + threadIdx.x] =
            __float2half_rn(tile[threadIdx.x][i] * g);
}

__global__ void bias_kernel(const float* __restrict__ beta,
                            const float* __restrict__ W,
                            float* __restrict__ out, int K, int N) {
    __shared__ float red[16][17];
    int n = blockIdx.x * 16 + (threadIdx.x & 15);
    int kg = threadIdx.x >> 4;
    float s = 0.f;
    for (int k = kg; k < K; k += 16) s += beta[k] * W[(size_t)k * N + n];
    red[kg][threadIdx.x & 15] = s;
    __syncthreads();
    if (kg == 0) {
        float t = 0.f;
#pragma unroll
        for (int i = 0; i < 16; i++) t += red[i][threadIdx.x & 15];
        out[n] = t;
    }
}

// ======================= fp16 HMMA GEMM, 512 threads ========================
#define CP_ASYNC16(dst, src) \
    asm volatile("cp.async.cg.shared.global [%0], [%1], 16;" \
                 :: "r"(dst), "l"(src))
#define CP_COMMIT() asm volatile("cp.async.commit_group;" ::: "memory")
#define CP_WAITG(n) asm volatile("cp.async.wait_group %0;" :: "n"(n) : "memory")

#define LDSM4(r0, r1, r2, r3, addr)                                          \
    asm volatile("ldmatrix.sync.aligned.m8n8.x4.shared.b16 {%0,%1,%2,%3}, [%4];" \
        : "=r"(r0), "=r"(r1), "=r"(r2), "=r"(r3) : "r"(addr))

#define MMAH(d, a, b0, b1)                                                   \
    asm volatile("mma.sync.aligned.m16n8k16.row.col.f32.f16.f16.f32 "        \
        "{%0,%1,%2,%3}, {%4,%5,%6,%7}, {%8,%9}, {%0,%1,%2,%3};"              \
        : "+f"((d)[0]), "+f"((d)[1]), "+f"((d)[2]), "+f"((d)[3])             \
        : "r"((a)[0]), "r"((a)[1]), "r"((a)[2]), "r"((a)[3]),                \
          "r"(b0), "r"(b1))

__device__ __forceinline__ uint32_t smem_u32(const void* p) {
    uint32_t a;
    asm("{ .reg .u64 t; cvta.to.shared.u64 t, %1; cvt.u32.u64 %0, t; }"
        : "=r"(a) : "l"(p));
    return a;
}
__device__ __forceinline__ uint32_t swz(uint32_t off) {
    return off ^ ((off >> 3) & 0x70);
}
__device__ __forceinline__ void store2(float* p, float a, float b) {
    *(float2*)p = make_float2(a, b);
}
__device__ __forceinline__ void store2(__half* p, float a, float b) {
    *(__half2*)p = __floats2half2_rn(a, b);
}

// CTA tile 128 x BN, 16 warps (2m x 8n), warp tile 64 x BN/8, chunk 64, 3 stages
template <int BN, typename OutT>
__global__ __launch_bounds__(512, 1) void gemm_h_kernel(
    const __half* __restrict__ Ain, const __half* __restrict__ Win,
    OutT* __restrict__ C, int K, int N, int ldc,
    const float* __restrict__ bias, const float* __restrict__ resid,
    int relu, int remap) {
    constexpr int WN = BN / 8;
    constexpr int NT = WN / 8;
    constexpr int ST = 16384 + BN * 128;
    constexpr int NB = BN / 64;
    extern __shared__ char sm[];
    uint32_t smb = smem_u32(sm);
    int tid = threadIdx.x, wid = tid >> 5, lane = tid & 31;
    int warp_m = wid >> 3, warp_n = wid & 7;

    int m0 = blockIdx.y << 7, n0 = blockIdx.x * BN;
    const __half* A = Ain + (size_t)m0 * K;
    const __half* B = Win + (size_t)n0 * K;
    int NC = K >> 6;

    // hoisted copy state
    uint32_t sA[2]; const __half* gA[2];
#pragma unroll
    for (int i = 0; i < 2; i++) {
        int flat = i * 512 + tid;
        int row = flat >> 3, c16 = flat & 7;
        sA[i] = swz((uint32_t)(row * 128 + c16 * 16));
        gA[i] = A + (size_t)row * K + c16 * 8;
    }
    uint32_t sB[NB]; const __half* gB[NB];
#pragma unroll
    for (int i = 0; i < NB; i++) {
        int flat = i * 512 + tid;
        int row = flat >> 3, c16 = flat & 7;
        sB[i] = 16384u + swz((uint32_t)(row * 128 + c16 * 16));
        gB[i] = B + (size_t)row * K + c16 * 8;
    }

    int lrow = lane & 15, lhalf = lane >> 4;
    // hoisted A-fragment smem offsets
    uint32_t aOff[4][4];
#pragma unroll
    for (int kq = 0; kq < 4; kq++)
#pragma unroll
        for (int mt = 0; mt < 4; mt++)
            aOff[kq][mt] = swz((uint32_t)((warp_m * 64 + mt * 16 + lrow) * 128 +
                                          (kq * 2 + lhalf) * 16));

    float acc[4][NT][4];
#pragma unroll
    for (int i = 0; i < 4; i++)
#pragma unroll
        for (int j = 0; j < NT; j++)
#pragma unroll
            for (int k = 0; k < 4; k++) acc[i][j][k] = 0.f;

    // prologue: chunks 0, 1
#pragma unroll
    for (int pc = 0; pc < 2; pc++) {
        uint32_t stb = smb + (uint32_t)(pc * ST);
        int koff = pc * 64;
#pragma unroll
        for (int i = 0; i < 2; i++) CP_ASYNC16(stb + sA[i], gA[i] + koff);
#pragma unroll
        for (int i = 0; i < NB; i++) CP_ASYNC16(stb + sB[i], gB[i] + koff);
        CP_COMMIT();
    }

    for (int c = 0; c < NC; c++) {
        if (c + 1 < NC) { CP_WAITG(1); } else { CP_WAITG(0); }
        __syncthreads();
        uint32_t st = smb + (uint32_t)((c % 3) * ST);
#pragma unroll
        for (int kq = 0; kq < 4; kq++) {
            uint32_t ah[4][4];
#pragma unroll
            for (int mt = 0; mt < 4; mt++)
                LDSM4(ah[mt][0], ah[mt][1], ah[mt][2], ah[mt][3],
                      st + aOff[kq][mt]);
#pragma unroll
            for (int nt2 = 0; nt2 < NT / 2; nt2++) {
                uint32_t ro = swz((uint32_t)((warp_n * WN + nt2 * 16 + lrow) * 128 +
                                             (kq * 2 + lhalf) * 16));
                uint32_t r0, r1, r2, r3;
                LDSM4(r0, r1, r2, r3, st + 16384 + ro);
#pragma unroll
                for (int mt = 0; mt < 4; mt++) {
                    MMAH(acc[mt][nt2 * 2],     ah[mt], r0, r2);
                    MMAH(acc[mt][nt2 * 2 + 1], ah[mt], r1, r3);
                }
            }
        }
        if (c + 2 < NC) {
            uint32_t stb = smb + (uint32_t)(((c + 2) % 3) * ST);
            int koff = (c + 2) * 64;
#pragma unroll
            for (int i = 0; i < 2; i++) CP_ASYNC16(stb + sA[i], gA[i] + koff);
#pragma unroll
            for (int i = 0; i < NB; i++) CP_ASYNC16(stb + sB[i], gB[i] + koff);
            CP_COMMIT();
        }
    }

    // epilogue
    int qrow = lane >> 2, qcol = (lane & 3) * 2;
#pragma unroll
    for (int mt = 0; mt < 4; mt++) {
#pragma unroll
        for (int half = 0; half < 2; half++) {
            int r = m0 + warp_m * 64 + mt * 16 + half * 8 + qrow;
            int crow;
            if (remap == 1)      crow = (r >> 6)  * SKV + Ss + (r & 63);
            else if (remap == 2) crow = (r >> 11) * SKV + (r & 2047);
            else                 crow = r;
            int cb = n0 + warp_n * WN;
            OutT* cp = C + (size_t)crow * ldc + cb;
            const float* rp = resid ? resid + (size_t)r * N + cb : nullptr;
            const float* bp = bias ? bias + cb : nullptr;
#pragma unroll
            for (int nt = 0; nt < NT; nt++) {
                float v0 = acc[mt][nt][half * 2];
                float v1 = acc[mt][nt][half * 2 + 1];
                int col = nt * 8 + qcol;
                if (bp) { v0 += bp[col]; v1 += bp[col + 1]; }
                if (rp) { v0 += rp[col]; v1 += rp[col + 1]; }
                if (relu) { v0 = fmaxf(v0, 0.f); v1 = fmaxf(v1, 0.f); }
                store2(cp + col, v0, v1);
            }
        }
    }
}

// ======================= fused attention (fp16 smem) ========================
#define ASTR 104
#define ATT_SMEM (128 * ASTR * 2 + 64 * 33 * 4)   /* 35072 */

__global__ __launch_bounds__(256) void attention_kernel(
    const __half* __restrict__ Q, const __half* __restrict__ Kb,
    const __half* __restrict__ Vb, __half* __restrict__ O,
    const float* __restrict__ qw, const float* __restrict__ qb,
    const float* __restrict__ kw, const float* __restrict__ kb) {
    extern __shared__ char smc[];
    __half* qs = (__half*)smc;              // [64][104]
    __half* ks = qs + 64 * ASTR;            // [32][104]
    __half* vs = ks + 32 * ASTR;            // [32][104]
    float*  ps = (float*)(vs + 32 * ASTR);  // [64][33]

    int tid = threadIdx.x;
    int bh = blockIdx.x;
    int b = bh >> 4, h = bh & 15;
    const float qscale = rsqrtf((float)HDd);

    int myrow = tid >> 2, mypart = tid & 3;
    int qg = tid >> 4, kg = tid & 15;

    // Q load + per-head LN + scale -> fp16 smem
    {
        const __half* qp = Q + (size_t)(b * NLl + myrow) * HHD + h * HDd + mypart * 24;
        float v[24];
        float s = 0.f, ss = 0.f;
#pragma unroll
        for (int i = 0; i < 24; i += 8) {
            uint4 t = *(const uint4*)(qp + i);
            __half2* hp = (__half2*)&t;
#pragma unroll
            for (int j = 0; j < 4; j++) {
                float2 f = __half22float2(hp[j]);
                v[i + 2 * j] = f.x; v[i + 2 * j + 1] = f.y;
            }
        }
#pragma unroll
        for (int i = 0; i < 24; i++) { s += v[i]; ss += v[i] * v[i]; }
#pragma unroll
        for (int o = 1; o < 4; o <<= 1) {
            s  += __shfl_xor_sync(0xffffffffu, s, o);
            ss += __shfl_xor_sync(0xffffffffu, ss, o);
        }
        float mmu = s * (1.f / 96.f);
        float rsd = rsqrtf(ss * (1.f / 96.f) - mmu * mmu + EPSf);
        __half2 hq[12];
#pragma unroll
        for (int i = 0; i < 12; i++) {
            int c = mypart * 24 + 2 * i;
            float a0 = ((v[2 * i]     - mmu) * rsd * qw[c]     + qb[c])     * qscale;
            float a1 = ((v[2 * i + 1] - mmu) * rsd * qw[c + 1] + qb[c + 1]) * qscale;
            hq[i] = __floats2half2_rn(a0, a1);
        }
        __half* dst = qs + myrow * ASTR + mypart * 24;
        *(uint4*)(dst)      = *(uint4*)&hq[0];
        *(uint4*)(dst + 8)  = *(uint4*)&hq[4];
        *(uint4*)(dst + 16) = *(uint4*)&hq[8];
    }
    __syncthreads();

    float m_run = -INFINITY, l_run = 0.f;
    float oacc[24];
#pragma unroll
    for (int i = 0; i < 24; i++) oacc[i] = 0.f;

    for (int t = 0; t < SKV / 32; t++) {
        // K (head-LN) + V (raw copy) into fp16 smem
        {
            int j = tid >> 3, p8 = tid & 7;
            int kidx = t * 32 + j;
            const __half* kp = Kb + ((size_t)b * SKV + kidx) * HHD + h * HDd + p8 * 12;
            const __half* vp = Vb + ((size_t)b * SKV + kidx) * HHD + h * HDd + p8 * 12;
            uint2 kr[3], vr[3];
#pragma unroll
            for (int i = 0; i < 3; i++) {
                kr[i] = *(const uint2*)(kp + i * 4);
                vr[i] = *(const uint2*)(vp + i * 4);
            }
            float kv[12];
#pragma unroll
            for (int i = 0; i < 3; i++) {
                __half2* hk = (__half2*)&kr[i];
                float2 f0 = __half22float2(hk[0]), f1 = __half22float2(hk[1]);
                kv[i * 4] = f0.x; kv[i * 4 + 1] = f0.y;
                kv[i * 4 + 2] = f1.x; kv[i * 4 + 3] = f1.y;
            }
            float s = 0.f, ss = 0.f;
#pragma unroll
            for (int i = 0; i < 12; i++) { s += kv[i]; ss += kv[i] * kv[i]; }
#pragma unroll
            for (int o = 1; o < 8; o <<= 1) {
                s  += __shfl_xor_sync(0xffffffffu, s, o);
                ss += __shfl_xor_sync(0xffffffffu, ss, o);
            }
            float mmu = s * (1.f / 96.f);
            float rsd = rsqrtf(ss * (1.f / 96.f) - mmu * mmu + EPSf);
            __half2 hk[6];
#pragma unroll
            for (int i = 0; i < 6; i++) {
                int c = p8 * 12 + 2 * i;
                hk[i] = __floats2half2_rn(
                    (kv[2 * i]     - mmu) * rsd * kw[c]     + kb[c],
                    (kv[2 * i + 1] - mmu) * rsd * kw[c + 1] + kb[c + 1]);
            }
            __half* kd = ks + j * ASTR + p8 * 12;
            __half* vd = vs + j * ASTR + p8 * 12;
#pragma unroll
            for (int i = 0; i < 3; i++) {
                *(uint2*)(kd + i * 4) = ((uint2*)hk)[i];
                *(uint2*)(vd + i * 4) = vr[i];
            }
        }
        __syncthreads();

        // scores: 4 q-rows x 2 k-cols per thread, d = 96
        {
            float sc[4][2];
#pragma unroll
            for (int i = 0; i < 4; i++) { sc[i][0] = 0.f; sc[i][1] = 0.f; }
            int q0 = qg << 2, k0 = kg << 1;
#pragma unroll
            for (int d = 0; d < 96; d += 8) {
                uint4 kr0 = *(uint4*)(ks + k0 * ASTR + d);
                uint4 kr1 = *(uint4*)(ks + (k0 + 1) * ASTR + d);
                float2 k0f[4], k1f[4];
                __half2* h0 = (__half2*)&kr0;
                __half2* h1 = (__half2*)&kr1;
#pragma unroll
                for (int j = 0; j < 4; j++) {
                    k0f[j] = __half22float2(h0[j]);
                    k1f[j] = __half22float2(h1[j]);
                }
#pragma unroll
                for (int i = 0; i < 4; i++) {
                    uint4 qr = *(uint4*)(qs + (q0 + i) * ASTR + d);
                    __half2* hqv = (__half2*)&qr;
#pragma unroll
                    for (int j = 0; j < 4; j++) {
                        float2 qf = __half22float2(hqv[j]);
                        sc[i][0] += qf.x * k0f[j].x + qf.y * k0f[j].y;
                        sc[i][1] += qf.x * k1f[j].x + qf.y * k1f[j].y;
                    }
                }
            }
#pragma unroll
            for (int i = 0; i < 4; i++) {
                ps[(q0 + i) * 33 + k0]     = sc[i][0];
                ps[(q0 + i) * 33 + k0 + 1] = sc[i][1];
            }
        }
        __syncwarp();

        // online softmax + PV
        {
            float p8v[8];
            float mx = -INFINITY;
#pragma unroll
            for (int i = 0; i < 8; i++) {
                p8v[i] = ps[myrow * 33 + mypart * 8 + i];
                mx = fmaxf(mx, p8v[i]);
            }
#pragma unroll
            for (int o = 1; o < 4; o <<= 1)
                mx = fmaxf(mx, __shfl_xor_sync(0xffffffffu, mx, o));
            float mnew = fmaxf(m_run, mx);
            float corr = __expf(m_run - mnew);
            float psum = 0.f;
#pragma unroll
            for (int i = 0; i < 8; i++) {
                p8v[i] = __expf(p8v[i] - mnew);
                psum += p8v[i];
                ps[myrow * 33 + mypart * 8 + i] = p8v[i];
            }
#pragma unroll
            for (int o = 1; o < 4; o <<= 1)
                psum += __shfl_xor_sync(0xffffffffu, psum, o);
            l_run = l_run * corr + psum;
            m_run = mnew;
#pragma unroll
            for (int i = 0; i < 24; i++) oacc[i] *= corr;
            __syncwarp();
#pragma unroll 4
            for (int j = 0; j < 32; j++) {
                float p = ps[myrow * 33 + j];
                const __half* vrp = vs + j * ASTR + mypart * 24;
                uint4 v0 = *(uint4*)(vrp);
                uint4 v1 = *(uint4*)(vrp + 8);
                uint4 v2 = *(uint4*)(vrp + 16);
                __half2* hv0 = (__half2*)&v0;
                __half2* hv1 = (__half2*)&v1;
                __half2* hv2 = (__half2*)&v2;
#pragma unroll
                for (int i = 0; i < 4; i++) {
                    float2 f = __half22float2(hv0[i]);
                    oacc[2 * i]     += p * f.x;
                    oacc[2 * i + 1] += p * f.y;
                    f = __half22float2(hv1[i]);
                    oacc[8 + 2 * i]     += p * f.x;
                    oacc[8 + 2 * i + 1] += p * f.y;
                    f = __half22float2(hv2[i]);
                    oacc[16 + 2 * i]     += p * f.x;
                    oacc[16 + 2 * i + 1] += p * f.y;
                }
            }
        }
        __syncthreads();
    }

    {
        float inv = 1.f / l_run;
        __half* op = O + (size_t)(b * NLl + myrow) * HHD + h * HDd + mypart * 24;
#pragma unroll
        for (int i = 0; i < 24; i += 2)
            *(__half2*)(op + i) = __floats2half2_rn(oacc[i] * inv, oacc[i + 1] * inv);
    }
}

// ======================= final layer norm -> d_out ==========================
__global__ void final_ln_kernel(float* __restrict__ out,
                                const float* __restrict__ w,
                                const float* __restrict__ bia) {
    int row = blockIdx.x;
    const float* x = g_lat + (size_t)row * Dd;
    float s = 0.f, ss = 0.f;
    for (int c = threadIdx.x; c < Dd; c += blockDim.x) {
        float v = x[c]; s += v; ss += v * v;
    }
#pragma unroll
    for (int o = 16; o > 0; o >>= 1) {
        s  += __shfl_xor_sync(0xffffffffu, s, o);
        ss += __shfl_xor_sync(0xffffffffu, ss, o);
    }
    __shared__ float red_s[8], red_q[8];
    __shared__ float sh_m, sh_r;
    int wrp = threadIdx.x >> 5, nl = threadIdx.x & 31;
    if (nl == 0) { red_s[wrp] = s; red_q[wrp] = ss; }
    __syncthreads();
    if (threadIdx.x == 0) {
        float S = 0.f, Q = 0.f;
        for (int i = 0; i < 8; i++) { S += red_s[i]; Q += red_q[i]; }
        float m = S / (float)Dd;
        sh_m = m;
        sh_r = rsqrtf(Q / (float)Dd - m * m + EPSf);
    }
    __syncthreads();
    float m = sh_m, r = sh_r;
    for (int c = threadIdx.x; c < Dd; c += blockDim.x)
        out[(size_t)row * Dd + c] = (x[c] - m) * r * w[c] + bia[c];
}

// ======================= launch =============================================
extern "C" void kernel_launch(void* const* d_in, const int* in_sizes, int n_in,
                              void* d_out, int out_size) {
    const float* context  = (const float*)d_in[0];
    const float* latents  = (const float*)d_in[1];
    const float* ctx_ln_w = (const float*)d_in[2];
    const float* ctx_ln_b = (const float*)d_in[3];
    const float* lat_ln_w = (const float*)d_in[4];
    const float* lat_ln_b = (const float*)d_in[5];
    const float* q_ln_w   = (const float*)d_in[6];
    const float* q_ln_b   = (const float*)d_in[7];
    const float* k_ln_w   = (const float*)d_in[8];
    const float* k_ln_b   = (const float*)d_in[9];
    const float* wq       = (const float*)d_in[10];
    const float* wk       = (const float*)d_in[11];
    const float* wv       = (const float*)d_in[12];
    const float* wo       = (const float*)d_in[13];
    const float* mlp_ln_w = (const float*)d_in[14];
    const float* mlp_ln_b = (const float*)d_in[15];
    const float* w_fc     = (const float*)d_in[16];
    const float* w_cproj  = (const float*)d_in[17];
    const float* fin_w    = (const float*)d_in[18];
    const float* fin_b    = (const float*)d_in[19];
    (void)in_sizes; (void)n_in; (void)out_size;

    float *pLat, *pBias;
    __half *pW, *pActx, *pAlat, *pAmlp, *pQh, *pK, *pV, *pAttnH;
    cudaGetSymbolAddress((void**)&pLat,   g_lat);
    cudaGetSymbolAddress((void**)&pBias,  g_bias);
    cudaGetSymbolAddress((void**)&pW,     g_W);
    cudaGetSymbolAddress((void**)&pActx,  g_Actx);
    cudaGetSymbolAddress((void**)&pAlat,  g_Alat);
    cudaGetSymbolAddress((void**)&pAmlp,  g_Amlp);
    cudaGetSymbolAddress((void**)&pQh,    g_Qh);
    cudaGetSymbolAddress((void**)&pK,     g_K);
    cudaGetSymbolAddress((void**)&pV,     g_V);
    cudaGetSymbolAddress((void**)&pAttnH, g_attnH);

    constexpr int SM256 = 3 * (16384 + 256 * 128);  // 147456
    constexpr int SM128 = 3 * (16384 + 128 * 128);  // 98304
    cudaFuncSetAttribute(attention_kernel,
                         cudaFuncAttributeMaxDynamicSharedMemorySize, ATT_SMEM);
    cudaFuncSetAttribute(gemm_h_kernel<256, __half>,
                         cudaFuncAttributeMaxDynamicSharedMemorySize, SM256);
    cudaFuncSetAttribute(gemm_h_kernel<128, __half>,
                         cudaFuncAttributeMaxDynamicSharedMemorySize, SM128);
    cudaFuncSetAttribute(gemm_h_kernel<128, float>,
                         cudaFuncAttributeMaxDynamicSharedMemorySize, SM128);

    const int ML = Bb * NLl;   // 2048
    const int MC = Bb * Ss;    // 65536
    dim3 tb(32, 8);

    // ---- prologue ordered so ncu (captures launch index 3) hits ctx K GEMM
    packln_kernel<<<MC, 256>>>(context, nullptr, nullptr, pActx, Dd);   // #0
    wt_packh_kernel<<<dim3(HHD / 32, Dd / 32), tb>>>(
        wk, ctx_ln_w, pW + OFF_WKF, Dd, HHD);                           // #1
    bias_kernel<<<HHD / 16, 256>>>(ctx_ln_b, wk, pBias + 0, Dd, HHD);   // #2
    gemm_h_kernel<256, __half><<<dim3(HHD / 256, MC / 128), 512, SM256>>>( // #3
        pActx, pW + OFF_WKF, pK, Dd, HHD, HHD, pBias + 0, nullptr, 0, 2);
    wt_packh_kernel<<<dim3(HHD / 32, Dd / 32), tb>>>(
        wv, ctx_ln_w, pW + OFF_WVF, Dd, HHD);
    bias_kernel<<<HHD / 16, 256>>>(ctx_ln_b, wv, pBias + HHD, Dd, HHD);
    gemm_h_kernel<256, __half><<<dim3(HHD / 256, MC / 128), 512, SM256>>>(
        pActx, pW + OFF_WVF, pV, Dd, HHD, HHD, pBias + HHD, nullptr, 0, 2);

    // ---- remaining one-time weight packing ----
    for (int i = 0; i < DEPTHn; i++) {
        size_t wb = (size_t)i * LAYER_W;
        const float* gci = ctx_ln_w + i * Dd;
        const float* bci = ctx_ln_b + i * Dd;
        wt_packh_kernel<<<dim3(HHD / 32, Dd / 32), tb>>>(
            wq + (size_t)i * Dd * HHD, nullptr, pW + wb + OFF_WQ, Dd, HHD);
        wt_packh_kernel<<<dim3(HHD / 32, Dd / 32), tb>>>(
            wk + (size_t)i * Dd * HHD, nullptr, pW + wb + OFF_WK, Dd, HHD);
        wt_packh_kernel<<<dim3(HHD / 32, Dd / 32), tb>>>(
            wv + (size_t)i * Dd * HHD, nullptr, pW + wb + OFF_WV, Dd, HHD);
        if (i > 0) {
            wt_packh_kernel<<<dim3(HHD / 32, Dd / 32), tb>>>(
                wk + (size_t)i * Dd * HHD, gci, pW + wb + OFF_WKF, Dd, HHD);
            wt_packh_kernel<<<dim3(HHD / 32, Dd / 32), tb>>>(
                wv + (size_t)i * Dd * HHD, gci, pW + wb + OFF_WVF, Dd, HHD);
            bias_kernel<<<HHD / 16, 256>>>(bci, wk + (size_t)i * Dd * HHD,
                                           pBias + (i * 2 + 0) * HHD, Dd, HHD);
            bias_kernel<<<HHD / 16, 256>>>(bci, wv + (size_t)i * Dd * HHD,
                                           pBias + (i * 2 + 1) * HHD, Dd, HHD);
        }
        wt_packh_kernel<<<dim3(Dd / 32, HHD / 32), tb>>>(
            wo + (size_t)i * HHD * Dd, nullptr, pW + wb + OFF_WO, HHD, Dd);
        wt_packh_kernel<<<dim3(FFf / 32, Dd / 32), tb>>>(
            w_fc + (size_t)i * Dd * FFf, nullptr, pW + wb + OFF_WFC, Dd, FFf);
        wt_packh_kernel<<<dim3(Dd / 32, FFf / 32), tb>>>(
            w_cproj + (size_t)i * FFf * Dd, nullptr, pW + wb + OFF_WCP, FFf, Dd);
    }

    broadcast_lat_kernel<<<(Bb * NLl * Dd + 255) / 256, 256>>>(latents);

    for (int i = 0; i < DEPTHn; i++) {
        size_t wb = (size_t)i * LAYER_W;
        const float* llw = lat_ln_w + i * Dd, *llb = lat_ln_b + i * Dd;
        const float* mlw = mlp_ln_w + i * Dd, *mlb = mlp_ln_b + i * Dd;
        const float* qlw = q_ln_w + i * HDd, *qlb = q_ln_b + i * HDd;
        const float* klw = k_ln_w + i * HDd, *klb = k_ln_b + i * HDd;

        // latent QKV (BN=128 tiles)
        packln_kernel<<<ML, 256>>>(pLat, llw, llb, pAlat, Dd);
        gemm_h_kernel<128, __half><<<dim3(HHD / 128, ML / 128), 512, SM128>>>(
            pAlat, pW + wb + OFF_WQ, pQh, Dd, HHD, HHD, nullptr, nullptr, 0, 0);
        gemm_h_kernel<128, __half><<<dim3(HHD / 128, ML / 128), 512, SM128>>>(
            pAlat, pW + wb + OFF_WK, pK, Dd, HHD, HHD, nullptr, nullptr, 0, 1);
        gemm_h_kernel<128, __half><<<dim3(HHD / 128, ML / 128), 512, SM128>>>(
            pAlat, pW + wb + OFF_WV, pV, Dd, HHD, HHD, nullptr, nullptr, 0, 1);

        // context KV (layer 0 done in prologue)
        if (i > 0) {
            gemm_h_kernel<256, __half><<<dim3(HHD / 256, MC / 128), 512, SM256>>>(
                pActx, pW + wb + OFF_WKF, pK, Dd, HHD, HHD,
                pBias + (i * 2 + 0) * HHD, nullptr, 0, 2);
            gemm_h_kernel<256, __half><<<dim3(HHD / 256, MC / 128), 512, SM256>>>(
                pActx, pW + wb + OFF_WVF, pV, Dd, HHD, HHD,
                pBias + (i * 2 + 1) * HHD, nullptr, 0, 2);
        }

        attention_kernel<<<Bb * Hh, 256, ATT_SMEM>>>(pQh, pK, pV, pAttnH,
                                                     qlw, qlb, klw, klb);

        // wo projection + residual
        gemm_h_kernel<128, float><<<dim3(Dd / 128, ML / 128), 512, SM128>>>(
            pAttnH, pW + wb + OFF_WO, pLat, HHD, Dd, Dd, nullptr, pLat, 0, 0);

        // MLP
        packln_kernel<<<ML, 256>>>(pLat, mlw, mlb, pAlat, Dd);
        gemm_h_kernel<128, __half><<<dim3(FFf / 128, ML / 128), 512, SM128>>>(
            pAlat, pW + wb + OFF_WFC, pAmlp, Dd, FFf, FFf, nullptr, nullptr, 1, 0);
        gemm_h_kernel<128, float><<<dim3(Dd / 128, ML / 128), 512, SM128>>>(
            pAmlp, pW + wb + OFF_WCP, pLat, FFf, Dd, Dd, nullptr, pLat, 0, 0);
    }

    final_ln_kernel<<<Bb * NLl, 256>>>((float*)d_out, fin_w, fin_b);
}

// round 9
// speedup vs baseline: 7.0664x; 1.4819x over previous
#include <cuda_runtime.h>
#include <cuda_fp16.h>
#include <cstdint>
#include <math.h>

#define Bb     32
#define Ss     2048
#define Dd     1280
#define Hh     16
#define HDd    96
#define NLl    64
#define DEPTHn 3
#define FFf    5120
#define SKV    (Ss + NLl)      /* 2112 */
#define HHD    (Hh * HDd)      /* 1536 */
#define EPSf   1e-5f

// ======================= scratch (device globals) ===========================
__device__ float g_lat[Bb * NLl * Dd];
__device__ float g_bias[DEPTHn * 2 * HHD];
__device__ __half g_Qh[Bb * NLl * HHD];
__device__ __half g_K[(size_t)Bb * SKV * HHD];
__device__ __half g_V[(size_t)Bb * SKV * HHD];
__device__ __half g_attnH[Bb * NLl * HHD];
__device__ __half g_Amlp[(size_t)Bb * NLl * FFf];

#define SZ1      1966080u
#define SZFC     6553600u
#define OFF_WQ   0u
#define OFF_WK   (SZ1)
#define OFF_WV   (2u * SZ1)
#define OFF_WKF  (3u * SZ1)
#define OFF_WVF  (4u * SZ1)
#define OFF_WO   (5u * SZ1)
#define OFF_WFC  (6u * SZ1)
#define OFF_WCP  (6u * SZ1 + SZFC)
#define LAYER_W  (6u * SZ1 + 2u * SZFC)
__device__ __half g_W[(size_t)DEPTHn * LAYER_W];
__device__ __half g_Actx[(size_t)Bb * Ss * Dd];
__device__ __half g_Alat[Bb * NLl * Dd];

// ======================= prep kernels ========================================
__global__ void packln_kernel(const float* __restrict__ X,
                              const float* __restrict__ lnw,
                              const float* __restrict__ lnb,
                              __half* __restrict__ out, int ncols) {
    int row = blockIdx.x;
    const float* x = X + (size_t)row * ncols;
    __half* o = out + (size_t)row * ncols;
    float v[8];
    int nv = 0;
    float s = 0.f, ss = 0.f;
    for (int c = threadIdx.x; c < ncols; c += blockDim.x) {
        float t = x[c];
        v[nv++] = t;
        s += t; ss += t * t;
    }
#pragma unroll
    for (int o2 = 16; o2 > 0; o2 >>= 1) {
        s  += __shfl_xor_sync(0xffffffffu, s, o2);
        ss += __shfl_xor_sync(0xffffffffu, ss, o2);
    }
    __shared__ float red_s[8], red_q[8];
    __shared__ float sh_m, sh_r;
    int w = threadIdx.x >> 5, nl = threadIdx.x & 31;
    if (nl == 0) { red_s[w] = s; red_q[w] = ss; }
    __syncthreads();
    if (threadIdx.x == 0) {
        float S = 0.f, Q = 0.f;
        int nw = blockDim.x >> 5;
        for (int i = 0; i < nw; i++) { S += red_s[i]; Q += red_q[i]; }
        float m = S / (float)ncols;
        sh_m = m;
        sh_r = rsqrtf(Q / (float)ncols - m * m + EPSf);
    }
    __syncthreads();
    float mu = sh_m, rs = sh_r;
    nv = 0;
    for (int c = threadIdx.x; c < ncols; c += blockDim.x) {
        float t = (v[nv++] - mu) * rs;
        if (lnw) t = t * lnw[c] + lnb[c];
        o[c] = __float2half_rn(t);
    }
}

__global__ void broadcast_lat_kernel(const float* __restrict__ latents) {
    int i = blockIdx.x * blockDim.x + threadIdx.x;
    const int per = NLl * Dd;
    if (i < Bb * per) g_lat[i] = latents[i % per];
}

__global__ void wt_packh_kernel(const float* __restrict__ W,
                                const float* __restrict__ gamma,
                                __half* __restrict__ out, int K, int N) {
    __shared__ float tile[32][33];
    int n0 = blockIdx.x << 5, k0 = blockIdx.y << 5;
    for (int i = threadIdx.y; i < 32; i += 8)
        tile[i][threadIdx.x] = W[(size_t)(k0 + i) * N + n0 + threadIdx.x];
    __syncthreads();
    float g = gamma ? gamma[k0 + threadIdx.x] : 1.f;
    for (int i = threadIdx.y; i < 32; i += 8)
        out[(size_t)(n0 + i) * K + k0 + threadIdx.x] =
            __float2half_rn(tile[threadIdx.x][i] * g);
}

__global__ void bias_kernel(const float* __restrict__ beta,
                            const float* __restrict__ W,
                            float* __restrict__ out, int K, int N) {
    __shared__ float red[16][17];
    int n = blockIdx.x * 16 + (threadIdx.x & 15);
    int kg = threadIdx.x >> 4;
    float s = 0.f;
    for (int k = kg; k < K; k += 16) s += beta[k] * W[(size_t)k * N + n];
    red[kg][threadIdx.x & 15] = s;
    __syncthreads();
    if (kg == 0) {
        float t = 0.f;
#pragma unroll
        for (int i = 0; i < 16; i++) t += red[i][threadIdx.x & 15];
        out[n] = t;
    }
}

// ======================= fp16 HMMA GEMM, 512 threads ========================
#define CP_ASYNC16(dst, src) \
    asm volatile("cp.async.cg.shared.global [%0], [%1], 16;" \
                 :: "r"(dst), "l"(src))
#define CP_COMMIT() asm volatile("cp.async.commit_group;" ::: "memory")
#define CP_WAITG(n) asm volatile("cp.async.wait_group %0;" :: "n"(n) : "memory")

#define LDSM4(r0, r1, r2, r3, addr)                                          \
    asm volatile("ldmatrix.sync.aligned.m8n8.x4.shared.b16 {%0,%1,%2,%3}, [%4];" \
        : "=r"(r0), "=r"(r1), "=r"(r2), "=r"(r3) : "r"(addr))

#define LDSM4T(r0, r1, r2, r3, addr)                                         \
    asm volatile("ldmatrix.sync.aligned.m8n8.x4.trans.shared.b16 {%0,%1,%2,%3}, [%4];" \
        : "=r"(r0), "=r"(r1), "=r"(r2), "=r"(r3) : "r"(addr))

#define MMAH(d, a, b0, b1)                                                   \
    asm volatile("mma.sync.aligned.m16n8k16.row.col.f32.f16.f16.f32 "        \
        "{%0,%1,%2,%3}, {%4,%5,%6,%7}, {%8,%9}, {%0,%1,%2,%3};"              \
        : "+f"((d)[0]), "+f"((d)[1]), "+f"((d)[2]), "+f"((d)[3])             \
        : "r"((a)[0]), "r"((a)[1]), "r"((a)[2]), "r"((a)[3]),                \
          "r"(b0), "r"(b1))

__device__ __forceinline__ uint32_t smem_u32(const void* p) {
    uint32_t a;
    asm("{ .reg .u64 t; cvta.to.shared.u64 t, %1; cvt.u32.u64 %0, t; }"
        : "=r"(a) : "l"(p));
    return a;
}
__device__ __forceinline__ uint32_t swz(uint32_t off) {
    return off ^ ((off >> 3) & 0x70);
}
__device__ __forceinline__ void store2(float* p, float a, float b) {
    *(float2*)p = make_float2(a, b);
}
__device__ __forceinline__ void store2(__half* p, float a, float b) {
    *(__half2*)p = __floats2half2_rn(a, b);
}

template <int BN, typename OutT>
__global__ __launch_bounds__(512, 1) void gemm_h_kernel(
    const __half* __restrict__ Ain, const __half* __restrict__ Win,
    OutT* __restrict__ C, int K, int N, int ldc,
    const float* __restrict__ bias, const float* __restrict__ resid,
    int relu, int remap) {
    constexpr int WN = BN / 8;
    constexpr int NT = WN / 8;
    constexpr int ST = 16384 + BN * 128;
    constexpr int NB = BN / 64;
    extern __shared__ char sm[];
    uint32_t smb = smem_u32(sm);
    int tid = threadIdx.x, wid = tid >> 5, lane = tid & 31;
    int warp_m = wid >> 3, warp_n = wid & 7;

    int m0 = blockIdx.y << 7, n0 = blockIdx.x * BN;
    const __half* A = Ain + (size_t)m0 * K;
    const __half* B = Win + (size_t)n0 * K;
    int NC = K >> 6;

    uint32_t sA[2]; const __half* gA[2];
#pragma unroll
    for (int i = 0; i < 2; i++) {
        int flat = i * 512 + tid;
        int row = flat >> 3, c16 = flat & 7;
        sA[i] = swz((uint32_t)(row * 128 + c16 * 16));
        gA[i] = A + (size_t)row * K + c16 * 8;
    }
    uint32_t sB[NB]; const __half* gB[NB];
#pragma unroll
    for (int i = 0; i < NB; i++) {
        int flat = i * 512 + tid;
        int row = flat >> 3, c16 = flat & 7;
        sB[i] = 16384u + swz((uint32_t)(row * 128 + c16 * 16));
        gB[i] = B + (size_t)row * K + c16 * 8;
    }

    int lrow = lane & 15, lhalf = lane >> 4;
    uint32_t aOff[4][4];
#pragma unroll
    for (int kq = 0; kq < 4; kq++)
#pragma unroll
        for (int mt = 0; mt < 4; mt++)
            aOff[kq][mt] = swz((uint32_t)((warp_m * 64 + mt * 16 + lrow) * 128 +
                                          (kq * 2 + lhalf) * 16));

    float acc[4][NT][4];
#pragma unroll
    for (int i = 0; i < 4; i++)
#pragma unroll
        for (int j = 0; j < NT; j++)
#pragma unroll
            for (int k = 0; k < 4; k++) acc[i][j][k] = 0.f;

#pragma unroll
    for (int pc = 0; pc < 2; pc++) {
        uint32_t stb = smb + (uint32_t)(pc * ST);
        int koff = pc * 64;
#pragma unroll
        for (int i = 0; i < 2; i++) CP_ASYNC16(stb + sA[i], gA[i] + koff);
#pragma unroll
        for (int i = 0; i < NB; i++) CP_ASYNC16(stb + sB[i], gB[i] + koff);
        CP_COMMIT();
    }

    for (int c = 0; c < NC; c++) {
        if (c + 1 < NC) { CP_WAITG(1); } else { CP_WAITG(0); }
        __syncthreads();
        uint32_t st = smb + (uint32_t)((c % 3) * ST);
#pragma unroll
        for (int kq = 0; kq < 4; kq++) {
            uint32_t ah[4][4];
#pragma unroll
            for (int mt = 0; mt < 4; mt++)
                LDSM4(ah[mt][0], ah[mt][1], ah[mt][2], ah[mt][3],
                      st + aOff[kq][mt]);
#pragma unroll
            for (int nt2 = 0; nt2 < NT / 2; nt2++) {
                uint32_t ro = swz((uint32_t)((warp_n * WN + nt2 * 16 + lrow) * 128 +
                                             (kq * 2 + lhalf) * 16));
                uint32_t r0, r1, r2, r3;
                LDSM4(r0, r1, r2, r3, st + 16384 + ro);
#pragma unroll
                for (int mt = 0; mt < 4; mt++) {
                    MMAH(acc[mt][nt2 * 2],     ah[mt], r0, r2);
                    MMAH(acc[mt][nt2 * 2 + 1], ah[mt], r1, r3);
                }
            }
        }
        if (c + 2 < NC) {
            uint32_t stb = smb + (uint32_t)(((c + 2) % 3) * ST);
            int koff = (c + 2) * 64;
#pragma unroll
            for (int i = 0; i < 2; i++) CP_ASYNC16(stb + sA[i], gA[i] + koff);
#pragma unroll
            for (int i = 0; i < NB; i++) CP_ASYNC16(stb + sB[i], gB[i] + koff);
            CP_COMMIT();
        }
    }

    int qrow = lane >> 2, qcol = (lane & 3) * 2;
#pragma unroll
    for (int mt = 0; mt < 4; mt++) {
#pragma unroll
        for (int half = 0; half < 2; half++) {
            int r = m0 + warp_m * 64 + mt * 16 + half * 8 + qrow;
            int crow;
            if (remap == 1)      crow = (r >> 6)  * SKV + Ss + (r & 63);
            else if (remap == 2) crow = (r >> 11) * SKV + (r & 2047);
            else                 crow = r;
            int cb = n0 + warp_n * WN;
            OutT* cp = C + (size_t)crow * ldc + cb;
            const float* rp = resid ? resid + (size_t)r * N + cb : nullptr;
            const float* bp = bias ? bias + cb : nullptr;
#pragma unroll
            for (int nt = 0; nt < NT; nt++) {
                float v0 = acc[mt][nt][half * 2];
                float v1 = acc[mt][nt][half * 2 + 1];
                int col = nt * 8 + qcol;
                if (bp) { v0 += bp[col]; v1 += bp[col + 1]; }
                if (rp) { v0 += rp[col]; v1 += rp[col + 1]; }
                if (relu) { v0 = fmaxf(v0, 0.f); v1 = fmaxf(v1, 0.f); }
                store2(cp + col, v0, v1);
            }
        }
    }
}

// ======================= HMMA flash attention ===============================
// One CTA per (b, h); 8 warps. KV tiles of 64. S warp tile 16x32, PV 16x48.
// smem strides: q/k/v 104 halfs (208B), p 72 halfs (144B) -> conflict-free LDSM.
#define AQS   0
#define AKS   13312
#define AVS   26624
#define APS   39936
#define AMB   49152      /* m_buf[2][64] f32 */
#define ALR   49664      /* l_run[64] */
#define AMX   49920      /* red_mx[64][2] */
#define ASM_  50432      /* red_sm[64][2] */
#define ATT_SMEM 50944

__global__ __launch_bounds__(256) void attention_kernel(
    const __half* __restrict__ Q, const __half* __restrict__ Kb,
    const __half* __restrict__ Vb, __half* __restrict__ O,
    const float* __restrict__ qw, const float* __restrict__ qb,
    const float* __restrict__ kw, const float* __restrict__ kb) {
    extern __shared__ char smc[];
    __half* qs = (__half*)(smc + AQS);
    __half* ks = (__half*)(smc + AKS);
    __half* vs = (__half*)(smc + AVS);
    __half* psm = (__half*)(smc + APS);
    float* mbuf = (float*)(smc + AMB);
    float* lrun = (float*)(smc + ALR);
    float* rmx  = (float*)(smc + AMX);
    float* rsm  = (float*)(smc + ASM_);
    uint32_t smb = smem_u32(smc);

    int tid = threadIdx.x, wid = tid >> 5, lane = tid & 31;
    int warp_m = wid >> 1, warp_n = wid & 1;
    int b = blockIdx.x >> 4, h = blockIdx.x & 15;
    const float qscale = rsqrtf((float)HDd);

    int jrow = tid >> 2, part = tid & 3;    // loader mapping (64 rows x 4 parts)
    int lrow = lane & 15, lhalf = lane >> 4;
    int qrow = lane >> 2, qpair = lane & 3;
    int r0 = warp_m * 16 + qrow, r1 = r0 + 8;

    // ---- Q load + head-LN + scale -> qs ----
    {
        const __half* qp = Q + (size_t)(b * NLl + jrow) * HHD + h * HDd + part * 24;
        float v[24];
        float s = 0.f, ss = 0.f;
#pragma unroll
        for (int i = 0; i < 3; i++) {
            uint4 t = *(const uint4*)(qp + i * 8);
            __half2* hp = (__half2*)&t;
#pragma unroll
            for (int j = 0; j < 4; j++) {
                float2 f = __half22float2(hp[j]);
                v[i * 8 + 2 * j] = f.x; v[i * 8 + 2 * j + 1] = f.y;
            }
        }
#pragma unroll
        for (int i = 0; i < 24; i++) { s += v[i]; ss += v[i] * v[i]; }
#pragma unroll
        for (int o = 1; o < 4; o <<= 1) {
            s  += __shfl_xor_sync(0xffffffffu, s, o);
            ss += __shfl_xor_sync(0xffffffffu, ss, o);
        }
        float mmu = s * (1.f / 96.f);
        float rsd = rsqrtf(ss * (1.f / 96.f) - mmu * mmu + EPSf);
        __half2 hq[12];
#pragma unroll
        for (int i = 0; i < 12; i++) {
            int c = part * 24 + 2 * i;
            hq[i] = __floats2half2_rn(
                ((v[2 * i]     - mmu) * rsd * qw[c]     + qb[c])     * qscale,
                ((v[2 * i + 1] - mmu) * rsd * qw[c + 1] + qb[c + 1]) * qscale);
        }
        __half* dst = qs + jrow * 104 + part * 24;
        *(uint4*)(dst)      = *(uint4*)&hq[0];
        *(uint4*)(dst + 8)  = *(uint4*)&hq[4];
        *(uint4*)(dst + 16) = *(uint4*)&hq[8];
    }
    if (tid < 64) { mbuf[tid] = -1e30f; lrun[tid] = 0.f; }
    __syncthreads();

    float oac[6][4];
#pragma unroll
    for (int j = 0; j < 6; j++)
#pragma unroll
        for (int k = 0; k < 4; k++) oac[j][k] = 0.f;

    for (int t = 0; t < SKV / 64; t++) {
        // ---- load K (head-LN) + V tiles of 64 rows ----
        {
            int kidx = t * 64 + jrow;
            const __half* kp = Kb + ((size_t)b * SKV + kidx) * HHD + h * HDd + part * 24;
            const __half* vp = Vb + ((size_t)b * SKV + kidx) * HHD + h * HDd + part * 24;
            uint4 kr[3], vr[3];
#pragma unroll
            for (int i = 0; i < 3; i++) {
                kr[i] = *(const uint4*)(kp + i * 8);
                vr[i] = *(const uint4*)(vp + i * 8);
            }
            float kv[24];
#pragma unroll
            for (int i = 0; i < 3; i++) {
                __half2* hk = (__half2*)&kr[i];
#pragma unroll
                for (int j = 0; j < 4; j++) {
                    float2 f = __half22float2(hk[j]);
                    kv[i * 8 + 2 * j] = f.x; kv[i * 8 + 2 * j + 1] = f.y;
                }
            }
            float s = 0.f, ss = 0.f;
#pragma unroll
            for (int i = 0; i < 24; i++) { s += kv[i]; ss += kv[i] * kv[i]; }
#pragma unroll
            for (int o = 1; o < 4; o <<= 1) {
                s  += __shfl_xor_sync(0xffffffffu, s, o);
                ss += __shfl_xor_sync(0xffffffffu, ss, o);
            }
            float mmu = s * (1.f / 96.f);
            float rsd = rsqrtf(ss * (1.f / 96.f) - mmu * mmu + EPSf);
            __half2 hk2[12];
#pragma unroll
            for (int i = 0; i < 12; i++) {
                int c = part * 24 + 2 * i;
                hk2[i] = __floats2half2_rn(
                    (kv[2 * i]     - mmu) * rsd * kw[c]     + kb[c],
                    (kv[2 * i + 1] - mmu) * rsd * kw[c + 1] + kb[c + 1]);
            }
            __half* kd = ks + jrow * 104 + part * 24;
            __half* vd = vs + jrow * 104 + part * 24;
            *(uint4*)(kd)      = *(uint4*)&hk2[0];
            *(uint4*)(kd + 8)  = *(uint4*)&hk2[4];
            *(uint4*)(kd + 16) = *(uint4*)&hk2[8];
            *(uint4*)(vd)      = vr[0];
            *(uint4*)(vd + 8)  = vr[1];
            *(uint4*)(vd + 16) = vr[2];
        }
        __syncthreads();

        // ---- S = Q @ K^T : warp tile 16x32 ----
        float sc[4][4];
#pragma unroll
        for (int i = 0; i < 4; i++)
#pragma unroll
            for (int k = 0; k < 4; k++) sc[i][k] = 0.f;
#pragma unroll
        for (int k6 = 0; k6 < 6; k6++) {
            uint32_t a[4];
            LDSM4(a[0], a[1], a[2], a[3],
                  smb + AQS + (uint32_t)((warp_m * 16 + lrow) * 208 + (k6 * 2 + lhalf) * 16));
#pragma unroll
            for (int nt2 = 0; nt2 < 2; nt2++) {
                uint32_t b0, b1, b2, b3;
                LDSM4(b0, b1, b2, b3,
                      smb + AKS + (uint32_t)((warp_n * 32 + nt2 * 16 + lrow) * 208 +
                                             (k6 * 2 + lhalf) * 16));
                MMAH(sc[nt2 * 2],     a, b0, b2);
                MMAH(sc[nt2 * 2 + 1], a, b1, b3);
            }
        }

        // ---- row max (warp half) -> smem ----
        float mx0 = -1e30f, mx1 = -1e30f;
#pragma unroll
        for (int nt = 0; nt < 4; nt++) {
            mx0 = fmaxf(mx0, fmaxf(sc[nt][0], sc[nt][1]));
            mx1 = fmaxf(mx1, fmaxf(sc[nt][2], sc[nt][3]));
        }
        mx0 = fmaxf(mx0, __shfl_xor_sync(0xffffffffu, mx0, 1));
        mx0 = fmaxf(mx0, __shfl_xor_sync(0xffffffffu, mx0, 2));
        mx1 = fmaxf(mx1, __shfl_xor_sync(0xffffffffu, mx1, 1));
        mx1 = fmaxf(mx1, __shfl_xor_sync(0xffffffffu, mx1, 2));
        if (qpair == 0) {
            rmx[r0 * 2 + warp_n] = mx0;
            rmx[r1 * 2 + warp_n] = mx1;
        }
        __syncthreads();

        // ---- softmax: exp, P->smem, row sums ----
        int p = t & 1;
        float mo0 = mbuf[p * 64 + r0], mo1 = mbuf[p * 64 + r1];
        float mn0 = fmaxf(mo0, fmaxf(rmx[r0 * 2], rmx[r0 * 2 + 1]));
        float mn1 = fmaxf(mo1, fmaxf(rmx[r1 * 2], rmx[r1 * 2 + 1]));
        float cr0 = __expf(mo0 - mn0), cr1 = __expf(mo1 - mn1);
        if (warp_n == 0 && qpair == 0) {
            mbuf[(p ^ 1) * 64 + r0] = mn0;
            mbuf[(p ^ 1) * 64 + r1] = mn1;
        }
        float s0 = 0.f, s1 = 0.f;
#pragma unroll
        for (int nt = 0; nt < 4; nt++) {
            float e0 = __expf(sc[nt][0] - mn0);
            float e1 = __expf(sc[nt][1] - mn0);
            float e2 = __expf(sc[nt][2] - mn1);
            float e3 = __expf(sc[nt][3] - mn1);
            s0 += e0 + e1; s1 += e2 + e3;
            int col = warp_n * 32 + nt * 8 + qpair * 2;
            *(__half2*)(psm + r0 * 72 + col) = __floats2half2_rn(e0, e1);
            *(__half2*)(psm + r1 * 72 + col) = __floats2half2_rn(e2, e3);
        }
        s0 += __shfl_xor_sync(0xffffffffu, s0, 1);
        s0 += __shfl_xor_sync(0xffffffffu, s0, 2);
        s1 += __shfl_xor_sync(0xffffffffu, s1, 1);
        s1 += __shfl_xor_sync(0xffffffffu, s1, 2);
        if (qpair == 0) {
            rsm[r0 * 2 + warp_n] = s0;
            rsm[r1 * 2 + warp_n] = s1;
        }
        __syncthreads();
        if (warp_n == 0 && qpair == 0) {
            lrun[r0] = lrun[r0] * cr0 + rsm[r0 * 2] + rsm[r0 * 2 + 1];
            lrun[r1] = lrun[r1] * cr1 + rsm[r1 * 2] + rsm[r1 * 2 + 1];
        }

        // ---- PV: O += P @ V, warp tile 16x48 ----
#pragma unroll
        for (int j = 0; j < 6; j++) {
            oac[j][0] *= cr0; oac[j][1] *= cr0;
            oac[j][2] *= cr1; oac[j][3] *= cr1;
        }
        int w8 = lane & 7, blk = lane >> 3;
#pragma unroll
        for (int kk = 0; kk < 4; kk++) {
            uint32_t a[4];
            LDSM4(a[0], a[1], a[2], a[3],
                  smb + APS + (uint32_t)((warp_m * 16 + lrow) * 144 + (kk * 2 + lhalf) * 16));
#pragma unroll
            for (int pr = 0; pr < 3; pr++) {
                int vrow = kk * 16 + w8 + 8 * (blk & 1);
                int vcol = warp_n * 48 + pr * 16 + 8 * (blk >> 1);
                uint32_t b0, b1, b2, b3;
                LDSM4T(b0, b1, b2, b3,
                       smb + AVS + (uint32_t)(vrow * 208 + vcol * 2));
                MMAH(oac[pr * 2],     a, b0, b1);
                MMAH(oac[pr * 2 + 1], a, b2, b3);
            }
        }
        __syncthreads();
    }

    // ---- normalize + write ----
    float inv0 = 1.f / lrun[r0], inv1 = 1.f / lrun[r1];
#pragma unroll
    for (int j = 0; j < 6; j++) {
        int col = warp_n * 48 + j * 8 + qpair * 2;
        __half* op0 = O + (size_t)(b * NLl + r0) * HHD + h * HDd + col;
        __half* op1 = O + (size_t)(b * NLl + r1) * HHD + h * HDd + col;
        *(__half2*)op0 = __floats2half2_rn(oac[j][0] * inv0, oac[j][1] * inv0);
        *(__half2*)op1 = __floats2half2_rn(oac[j][2] * inv1, oac[j][3] * inv1);
    }
}

// ======================= final layer norm -> d_out ==========================
__global__ void final_ln_kernel(float* __restrict__ out,
                                const float* __restrict__ w,
                                const float* __restrict__ bia) {
    int row = blockIdx.x;
    const float* x = g_lat + (size_t)row * Dd;
    float s = 0.f, ss = 0.f;
    for (int c = threadIdx.x; c < Dd; c += blockDim.x) {
        float v = x[c]; s += v; ss += v * v;
    }
#pragma unroll
    for (int o = 16; o > 0; o >>= 1) {
        s  += __shfl_xor_sync(0xffffffffu, s, o);
        ss += __shfl_xor_sync(0xffffffffu, ss, o);
    }
    __shared__ float red_s[8], red_q[8];
    __shared__ float sh_m, sh_r;
    int wrp = threadIdx.x >> 5, nl = threadIdx.x & 31;
    if (nl == 0) { red_s[wrp] = s; red_q[wrp] = ss; }
    __syncthreads();
    if (threadIdx.x == 0) {
        float S = 0.f, Q = 0.f;
        for (int i = 0; i < 8; i++) { S += red_s[i]; Q += red_q[i]; }
        float m = S / (float)Dd;
        sh_m = m;
        sh_r = rsqrtf(Q / (float)Dd - m * m + EPSf);
    }
    __syncthreads();
    float m = sh_m, r = sh_r;
    for (int c = threadIdx.x; c < Dd; c += blockDim.x)
        out[(size_t)row * Dd + c] = (x[c] - m) * r * w[c] + bia[c];
}

// ======================= launch =============================================
extern "C" void kernel_launch(void* const* d_in, const int* in_sizes, int n_in,
                              void* d_out, int out_size) {
    const float* context  = (const float*)d_in[0];
    const float* latents  = (const float*)d_in[1];
    const float* ctx_ln_w = (const float*)d_in[2];
    const float* ctx_ln_b = (const float*)d_in[3];
    const float* lat_ln_w = (const float*)d_in[4];
    const float* lat_ln_b = (const float*)d_in[5];
    const float* q_ln_w   = (const float*)d_in[6];
    const float* q_ln_b   = (const float*)d_in[7];
    const float* k_ln_w   = (const float*)d_in[8];
    const float* k_ln_b   = (const float*)d_in[9];
    const float* wq       = (const float*)d_in[10];
    const float* wk       = (const float*)d_in[11];
    const float* wv       = (const float*)d_in[12];
    const float* wo       = (const float*)d_in[13];
    const float* mlp_ln_w = (const float*)d_in[14];
    const float* mlp_ln_b = (const float*)d_in[15];
    const float* w_fc     = (const float*)d_in[16];
    const float* w_cproj  = (const float*)d_in[17];
    const float* fin_w    = (const float*)d_in[18];
    const float* fin_b    = (const float*)d_in[19];
    (void)in_sizes; (void)n_in; (void)out_size;

    float *pLat, *pBias;
    __half *pW, *pActx, *pAlat, *pAmlp, *pQh, *pK, *pV, *pAttnH;
    cudaGetSymbolAddress((void**)&pLat,   g_lat);
    cudaGetSymbolAddress((void**)&pBias,  g_bias);
    cudaGetSymbolAddress((void**)&pW,     g_W);
    cudaGetSymbolAddress((void**)&pActx,  g_Actx);
    cudaGetSymbolAddress((void**)&pAlat,  g_Alat);
    cudaGetSymbolAddress((void**)&pAmlp,  g_Amlp);
    cudaGetSymbolAddress((void**)&pQh,    g_Qh);
    cudaGetSymbolAddress((void**)&pK,     g_K);
    cudaGetSymbolAddress((void**)&pV,     g_V);
    cudaGetSymbolAddress((void**)&pAttnH, g_attnH);

    constexpr int SM256 = 3 * (16384 + 256 * 128);
    constexpr int SM128 = 3 * (16384 + 128 * 128);
    cudaFuncSetAttribute(attention_kernel,
                         cudaFuncAttributeMaxDynamicSharedMemorySize, ATT_SMEM);
    cudaFuncSetAttribute(gemm_h_kernel<256, __half>,
                         cudaFuncAttributeMaxDynamicSharedMemorySize, SM256);
    cudaFuncSetAttribute(gemm_h_kernel<128, __half>,
                         cudaFuncAttributeMaxDynamicSharedMemorySize, SM128);
    cudaFuncSetAttribute(gemm_h_kernel<128, float>,
                         cudaFuncAttributeMaxDynamicSharedMemorySize, SM128);

    const int ML = Bb * NLl;   // 2048
    const int MC = Bb * Ss;    // 65536
    dim3 tb(32, 8);

    packln_kernel<<<MC, 256>>>(context, nullptr, nullptr, pActx, Dd);
    wt_packh_kernel<<<dim3(HHD / 32, Dd / 32), tb>>>(
        wk, ctx_ln_w, pW + OFF_WKF, Dd, HHD);
    bias_kernel<<<HHD / 16, 256>>>(ctx_ln_b, wk, pBias + 0, Dd, HHD);
    gemm_h_kernel<256, __half><<<dim3(HHD / 256, MC / 128), 512, SM256>>>(
        pActx, pW + OFF_WKF, pK, Dd, HHD, HHD, pBias + 0, nullptr, 0, 2);
    wt_packh_kernel<<<dim3(HHD / 32, Dd / 32), tb>>>(
        wv, ctx_ln_w, pW + OFF_WVF, Dd, HHD);
    bias_kernel<<<HHD / 16, 256>>>(ctx_ln_b, wv, pBias + HHD, Dd, HHD);
    gemm_h_kernel<256, __half><<<dim3(HHD / 256, MC / 128), 512, SM256>>>(
        pActx, pW + OFF_WVF, pV, Dd, HHD, HHD, pBias + HHD, nullptr, 0, 2);

    for (int i = 0; i < DEPTHn; i++) {
        size_t wb = (size_t)i * LAYER_W;
        const float* gci = ctx_ln_w + i * Dd;
        const float* bci = ctx_ln_b + i * Dd;
        wt_packh_kernel<<<dim3(HHD / 32, Dd / 32), tb>>>(
            wq + (size_t)i * Dd * HHD, nullptr, pW + wb + OFF_WQ, Dd, HHD);
        wt_packh_kernel<<<dim3(HHD / 32, Dd / 32), tb>>>(
            wk + (size_t)i * Dd * HHD, nullptr, pW + wb + OFF_WK, Dd, HHD);
        wt_packh_kernel<<<dim3(HHD / 32, Dd / 32), tb>>>(
            wv + (size_t)i * Dd * HHD, nullptr, pW + wb + OFF_WV, Dd, HHD);
        if (i > 0) {
            wt_packh_kernel<<<dim3(HHD / 32, Dd / 32), tb>>>(
                wk + (size_t)i * Dd * HHD, gci, pW + wb + OFF_WKF, Dd, HHD);
            wt_packh_kernel<<<dim3(HHD / 32, Dd / 32), tb>>>(
                wv + (size_t)i * Dd * HHD, gci, pW + wb + OFF_WVF, Dd, HHD);
            bias_kernel<<<HHD / 16, 256>>>(bci, wk + (size_t)i * Dd * HHD,
                                           pBias + (i * 2 + 0) * HHD, Dd, HHD);
            bias_kernel<<<HHD / 16, 256>>>(bci, wv + (size_t)i * Dd * HHD,
                                           pBias + (i * 2 + 1) * HHD, Dd, HHD);
        }
        wt_packh_kernel<<<dim3(Dd / 32, HHD / 32), tb>>>(
            wo + (size_t)i * HHD * Dd, nullptr, pW + wb + OFF_WO, HHD, Dd);
        wt_packh_kernel<<<dim3(FFf / 32, Dd / 32), tb>>>(
            w_fc + (size_t)i * Dd * FFf, nullptr, pW + wb + OFF_WFC, Dd, FFf);
        wt_packh_kernel<<<dim3(Dd / 32, FFf / 32), tb>>>(
            w_cproj + (size_t)i * FFf * Dd, nullptr, pW + wb + OFF_WCP, FFf, Dd);
    }

    broadcast_lat_kernel<<<(Bb * NLl * Dd + 255) / 256, 256>>>(latents);

    for (int i = 0; i < DEPTHn; i++) {
        size_t wb = (size_t)i * LAYER_W;
        const float* llw = lat_ln_w + i * Dd, *llb = lat_ln_b + i * Dd;
        const float* mlw = mlp_ln_w + i * Dd, *mlb = mlp_ln_b + i * Dd;
        const float* qlw = q_ln_w + i * HDd, *qlb = q_ln_b + i * HDd;
        const float* klw = k_ln_w + i * HDd, *klb = k_ln_b + i * HDd;

        packln_kernel<<<ML, 256>>>(pLat, llw, llb, pAlat, Dd);
        gemm_h_kernel<128, __half><<<dim3(HHD / 128, ML / 128), 512, SM128>>>(
            pAlat, pW + wb + OFF_WQ, pQh, Dd, HHD, HHD, nullptr, nullptr, 0, 0);
        gemm_h_kernel<128, __half><<<dim3(HHD / 128, ML / 128), 512, SM128>>>(
            pAlat, pW + wb + OFF_WK, pK, Dd, HHD, HHD, nullptr, nullptr, 0, 1);
        gemm_h_kernel<128, __half><<<dim3(HHD / 128, ML / 128), 512, SM128>>>(
            pAlat, pW + wb + OFF_WV, pV, Dd, HHD, HHD, nullptr, nullptr, 0, 1);

        if (i > 0) {
            gemm_h_kernel<256, __half><<<dim3(HHD / 256, MC / 128), 512, SM256>>>(
                pActx, pW + wb + OFF_WKF, pK, Dd, HHD, HHD,
                pBias + (i * 2 + 0) * HHD, nullptr, 0, 2);
            gemm_h_kernel<256, __half><<<dim3(HHD / 256, MC / 128), 512, SM256>>>(
                pActx, pW + wb + OFF_WVF, pV, Dd, HHD, HHD,
                pBias + (i * 2 + 1) * HHD, nullptr, 0, 2);
        }

        attention_kernel<<<Bb * Hh, 256, ATT_SMEM>>>(pQh, pK, pV, pAttnH,
                                                     qlw, qlb, klw, klb);

        gemm_h_kernel<128, float><<<dim3(Dd / 128, ML / 128), 512, SM128>>>(
            pAttnH, pW + wb + OFF_WO, pLat, HHD, Dd, Dd, nullptr, pLat, 0, 0);

        packln_kernel<<<ML, 256>>>(pLat, mlw, mlb, pAlat, Dd);
        gemm_h_kernel<128, __half><<<dim3(FFf / 128, ML / 128), 512, SM128>>>(
            pAlat, pW + wb + OFF_WFC, pAmlp, Dd, FFf, FFf, nullptr, nullptr, 1, 0);
        gemm_h_kernel<128, float><<<dim3(Dd / 128, ML / 128), 512, SM128>>>(
            pAmlp, pW + wb + OFF_WCP, pLat, FFf, Dd, Dd, nullptr, pLat, 0, 0);
    }

    final_ln_kernel<<<Bb * NLl, 256>>>((float*)d_out, fin_w, fin_b);
}